// round 4
// baseline (speedup 1.0000x reference)
#include <cuda_runtime.h>
#include <math.h>

#define BSZ   4
#define CCH   128
#define NPT   2000
#define KNNK  9
#define NHEAD 4
#define HD    32
#define BN_EPS 1e-5f

// ---------------- scratch ------------------------------------------------
__device__ float g_w1sb[2*CCH*CCH];   // [w1a+w1b ; w1b] (256x128)
__device__ float g_wkv [2*CCH*CCH];   // [wk ; wv]
__device__ float g_bkv [2*CCH];
__device__ float g_eb  [2*CCH];       // stacked epilogue for uvt: [b1;0]
__device__ float g_eg  [2*CCH];       //                            [g1;g1]
__device__ float g_ebe [2*CCH];       //                            [be1;0]
__device__ float g_gram[(size_t)BSZ*NPT*NPT];
__device__ float g_xx[BSZ*NPT];
__device__ int   g_idx[BSZ*NPT*KNNK];
__device__ float g_uvt[(size_t)BSZ*NPT*2*CCH];   // [b][n][256] : u3t | v3t
__device__ float g_h2 [(size_t)BSZ*CCH*NPT*KNNK];
__device__ float g_agg[BSZ*CCH*NPT];
__device__ float g_q  [BSZ*CCH*NPT];
__device__ float g_kv [BSZ*2*CCH*NPT];
__device__ float g_add[BSZ*CCH*NPT];
__device__ float g_cat[BSZ*2*CCH*NPT];
__device__ float g_hc [BSZ*2*CCH*NPT];

// ---------------- generic tiled SGEMM (R2 simple loader — proven) ---------
#define TM 128
#define TN 128
#define TK 8

template<bool TA, bool TB, bool EPIN>
__global__ void __launch_bounds__(256) gemm_k(
    const float* __restrict__ A, const float* __restrict__ B, float* __restrict__ Cm,
    int M, int Nc, int Kc, int lda, int ldb, int ldc,
    long long sA, long long sB, long long sC,
    float alpha,
    const float* __restrict__ bias,
    const float* __restrict__ gamma, const float* __restrict__ beta,
    int relu,
    const float* __restrict__ resid, long long sR, int ldr)
{
    int bz = blockIdx.z;
    A  += (long long)bz * sA;
    B  += (long long)bz * sB;
    Cm += (long long)bz * sC;
    if (resid) resid += (long long)bz * sR;

    __shared__ float As[TK][TM];
    __shared__ float Bs[TK][TN];

    int m0 = blockIdx.y * TM;
    int n0 = blockIdx.x * TN;
    int tid = threadIdx.x;
    int tx = tid % 16, ty = tid / 16;

    float acc[8][8];
    #pragma unroll
    for (int i=0;i<8;i++)
        #pragma unroll
        for (int j=0;j<8;j++) acc[i][j] = 0.f;

    for (int kt = 0; kt < Kc; kt += TK) {
        #pragma unroll
        for (int e = tid; e < TM*TK; e += 256) {
            int m, k;
            if (TA) { m = e % TM; k = e / TM; }
            else    { k = e % TK; m = e / TK; }
            int gm = m0 + m, gk = kt + k;
            float val = 0.f;
            if (gm < M && gk < Kc)
                val = TA ? A[(long long)gk*lda + gm] : A[(long long)gm*lda + gk];
            As[k][m] = val;
        }
        #pragma unroll
        for (int e = tid; e < TN*TK; e += 256) {
            int n, k;
            if (TB) { k = e % TK; n = e / TK; }
            else    { n = e % TN; k = e / TN; }
            int gn = n0 + n, gk = kt + k;
            float val = 0.f;
            if (gn < Nc && gk < Kc)
                val = TB ? B[(long long)gn*ldb + gk] : B[(long long)gk*ldb + gn];
            Bs[k][n] = val;
        }
        __syncthreads();
        #pragma unroll
        for (int kk = 0; kk < TK; kk++) {
            float4 a0 = *(const float4*)&As[kk][ty*8];
            float4 a1 = *(const float4*)&As[kk][ty*8+4];
            float4 b0 = *(const float4*)&Bs[kk][tx*8];
            float4 b1 = *(const float4*)&Bs[kk][tx*8+4];
            float a[8] = {a0.x,a0.y,a0.z,a0.w,a1.x,a1.y,a1.z,a1.w};
            float b[8] = {b0.x,b0.y,b0.z,b0.w,b1.x,b1.y,b1.z,b1.w};
            #pragma unroll
            for (int i=0;i<8;i++)
                #pragma unroll
                for (int j=0;j<8;j++)
                    acc[i][j] += a[i]*b[j];
        }
        __syncthreads();
    }

    const float invs = rsqrtf(1.0f + BN_EPS);
    #pragma unroll
    for (int i=0;i<8;i++) {
        int gm = m0 + ty*8 + i;
        if (gm >= M) continue;
        float bi = 0.f, ga = 1.f, be = 0.f;
        if (!EPIN) {
            if (bias)  bi = bias[gm];
            if (gamma) { ga = gamma[gm]*invs; be = beta[gm]; }
        }
        #pragma unroll
        for (int j=0;j<8;j++) {
            int gn = n0 + tx*8 + j;
            if (gn >= Nc) continue;
            if (EPIN) {
                if (bias)  bi = bias[gn];
                if (gamma) { ga = gamma[gn]*invs; be = beta[gn]; }
            }
            float r = acc[i][j]*alpha + bi;
            if (gamma) r = r*ga + be;
            if (relu)  r = fmaxf(r, 0.f);
            if (resid) r += resid[(long long)gm*ldr + gn];
            Cm[(long long)gm*ldc + gn] = r;
        }
    }
}

// ---------------- edge-conv GEMM: B built on the fly -----------------------
__global__ void __launch_bounds__(256) gemm_edge(
    const float* __restrict__ W,     // [128][128]
    const float* __restrict__ uvt,   // [B][N][256]
    const int* __restrict__ idx,
    const float* __restrict__ bias, const float* __restrict__ gamma,
    const float* __restrict__ beta,
    float* __restrict__ out)         // [B][128][18000]
{
    extern __shared__ float sm[];
    float* Asm = sm;                 // [128][128]  (m-major)
    float* Bsf = Asm + CCH*CCH;      // [TK][TN]
    int*  ncol = (int*)(Bsf + TK*TN);
    int*  jcol = ncol + TN;

    int b  = blockIdx.z;
    int n0 = blockIdx.x * TN;
    int tid = threadIdx.x;
    const float* ub = uvt + (long long)b*NPT*2*CCH;
    const int NCOLS = NPT*KNNK;

    #pragma unroll
    for (int it=0; it<16; it++){
        int e4 = tid + it*256;
        float4 w4 = *(const float4*)(W + e4*4);
        *(float4*)(Asm + e4*4) = w4;
    }
    if (tid < TN){
        int col = n0 + tid;
        if (col < NCOLS){
            int n = col / KNNK;
            int kk = col - n*KNNK;
            ncol[tid] = n;
            jcol[tid] = idx[(b*NPT+n)*KNNK + kk];
        } else { ncol[tid] = -1; jcol[tid] = 0; }
    }
    __syncthreads();

    int cc = tid & 127;
    int kh = tid >> 7;
    int nc = ncol[cc], jc = jcol[cc];
    bool valid = (nc >= 0);
    const float* up = ub + (long long)(valid ? nc : 0)*2*CCH;
    const float* vp = ub + (long long)(valid ? jc : 0)*2*CCH + CCH;

    int tx = tid & 15, ty = tid >> 4;
    float acc[8][8];
    #pragma unroll
    for (int i=0;i<8;i++)
        #pragma unroll
        for (int j=0;j<8;j++) acc[i][j] = 0.f;

    for (int kt = 0; kt < CCH; kt += TK){
        float4 u4 = *(const float4*)(up + kt + kh*4);
        float4 v4 = *(const float4*)(vp + kt + kh*4);
        Bsf[(kh*4+0)*TN + cc] = valid ? fmaxf(u4.x - v4.x, 0.f) : 0.f;
        Bsf[(kh*4+1)*TN + cc] = valid ? fmaxf(u4.y - v4.y, 0.f) : 0.f;
        Bsf[(kh*4+2)*TN + cc] = valid ? fmaxf(u4.z - v4.z, 0.f) : 0.f;
        Bsf[(kh*4+3)*TN + cc] = valid ? fmaxf(u4.w - v4.w, 0.f) : 0.f;
        __syncthreads();
        #pragma unroll
        for (int kk4=0; kk4<TK; kk4+=4){
            float4 av4[8];
            #pragma unroll
            for (int i=0;i<8;i++)
                av4[i] = *(const float4*)&Asm[(ty*8+i)*CCH + kt + kk4];
            #pragma unroll
            for (int q=0;q<4;q++){
                int kk = kk4 + q;
                float4 b0 = *(const float4*)&Bsf[kk*TN + tx*8];
                float4 b1 = *(const float4*)&Bsf[kk*TN + tx*8+4];
                float bv8[8] = {b0.x,b0.y,b0.z,b0.w,b1.x,b1.y,b1.z,b1.w};
                #pragma unroll
                for (int i=0;i<8;i++){
                    float a = (&av4[i].x)[q];
                    #pragma unroll
                    for (int j=0;j<8;j++) acc[i][j] += a*bv8[j];
                }
            }
        }
        __syncthreads();
    }

    const float invs = rsqrtf(1.0f + BN_EPS);
    float* ob = out + (long long)b*CCH*NCOLS;
    #pragma unroll
    for (int i=0;i<8;i++){
        int gm = ty*8 + i;
        float bi = bias[gm];
        float ga = gamma[gm]*invs;
        float be = beta[gm];
        #pragma unroll
        for (int j=0;j<8;j++){
            int gn = n0 + tx*8 + j;
            if (gn >= NCOLS) continue;
            float r = (acc[i][j] + bi)*ga + be;
            ob[(long long)gm*NCOLS + gn] = fmaxf(r, 0.f);
        }
    }
}

// ---------------- prep ------------------------------------------------------
__global__ void prep_kernel(const float* __restrict__ w1,
                            const float* __restrict__ wk, const float* __restrict__ wv,
                            const float* __restrict__ bk, const float* __restrict__ bv,
                            const float* __restrict__ b1, const float* __restrict__ g1,
                            const float* __restrict__ be1,
                            float* __restrict__ w1sb, float* __restrict__ wkv,
                            float* __restrict__ bkv,
                            float* __restrict__ eb, float* __restrict__ eg,
                            float* __restrict__ ebe)
{
    int i = blockIdx.x*blockDim.x + threadIdx.x;
    if (i < CCH*CCH) {
        int o = i / CCH, c = i % CCH;
        float a  = w1[o*2*CCH + c];
        float bb = w1[o*2*CCH + CCH + c];
        w1sb[i] = a + bb;
        w1sb[CCH*CCH + i] = bb;
        wkv[i] = wk[i];
        wkv[CCH*CCH + i] = wv[i];
    }
    if (i < CCH) {
        bkv[i] = bk[i];        bkv[CCH+i] = bv[i];
        eb[i]  = b1[i];        eb[CCH+i]  = 0.f;
        eg[i]  = g1[i];        eg[CCH+i]  = g1[i];
        ebe[i] = be1[i];       ebe[CCH+i] = 0.f;
    }
}

__global__ void xx_kernel(const float* __restrict__ gram, float* __restrict__ xx)
{
    int i = blockIdx.x*blockDim.x + threadIdx.x;
    if (i < BSZ*NPT) {
        int b = i / NPT, n = i % NPT;
        xx[i] = gram[((long long)(b*NPT+n))*NPT + n];
    }
}

// ---------------- topk: lane sort-8 + warp k-way merge -----------------------
__global__ void __launch_bounds__(256) topk_kernel(const float* __restrict__ gram,
                                                   const float* __restrict__ xx,
                                                   int* __restrict__ idx)
{
    int n = blockIdx.x, b = blockIdx.y;
    const float* row = gram + ((long long)(b*NPT+n))*NPT;
    const float* xb  = xx + b*NPT;
    int tid = threadIdx.x, w = tid >> 5, l = tid & 31;

    float v[8]; int id[8];
    #pragma unroll
    for (int j=0;j<8;j++){
        int m = w*256 + j*32 + l;
        bool ok = m < NPT;
        v[j]  = ok ? (2.f*row[m] - xb[m]) : -INFINITY;
        id[j] = ok ? m : 0x7fffffff;
    }
#define CSWP(a,bb) { bool sw = (v[a]<v[bb]) || (v[a]==v[bb] && id[a]>id[bb]); \
    float tv = sw?v[bb]:v[a]; float uv2 = sw?v[a]:v[bb]; v[a]=tv; v[bb]=uv2;   \
    int ti = sw?id[bb]:id[a]; int ui = sw?id[a]:id[bb]; id[a]=ti; id[bb]=ui; }
    CSWP(0,1) CSWP(2,3) CSWP(4,5) CSWP(6,7)
    CSWP(0,2) CSWP(1,3) CSWP(4,6) CSWP(5,7)
    CSWP(1,2) CSWP(5,6)
    CSWP(0,4) CSWP(1,5) CSWP(2,6) CSWP(3,7)
    CSWP(2,4) CSWP(3,5)
    CSWP(1,2) CSWP(3,4) CSWP(5,6)
#undef CSWP

    __shared__ float wv[8][12];
    __shared__ int   wi[8][12];

    float hv = v[0]; int hi = id[0];
    #pragma unroll
    for (int t=0;t<KNNK;t++){
        float bvv = hv; int bii = hi;
        #pragma unroll
        for (int s=16; s>0; s>>=1){
            float ov = __shfl_xor_sync(0xffffffffu, bvv, s);
            int   oi = __shfl_xor_sync(0xffffffffu, bii, s);
            if (ov > bvv || (ov == bvv && oi < bii)) { bvv = ov; bii = oi; }
        }
        if (l == 0) { wv[w][t] = bvv; wi[w][t] = bii; }
        if (hi == bii) {
            #pragma unroll
            for (int j=0;j<7;j++){ v[j]=v[j+1]; id[j]=id[j+1]; }
            v[7] = -INFINITY; id[7] = 0x7fffffff;
            hv = v[0]; hi = id[0];
        }
    }
    __syncthreads();

    if (w == 0){
        int ptr = 0;
        float hv2 = (l < 8) ? wv[l][0] : -INFINITY;
        int   hi2 = (l < 8) ? wi[l][0] : 0x7fffffff;
        int* outp = idx + (b*NPT+n)*KNNK;
        #pragma unroll
        for (int t=0;t<KNNK;t++){
            float bvv = hv2; int bii = hi2;
            #pragma unroll
            for (int s=16; s>0; s>>=1){
                float ov = __shfl_xor_sync(0xffffffffu, bvv, s);
                int   oi = __shfl_xor_sync(0xffffffffu, bii, s);
                if (ov > bvv || (ov == bvv && oi < bii)) { bvv = ov; bii = oi; }
            }
            if (l == 0) outp[t] = bii;
            if (hi2 == bii){
                ptr++;
                hv2 = (ptr < KNNK && l < 8) ? wv[l][ptr] : -INFINITY;
                hi2 = (ptr < KNNK && l < 8) ? wi[l][ptr] : 0x7fffffff;
            }
        }
    }
}

// agg[b,c,n] = max_k h2[...]; also writes top half of cat
__global__ void maxk_kernel(const float* __restrict__ h2,
                            float* __restrict__ agg, float* __restrict__ cat)
{
    int i = blockIdx.x*blockDim.x + threadIdx.x;
    if (i >= BSZ*CCH*NPT) return;
    int n = i % NPT;
    int c = (i / NPT) % CCH;
    int b = i / (NPT*CCH);
    const float* p = h2 + ((long long)(b*CCH+c))*NPT*KNNK + (long long)n*KNNK;
    float m = p[0];
    #pragma unroll
    for (int k = 1; k < KNNK; k++) m = fmaxf(m, p[k]);
    agg[i] = m;
    cat[(long long)b*2*CCH*NPT + (long long)c*NPT + n] = m;
}

// ---------------- flash attention: S in registers ----------------------------
#define QT 128
#define KT 64
#define QST_LD 132
#define VT_LD 36

__global__ void __launch_bounds__(256,2) flash_kernel(
    const float* __restrict__ q,   // [B][C][N]
    const float* __restrict__ kv,  // [B][2C][N]
    float* __restrict__ add)       // [B][C][N]
{
    __shared__ float Qst[HD*QST_LD];
    __shared__ float Ks [HD*KT];
    __shared__ float Vt [KT*VT_LD];

    int n0 = blockIdx.x * QT;
    int h  = blockIdx.y;
    int b  = blockIdx.z;
    const float* qh = q  + ((long long)b*CCH   + h*HD)*NPT;
    const float* kh = kv + ((long long)b*2*CCH + h*HD)*NPT;
    const float* vh = kv + ((long long)b*2*CCH + CCH + h*HD)*NPT;
    float* oh = add + ((long long)b*CCH + h*HD)*NPT;

    int tid = threadIdx.x;
    #pragma unroll
    for (int e = tid; e < HD*QT; e += 256) {
        int d = e >> 7, r = e & 127;
        int n = n0 + r;
        Qst[d*QST_LD + r] = (n < NPT) ? qh[d*NPT + n] : 0.f;
    }

    int r2 = tid >> 2;
    int colq = tid & 3;
    int row0 = 2*r2;

    float O0[HD], O1[HD];
    #pragma unroll
    for (int d=0; d<HD; d++){ O0[d]=0.f; O1[d]=0.f; }
    float m0r = -INFINITY, m1r = -INFINITY, l0r = 0.f, l1r = 0.f;

    const float scale = 0.17677669529663689f;
    const int ntiles = (NPT + KT - 1)/KT;

    for (int t = 0; t < ntiles; t++) {
        int mt0 = t*KT;
        __syncthreads();
        #pragma unroll
        for (int e = tid; e < HD*KT; e += 256) {
            int d = e >> 6, c = e & 63;
            int m = mt0 + c;
            Ks[d*KT + c]    = (m < NPT) ? kh[d*NPT + m] : 0.f;
            Vt[c*VT_LD + d] = (m < NPT) ? vh[d*NPT + m] : 0.f;
        }
        __syncthreads();

        float s0[16], s1[16];
        #pragma unroll
        for (int j=0;j<16;j++){ s0[j]=0.f; s1[j]=0.f; }

        #pragma unroll
        for (int kk=0; kk<HD; kk++){
            float2 a2 = *(const float2*)&Qst[kk*QST_LD + row0];
            const float* kp = &Ks[kk*KT + colq*16];
            #pragma unroll
            for (int jj=0; jj<4; jj++){
                float4 b4 = *(const float4*)(kp + jj*4);
                s0[jj*4+0] += a2.x*b4.x; s0[jj*4+1] += a2.x*b4.y;
                s0[jj*4+2] += a2.x*b4.z; s0[jj*4+3] += a2.x*b4.w;
                s1[jj*4+0] += a2.y*b4.x; s1[jj*4+1] += a2.y*b4.y;
                s1[jj*4+2] += a2.y*b4.z; s1[jj*4+3] += a2.y*b4.w;
            }
        }

        int mvalid = NPT - mt0;
        float lm0 = -INFINITY, lm1 = -INFINITY;
        #pragma unroll
        for (int j=0;j<16;j++){
            int m = colq*16 + j;
            s0[j] *= scale; s1[j] *= scale;
            if (m < mvalid){ lm0 = fmaxf(lm0, s0[j]); lm1 = fmaxf(lm1, s1[j]); }
        }
        lm0 = fmaxf(lm0, __shfl_xor_sync(0xffffffffu, lm0, 1));
        lm0 = fmaxf(lm0, __shfl_xor_sync(0xffffffffu, lm0, 2));
        lm1 = fmaxf(lm1, __shfl_xor_sync(0xffffffffu, lm1, 1));
        lm1 = fmaxf(lm1, __shfl_xor_sync(0xffffffffu, lm1, 2));

        float mn0 = fmaxf(m0r, lm0), mn1 = fmaxf(m1r, lm1);
        float al0 = __expf(m0r - mn0), al1 = __expf(m1r - mn1);
        m0r = mn0; m1r = mn1;

        float ls0 = 0.f, ls1 = 0.f;
        #pragma unroll
        for (int j=0;j<16;j++){
            int m = colq*16 + j;
            float e0 = (m < mvalid) ? __expf(s0[j] - mn0) : 0.f;
            float e1 = (m < mvalid) ? __expf(s1[j] - mn1) : 0.f;
            s0[j] = e0; s1[j] = e1;
            ls0 += e0; ls1 += e1;
        }
        l0r = l0r*al0 + ls0;
        l1r = l1r*al1 + ls1;
        #pragma unroll
        for (int d=0; d<HD; d++){ O0[d] *= al0; O1[d] *= al1; }

        #pragma unroll
        for (int j=0;j<16;j++){
            int m = colq*16 + j;
            const float* vr = &Vt[m*VT_LD];
            float p0 = s0[j], p1 = s1[j];
            #pragma unroll
            for (int d=0; d<HD; d+=4){
                float4 v4 = *(const float4*)&vr[d];
                O0[d]   += p0*v4.x; O0[d+1] += p0*v4.y;
                O0[d+2] += p0*v4.z; O0[d+3] += p0*v4.w;
                O1[d]   += p1*v4.x; O1[d+1] += p1*v4.y;
                O1[d+2] += p1*v4.z; O1[d+3] += p1*v4.w;
            }
        }
    }

    l0r += __shfl_xor_sync(0xffffffffu, l0r, 1);
    l0r += __shfl_xor_sync(0xffffffffu, l0r, 2);
    l1r += __shfl_xor_sync(0xffffffffu, l1r, 1);
    l1r += __shfl_xor_sync(0xffffffffu, l1r, 2);
    #pragma unroll
    for (int d=0; d<HD; d++){
        O0[d] += __shfl_xor_sync(0xffffffffu, O0[d], 1);
        O0[d] += __shfl_xor_sync(0xffffffffu, O0[d], 2);
        O1[d] += __shfl_xor_sync(0xffffffffu, O1[d], 1);
        O1[d] += __shfl_xor_sync(0xffffffffu, O1[d], 2);
    }
    if (colq == 0){
        float inv0 = 1.f / l0r, inv1 = 1.f / l1r;
        int n = n0 + row0;
        #pragma unroll
        for (int d=0; d<HD; d++){
            if (n < NPT)     oh[(long long)d*NPT + n]     = O0[d]*inv0;
            if (n+1 < NPT)   oh[(long long)d*NPT + n + 1] = O1[d]*inv1;
        }
    }
}

// ---------------- launch ------------------------------------------------------
static inline dim3 ggrid(int M, int Nc, int batches) {
    return dim3((Nc + TN - 1)/TN, (M + TM - 1)/TM, batches);
}

extern "C" void kernel_launch(void* const* d_in, const int* in_sizes, int n_in,
                              void* d_out, int out_size)
{
    const float* x    = (const float*)d_in[0];
    const float* y    = (const float*)d_in[1];
    const float* dgw1 = (const float*)d_in[2];
    const float* dgb1 = (const float*)d_in[3];
    const float* dgg1 = (const float*)d_in[4];
    const float* dgbe1= (const float*)d_in[5];
    const float* dgw2 = (const float*)d_in[6];
    const float* dgb2 = (const float*)d_in[7];
    const float* dgg2 = (const float*)d_in[8];
    const float* dgbe2= (const float*)d_in[9];
    const float* wq   = (const float*)d_in[10];
    const float* bq   = (const float*)d_in[11];
    const float* wk   = (const float*)d_in[12];
    const float* bk   = (const float*)d_in[13];
    const float* wv   = (const float*)d_in[14];
    const float* bv   = (const float*)d_in[15];
    const float* wmh  = (const float*)d_in[16];
    const float* bmh  = (const float*)d_in[17];
    const float* wc1  = (const float*)d_in[18];
    const float* bc1  = (const float*)d_in[19];
    const float* cg   = (const float*)d_in[20];
    const float* cbe  = (const float*)d_in[21];
    const float* wc2  = (const float*)d_in[22];
    const float* bc2  = (const float*)d_in[23];
    float* out = (float*)d_out;

    float *w1sb,*wkv,*bkv,*eb,*eg,*ebe,*gram,*xx,*uvt,*h2,*agg,*q,*kvb,*add,*cat,*hc;
    int* idx;
    cudaGetSymbolAddress((void**)&w1sb, g_w1sb);
    cudaGetSymbolAddress((void**)&wkv,  g_wkv);
    cudaGetSymbolAddress((void**)&bkv,  g_bkv);
    cudaGetSymbolAddress((void**)&eb,   g_eb);
    cudaGetSymbolAddress((void**)&eg,   g_eg);
    cudaGetSymbolAddress((void**)&ebe,  g_ebe);
    cudaGetSymbolAddress((void**)&gram, g_gram);
    cudaGetSymbolAddress((void**)&xx,   g_xx);
    cudaGetSymbolAddress((void**)&idx,  g_idx);
    cudaGetSymbolAddress((void**)&uvt,  g_uvt);
    cudaGetSymbolAddress((void**)&h2,   g_h2);
    cudaGetSymbolAddress((void**)&agg,  g_agg);
    cudaGetSymbolAddress((void**)&q,    g_q);
    cudaGetSymbolAddress((void**)&kvb,  g_kv);
    cudaGetSymbolAddress((void**)&add,  g_add);
    cudaGetSymbolAddress((void**)&cat,  g_cat);
    cudaGetSymbolAddress((void**)&hc,   g_hc);

    const long long CN  = (long long)CCH*NPT;
    const long long NN  = (long long)NPT*NPT;
    const int NCOLS = NPT*KNNK;
    const int EDGE_SMEM = (CCH*CCH + TK*TN)*4 + 2*TN*4;

    cudaFuncSetAttribute(gemm_edge, cudaFuncAttributeMaxDynamicSharedMemorySize, EDGE_SMEM);

    // 1) prep
    prep_kernel<<<(CCH*CCH+255)/256, 256>>>(dgw1, wk, wv, bk, bv,
                                            dgb1, dgg1, dgbe1,
                                            w1sb, wkv, bkv, eb, eg, ebe);

    // 2) gram[b] = x^T x
    gemm_k<true,false,false><<<ggrid(NPT,NPT,BSZ), 256>>>(
        x, x, gram, NPT, NPT, CCH, NPT, NPT, NPT,
        CN, CN, NN, 1.f, nullptr, nullptr, nullptr, 0, nullptr, 0, 0);

    // 3) diag + top-9
    xx_kernel<<<(BSZ*NPT+255)/256, 256>>>(gram, xx);
    topk_kernel<<<dim3(NPT, BSZ), 256>>>(gram, xx, idx);

    // 4) uvt[b][n][0:256] = ((x^T w1sb^T) + eb)*eg + ebe
    gemm_k<true,true,true><<<ggrid(NPT,2*CCH,BSZ), 256>>>(
        x, w1sb, uvt, NPT, 2*CCH, CCH, NPT, CCH, 2*CCH,
        CN, 0, (long long)NPT*2*CCH,
        1.f, eb, eg, ebe, 0, nullptr, 0, 0);

    // 5) conv2 with fused edge-feature construction + bn + relu
    {
        dim3 grid((NCOLS + TN - 1)/TN, 1, BSZ);
        gemm_edge<<<grid, 256, EDGE_SMEM>>>(dgw2, uvt, idx, dgb2, dgg2, dgbe2, h2);
    }

    // 6) max over k -> agg (+ top half of cat)
    maxk_kernel<<<(BSZ*CCH*NPT+255)/256, 256>>>(h2, agg, cat);

    // 7) q = wq@agg + bq ; kv = [wk;wv]@y + [bk;bv]
    gemm_k<false,false,false><<<ggrid(CCH,NPT,BSZ), 256>>>(
        wq, agg, q, CCH, NPT, CCH, CCH, NPT, NPT,
        0, CN, CN, 1.f, bq, nullptr, nullptr, 0, nullptr, 0, 0);
    gemm_k<false,false,false><<<ggrid(2*CCH,NPT,BSZ), 256>>>(
        wkv, y, kvb, 2*CCH, NPT, CCH, CCH, NPT, NPT,
        0, CN, 2*CN, 1.f, bkv, nullptr, nullptr, 0, nullptr, 0, 0);

    // 8) fused attention -> add
    {
        dim3 grid((NPT + QT - 1)/QT, NHEAD, BSZ);
        flash_kernel<<<grid, 256>>>(q, kvb, add);
    }

    // 9) mh conv -> bottom half of cat
    gemm_k<false,false,false><<<ggrid(CCH,NPT,BSZ), 256>>>(
        wmh, add, cat + CN, CCH, NPT, CCH, CCH, NPT, NPT,
        0, CN, 2*CN, 1.f, bmh, nullptr, nullptr, 0, nullptr, 0, 0);

    // 10) hc = relu(bn(wc1 @ cat + bc1))
    gemm_k<false,false,false><<<ggrid(2*CCH,NPT,BSZ), 256>>>(
        wc1, cat, hc, 2*CCH, NPT, 2*CCH, 2*CCH, NPT, NPT,
        0, 2*CN, 2*CN, 1.f, bc1, cg, cbe, 1, nullptr, 0, 0);

    // 11) out = agg + wc2 @ hc + bc2
    gemm_k<false,false,false><<<ggrid(CCH,NPT,BSZ), 256>>>(
        wc2, hc, out, CCH, NPT, 2*CCH, 2*CCH, NPT, NPT,
        0, 2*CN, CN, 1.f, bc2, nullptr, nullptr, 0, agg, CN, NPT);
}

// round 5
// speedup vs baseline: 1.6332x; 1.6332x over previous
#include <cuda_runtime.h>
#include <math.h>

#define BSZ   4
#define CCH   128
#define NPT   2000
#define KNNK  9
#define NHEAD 4
#define HD    32
#define BN_EPS 1e-5f

// ---------------- scratch ------------------------------------------------
__device__ float g_w1sb[2*CCH*CCH];   // [w1a+w1b ; w1b] (256x128)
__device__ float g_wkv [2*CCH*CCH];   // [wk ; wv]
__device__ float g_bkv [2*CCH];
__device__ float g_gram[(size_t)BSZ*NPT*NPT];
__device__ float g_xx[BSZ*NPT];
__device__ int   g_idx[BSZ*NPT*KNNK];
__device__ float g_uv[BSZ*2*CCH*NPT];            // u rows 0..127, v rows 128..255
__device__ float g_h [(size_t)BSZ*CCH*NPT*KNNK];
__device__ float g_h2[(size_t)BSZ*CCH*NPT*KNNK];
__device__ float g_agg[BSZ*CCH*NPT];
__device__ float g_q  [BSZ*CCH*NPT];
__device__ float g_kv [BSZ*2*CCH*NPT];
__device__ float g_add[BSZ*CCH*NPT];
__device__ float g_cat[BSZ*2*CCH*NPT];
__device__ float g_hc [BSZ*2*CCH*NPT];

// ---------------- generic tiled SGEMM (reg-prefetch double buffer) --------
#define TM 128
#define TN 128
#define TK 8

template<bool TA, bool TB>
__global__ void __launch_bounds__(256) gemm_k(
    const float* __restrict__ A, const float* __restrict__ B, float* __restrict__ Cm,
    int M, int Nc, int Kc, int lda, int ldb, int ldc,
    long long sA, long long sB, long long sC,
    float alpha,
    const float* __restrict__ bias,
    const float* __restrict__ gamma, const float* __restrict__ beta,
    int relu,
    const float* __restrict__ resid, long long sR, int ldr)
{
    int bz = blockIdx.z;
    A  += (long long)bz * sA;
    B  += (long long)bz * sB;
    Cm += (long long)bz * sC;
    if (resid) resid += (long long)bz * sR;

    __shared__ float As[TK][TM];
    __shared__ float Bs[TK][TN];

    int m0 = blockIdx.y * TM;
    int n0 = blockIdx.x * TN;
    int tid = threadIdx.x;
    int tx = tid % 16, ty = tid / 16;

    float acc[8][8];
    #pragma unroll
    for (int i=0;i<8;i++)
        #pragma unroll
        for (int j=0;j<8;j++) acc[i][j] = 0.f;

    float ra[4], rb[4];

#define GK_LOAD(KT0) {                                                     \
    _Pragma("unroll")                                                      \
    for (int it=0; it<4; it++){                                            \
        int e = tid + it*256; int m_,k_;                                   \
        if (TA){ m_ = e % TM; k_ = e / TM; } else { k_ = e % TK; m_ = e / TK; } \
        int gm = m0+m_, gk = (KT0)+k_;                                     \
        ra[it] = (gm<M && gk<Kc) ? (TA ? A[(long long)gk*lda+gm]           \
                                       : A[(long long)gm*lda+gk]) : 0.f;   \
    }                                                                      \
    _Pragma("unroll")                                                      \
    for (int it=0; it<4; it++){                                            \
        int e = tid + it*256; int n_,k_;                                   \
        if (TB){ k_ = e % TK; n_ = e / TK; } else { n_ = e % TN; k_ = e / TN; } \
        int gn = n0+n_, gk = (KT0)+k_;                                     \
        rb[it] = (gn<Nc && gk<Kc) ? (TB ? B[(long long)gn*ldb+gk]          \
                                        : B[(long long)gk*ldb+gn]) : 0.f;  \
    } }

#define GK_STORE() {                                                       \
    _Pragma("unroll")                                                      \
    for (int it=0; it<4; it++){                                            \
        int e = tid + it*256; int m_,k_;                                   \
        if (TA){ m_ = e % TM; k_ = e / TM; } else { k_ = e % TK; m_ = e / TK; } \
        As[k_][m_] = ra[it];                                               \
    }                                                                      \
    _Pragma("unroll")                                                      \
    for (int it=0; it<4; it++){                                            \
        int e = tid + it*256; int n_,k_;                                   \
        if (TB){ k_ = e % TK; n_ = e / TK; } else { n_ = e % TN; k_ = e / TN; } \
        Bs[k_][n_] = rb[it];                                               \
    } }

#define GK_COMPUTE() {                                                     \
    _Pragma("unroll")                                                      \
    for (int kk=0; kk<TK; kk++){                                           \
        float4 a0 = *(const float4*)&As[kk][ty*8];                         \
        float4 a1 = *(const float4*)&As[kk][ty*8+4];                       \
        float4 b0 = *(const float4*)&Bs[kk][tx*8];                         \
        float4 b1 = *(const float4*)&Bs[kk][tx*8+4];                       \
        float av[8] = {a0.x,a0.y,a0.z,a0.w,a1.x,a1.y,a1.z,a1.w};           \
        float bv8[8] = {b0.x,b0.y,b0.z,b0.w,b1.x,b1.y,b1.z,b1.w};          \
        _Pragma("unroll")                                                  \
        for (int i=0;i<8;i++)                                              \
            _Pragma("unroll")                                              \
            for (int j=0;j<8;j++) acc[i][j] += av[i]*bv8[j];               \
    } }

    GK_LOAD(0);
    GK_STORE();
    for (int kt = TK; kt < Kc; kt += TK) {
        __syncthreads();
        GK_LOAD(kt);
        GK_COMPUTE();
        __syncthreads();
        GK_STORE();
    }
    __syncthreads();
    GK_COMPUTE();

    const float invs = rsqrtf(1.0f + BN_EPS);
    #pragma unroll
    for (int i=0;i<8;i++) {
        int gm = m0 + ty*8 + i;
        if (gm >= M) continue;
        float bi = bias  ? bias[gm]       : 0.f;
        float ga = gamma ? gamma[gm]*invs : 1.f;
        float be = beta  ? beta[gm]       : 0.f;
        #pragma unroll
        for (int j=0;j<8;j++) {
            int gn = n0 + tx*8 + j;
            if (gn >= Nc) continue;
            float r = acc[i][j]*alpha + bi;
            if (gamma) r = r*ga + be;
            if (relu)  r = fmaxf(r, 0.f);
            if (resid) r += resid[(long long)gm*ldr + gn];
            Cm[(long long)gm*ldc + gn] = r;
        }
    }
#undef GK_LOAD
#undef GK_STORE
#undef GK_COMPUTE
}

// ---------------- prep ------------------------------------------------------
__global__ void prep_kernel(const float* __restrict__ w1,
                            const float* __restrict__ wk, const float* __restrict__ wv,
                            const float* __restrict__ bk, const float* __restrict__ bv,
                            float* __restrict__ w1sb, float* __restrict__ wkv,
                            float* __restrict__ bkv)
{
    int i = blockIdx.x*blockDim.x + threadIdx.x;
    if (i < CCH*CCH) {
        int o = i / CCH, c = i % CCH;
        float a  = w1[o*2*CCH + c];
        float bb = w1[o*2*CCH + CCH + c];
        w1sb[i] = a + bb;
        w1sb[CCH*CCH + i] = bb;
        wkv[i] = wk[i];
        wkv[CCH*CCH + i] = wv[i];
    }
    if (i < 2*CCH) bkv[i] = (i < CCH) ? bk[i] : bv[i - CCH];
}

__global__ void xx_kernel(const float* __restrict__ gram, float* __restrict__ xx)
{
    int i = blockIdx.x*blockDim.x + threadIdx.x;
    if (i < BSZ*NPT) {
        int b = i / NPT, n = i % NPT;
        xx[i] = gram[((long long)(b*NPT+n))*NPT + n];
    }
}

// ---------------- topk: lane sort-8 + warp k-way merge -----------------------
__global__ void __launch_bounds__(256) topk_kernel(const float* __restrict__ gram,
                                                   const float* __restrict__ xx,
                                                   int* __restrict__ idx)
{
    int n = blockIdx.x, b = blockIdx.y;
    const float* row = gram + ((long long)(b*NPT+n))*NPT;
    const float* xb  = xx + b*NPT;
    int tid = threadIdx.x, w = tid >> 5, l = tid & 31;

    float v[8]; int id[8];
    #pragma unroll
    for (int j=0;j<8;j++){
        int m = w*256 + j*32 + l;
        bool ok = m < NPT;
        v[j]  = ok ? (2.f*row[m] - xb[m]) : -INFINITY;
        id[j] = ok ? m : 0x7fffffff;
    }
#define CSWP(a,bb) { bool sw = (v[a]<v[bb]) || (v[a]==v[bb] && id[a]>id[bb]); \
    float tv = sw?v[bb]:v[a]; float uv2 = sw?v[a]:v[bb]; v[a]=tv; v[bb]=uv2;   \
    int ti = sw?id[bb]:id[a]; int ui = sw?id[a]:id[bb]; id[a]=ti; id[bb]=ui; }
    CSWP(0,1) CSWP(2,3) CSWP(4,5) CSWP(6,7)
    CSWP(0,2) CSWP(1,3) CSWP(4,6) CSWP(5,7)
    CSWP(1,2) CSWP(5,6)
    CSWP(0,4) CSWP(1,5) CSWP(2,6) CSWP(3,7)
    CSWP(2,4) CSWP(3,5)
    CSWP(1,2) CSWP(3,4) CSWP(5,6)
#undef CSWP

    __shared__ float wv[8][12];
    __shared__ int   wi[8][12];

    float hv = v[0]; int hi = id[0];
    #pragma unroll
    for (int t=0;t<KNNK;t++){
        float bvv = hv; int bii = hi;
        #pragma unroll
        for (int s=16; s>0; s>>=1){
            float ov = __shfl_xor_sync(0xffffffffu, bvv, s);
            int   oi = __shfl_xor_sync(0xffffffffu, bii, s);
            if (ov > bvv || (ov == bvv && oi < bii)) { bvv = ov; bii = oi; }
        }
        if (l == 0) { wv[w][t] = bvv; wi[w][t] = bii; }
        if (hi == bii) {
            #pragma unroll
            for (int j=0;j<7;j++){ v[j]=v[j+1]; id[j]=id[j+1]; }
            v[7] = -INFINITY; id[7] = 0x7fffffff;
            hv = v[0]; hi = id[0];
        }
    }
    __syncthreads();

    if (w == 0){
        int ptr = 0;
        float hv2 = (l < 8) ? wv[l][0] : -INFINITY;
        int   hi2 = (l < 8) ? wi[l][0] : 0x7fffffff;
        int* outp = idx + (b*NPT+n)*KNNK;
        #pragma unroll
        for (int t=0;t<KNNK;t++){
            float bvv = hv2; int bii = hi2;
            #pragma unroll
            for (int s=16; s>0; s>>=1){
                float ov = __shfl_xor_sync(0xffffffffu, bvv, s);
                int   oi = __shfl_xor_sync(0xffffffffu, bii, s);
                if (ov > bvv || (ov == bvv && oi < bii)) { bvv = ov; bii = oi; }
            }
            if (l == 0) outp[t] = bii;
            if (hi2 == bii){
                ptr++;
                hv2 = (ptr < KNNK && l < 8) ? wv[l][ptr] : -INFINITY;
                hi2 = (ptr < KNNK && l < 8) ? wi[l][ptr] : 0x7fffffff;
            }
        }
    }
}

// h[b,c,n*9+k] = relu( bn( u[b,c,n] - v[b,c,idx] + b1[c] ) )
__global__ void gather_h_kernel(const float* __restrict__ uv,
                                const int* __restrict__ idx,
                                const float* __restrict__ b1, const float* __restrict__ g1,
                                const float* __restrict__ be1, float* __restrict__ h)
{
    long long i = (long long)blockIdx.x*blockDim.x + threadIdx.x;
    const long long total = (long long)BSZ*CCH*NPT*KNNK;
    if (i >= total) return;
    int k = (int)(i % KNNK);
    long long r = i / KNNK;
    int n = (int)(r % NPT); r /= NPT;
    int c = (int)(r % CCH);
    int b = (int)(r / CCH);
    int j = idx[(b*NPT+n)*KNNK + k];
    const float* ub = uv + (long long)b*2*CCH*NPT + (long long)c*NPT;
    float uvv = ub[n];
    float vg  = ub[(long long)CCH*NPT + j];
    const float invs = rsqrtf(1.f + BN_EPS);
    float val = (uvv - vg + b1[c]) * (g1[c]*invs) + be1[c];
    h[((long long)(b*CCH+c))*NPT*KNNK + (long long)n*KNNK + k] = fmaxf(val, 0.f);
}

// agg[b,c,n] = max_k h2[...]; also writes top half of cat
__global__ void maxk_kernel(const float* __restrict__ h2,
                            float* __restrict__ agg, float* __restrict__ cat)
{
    int i = blockIdx.x*blockDim.x + threadIdx.x;
    if (i >= BSZ*CCH*NPT) return;
    int n = i % NPT;
    int c = (i / NPT) % CCH;
    int b = i / (NPT*CCH);
    const float* p = h2 + ((long long)(b*CCH+c))*NPT*KNNK + (long long)n*KNNK;
    float m = p[0];
    #pragma unroll
    for (int k = 1; k < KNNK; k++) m = fmaxf(m, p[k]);
    agg[i] = m;
    cat[(long long)b*2*CCH*NPT + (long long)c*NPT + n] = m;
}

// ---------------- flash attention (R2 proven version) -------------------------
#define QT 128
#define KT 64
#define QST_LD 132
#define VT_LD  36
#define PS_LD  68

__global__ void __launch_bounds__(256,2) flash_kernel(
    const float* __restrict__ q,   // [B][C][N]
    const float* __restrict__ kv,  // [B][2C][N]
    float* __restrict__ add)       // [B][C][N]
{
    extern __shared__ float sm[];
    float* Qst = sm;                         // [32][132]
    float* Ks  = Qst + HD*QST_LD;            // [32][64]
    float* Vt  = Ks  + HD*KT;                // [64][36]
    float* Ps  = Vt  + KT*VT_LD;             // [128][68]

    int n0 = blockIdx.x * QT;
    int h  = blockIdx.y;
    int b  = blockIdx.z;
    const float* qh = q  + ((long long)b*CCH   + h*HD)*NPT;
    const float* kh = kv + ((long long)b*2*CCH + h*HD)*NPT;
    const float* vh = kv + ((long long)b*2*CCH + CCH + h*HD)*NPT;
    float* oh = add + ((long long)b*CCH + h*HD)*NPT;

    int tid = threadIdx.x;
    for (int e = tid; e < HD*QT; e += 256) {
        int d = e >> 7, r = e & 127;
        int n = n0 + r;
        Qst[d*QST_LD + r] = (n < NPT) ? qh[d*NPT + n] : 0.f;
    }

    int ty = tid >> 4, tx = tid & 15;
    int rr = tid >> 1, part = tid & 1;

    float mrow = -INFINITY, lrow = 0.f;
    float O[HD];
    #pragma unroll
    for (int d=0; d<HD; d++) O[d] = 0.f;

    const float scale = 0.17677669529663689f;
    const int ntiles = (NPT + KT - 1)/KT;

    for (int t = 0; t < ntiles; t++) {
        int m0 = t*KT;
        __syncthreads();
        #pragma unroll
        for (int e = tid; e < HD*KT; e += 256) {
            int d = e >> 6, c = e & 63;
            int m = m0 + c;
            float kvld = (m < NPT) ? kh[d*NPT + m] : 0.f;
            float vvld = (m < NPT) ? vh[d*NPT + m] : 0.f;
            Ks[d*KT + c]  = kvld;
            Vt[c*VT_LD + d] = vvld;
        }
        __syncthreads();

        float acc[8][4];
        #pragma unroll
        for (int i=0;i<8;i++)
            #pragma unroll
            for (int j=0;j<4;j++) acc[i][j] = 0.f;
        #pragma unroll
        for (int kk=0; kk<HD; kk++) {
            float4 a0 = *(const float4*)&Qst[kk*QST_LD + ty*8];
            float4 a1 = *(const float4*)&Qst[kk*QST_LD + ty*8 + 4];
            float4 b4 = *(const float4*)&Ks[kk*KT + tx*4];
            float a[8] = {a0.x,a0.y,a0.z,a0.w,a1.x,a1.y,a1.z,a1.w};
            float bb[4] = {b4.x,b4.y,b4.z,b4.w};
            #pragma unroll
            for (int i=0;i<8;i++)
                #pragma unroll
                for (int j=0;j<4;j++) acc[i][j] += a[i]*bb[j];
        }
        #pragma unroll
        for (int i=0;i<8;i++)
            #pragma unroll
            for (int j=0;j<4;j++)
                Ps[(ty*8+i)*PS_LD + tx*4+j] = acc[i][j]*scale;
        __syncthreads();

        int mvalid = NPT - m0;
        float sv[32];
        float lm = -INFINITY;
        #pragma unroll
        for (int j=0;j<32;j++) {
            int m = part*32 + j;
            float s = Ps[rr*PS_LD + m];
            sv[j] = s;
            if (m < mvalid) lm = fmaxf(lm, s);
        }
        lm = fmaxf(lm, __shfl_xor_sync(0xffffffffu, lm, 1));
        float mnew = fmaxf(mrow, lm);
        float alpha = __expf(mrow - mnew);
        mrow = mnew;
        float ls = 0.f;
        #pragma unroll
        for (int j=0;j<32;j++) {
            int m = part*32 + j;
            float e = (m < mvalid) ? __expf(sv[j] - mnew) : 0.f;
            Ps[rr*PS_LD + m] = e;
            ls += e;
        }
        lrow = lrow*alpha + ls;
        #pragma unroll
        for (int d=0;d<HD;d++) O[d] *= alpha;

        #pragma unroll 8
        for (int ii=0; ii<32; ii++) {
            int m = ((ii + part) & 31) + part*32;
            float p = Ps[rr*PS_LD + m];
            const float* vrow = &Vt[m*VT_LD];
            #pragma unroll
            for (int d=0; d<HD; d+=4) {
                float4 v4 = *(const float4*)&vrow[d];
                O[d]   += p*v4.x;
                O[d+1] += p*v4.y;
                O[d+2] += p*v4.z;
                O[d+3] += p*v4.w;
            }
        }
    }

    float lt = lrow + __shfl_xor_sync(0xffffffffu, lrow, 1);
    float inv = 1.f / lt;
    int n = n0 + rr;
    #pragma unroll
    for (int d=0; d<HD; d++) {
        float o = O[d] + __shfl_xor_sync(0xffffffffu, O[d], 1);
        int mine = (part == 0) ? (d < 16) : (d >= 16);
        if (mine && n < NPT) oh[d*NPT + n] = o*inv;
    }
}

// ---------------- launch ------------------------------------------------------
static inline dim3 ggrid(int M, int Nc, int batches) {
    return dim3((Nc + TN - 1)/TN, (M + TM - 1)/TM, batches);
}

extern "C" void kernel_launch(void* const* d_in, const int* in_sizes, int n_in,
                              void* d_out, int out_size)
{
    const float* x    = (const float*)d_in[0];
    const float* y    = (const float*)d_in[1];
    const float* dgw1 = (const float*)d_in[2];
    const float* dgb1 = (const float*)d_in[3];
    const float* dgg1 = (const float*)d_in[4];
    const float* dgbe1= (const float*)d_in[5];
    const float* dgw2 = (const float*)d_in[6];
    const float* dgb2 = (const float*)d_in[7];
    const float* dgg2 = (const float*)d_in[8];
    const float* dgbe2= (const float*)d_in[9];
    const float* wq   = (const float*)d_in[10];
    const float* bq   = (const float*)d_in[11];
    const float* wk   = (const float*)d_in[12];
    const float* bk   = (const float*)d_in[13];
    const float* wv   = (const float*)d_in[14];
    const float* bv   = (const float*)d_in[15];
    const float* wmh  = (const float*)d_in[16];
    const float* bmh  = (const float*)d_in[17];
    const float* wc1  = (const float*)d_in[18];
    const float* bc1  = (const float*)d_in[19];
    const float* cg   = (const float*)d_in[20];
    const float* cbe  = (const float*)d_in[21];
    const float* wc2  = (const float*)d_in[22];
    const float* bc2  = (const float*)d_in[23];
    float* out = (float*)d_out;

    float *w1sb,*wkv,*bkv,*gram,*xx,*uv,*h,*h2,*agg,*q,*kvb,*add,*cat,*hc;
    int* idx;
    cudaGetSymbolAddress((void**)&w1sb, g_w1sb);
    cudaGetSymbolAddress((void**)&wkv,  g_wkv);
    cudaGetSymbolAddress((void**)&bkv,  g_bkv);
    cudaGetSymbolAddress((void**)&gram, g_gram);
    cudaGetSymbolAddress((void**)&xx,   g_xx);
    cudaGetSymbolAddress((void**)&idx,  g_idx);
    cudaGetSymbolAddress((void**)&uv,   g_uv);
    cudaGetSymbolAddress((void**)&h,    g_h);
    cudaGetSymbolAddress((void**)&h2,   g_h2);
    cudaGetSymbolAddress((void**)&agg,  g_agg);
    cudaGetSymbolAddress((void**)&q,    g_q);
    cudaGetSymbolAddress((void**)&kvb,  g_kv);
    cudaGetSymbolAddress((void**)&add,  g_add);
    cudaGetSymbolAddress((void**)&cat,  g_cat);
    cudaGetSymbolAddress((void**)&hc,   g_hc);

    const long long CN  = (long long)CCH*NPT;
    const long long NN  = (long long)NPT*NPT;
    const long long CNK = (long long)CCH*NPT*KNNK;
    const int FLASH_SMEM = (HD*QST_LD + HD*KT + KT*VT_LD + QT*PS_LD) * 4;

    cudaFuncSetAttribute(flash_kernel, cudaFuncAttributeMaxDynamicSharedMemorySize, FLASH_SMEM);

    // 1) prep
    prep_kernel<<<(CCH*CCH+255)/256, 256>>>(dgw1, wk, wv, bk, bv, w1sb, wkv, bkv);

    // 2) gram[b] = x^T x
    gemm_k<true,false><<<ggrid(NPT,NPT,BSZ), 256>>>(
        x, x, gram, NPT, NPT, CCH, NPT, NPT, NPT,
        CN, CN, NN, 1.f, nullptr, nullptr, nullptr, 0, nullptr, 0, 0);

    // 3) diag + top-9
    xx_kernel<<<(BSZ*NPT+255)/256, 256>>>(gram, xx);
    topk_kernel<<<dim3(NPT, BSZ), 256>>>(gram, xx, idx);

    // 4) uv = [w1s; w1b] @ x   (M=256)
    gemm_k<false,false><<<ggrid(2*CCH,NPT,BSZ), 256>>>(
        w1sb, x, uv, 2*CCH, NPT, CCH, CCH, NPT, NPT,
        0, CN, 2*CN, 1.f, nullptr, nullptr, nullptr, 0, nullptr, 0, 0);

    // 5) edge features -> h (bias+bn+relu fused)
    {
        long long total = (long long)BSZ*CNK;
        gather_h_kernel<<<(unsigned)((total+255)/256), 256>>>(uv, idx, dgb1, dgg1, dgbe1, h);
    }

    // 6) conv2 over 18000 cols, fused bn+relu
    gemm_k<false,false><<<ggrid(CCH, NPT*KNNK, BSZ), 256>>>(
        dgw2, h, h2, CCH, NPT*KNNK, CCH, CCH, NPT*KNNK, NPT*KNNK,
        0, CNK, CNK, 1.f, dgb2, dgg2, dgbe2, 1, nullptr, 0, 0);

    // 7) max over k -> agg (+ top half of cat)
    maxk_kernel<<<(BSZ*CCH*NPT+255)/256, 256>>>(h2, agg, cat);

    // 8) q = wq@agg + bq ; kv = [wk;wv]@y + [bk;bv]
    gemm_k<false,false><<<ggrid(CCH,NPT,BSZ), 256>>>(
        wq, agg, q, CCH, NPT, CCH, CCH, NPT, NPT,
        0, CN, CN, 1.f, bq, nullptr, nullptr, 0, nullptr, 0, 0);
    gemm_k<false,false><<<ggrid(2*CCH,NPT,BSZ), 256>>>(
        wkv, y, kvb, 2*CCH, NPT, CCH, CCH, NPT, NPT,
        0, CN, 2*CN, 1.f, bkv, nullptr, nullptr, 0, nullptr, 0, 0);

    // 9) fused attention -> add
    {
        dim3 grid((NPT + QT - 1)/QT, NHEAD, BSZ);
        flash_kernel<<<grid, 256, FLASH_SMEM>>>(q, kvb, add);
    }

    // 10) mh conv -> bottom half of cat
    gemm_k<false,false><<<ggrid(CCH,NPT,BSZ), 256>>>(
        wmh, add, cat + CN, CCH, NPT, CCH, CCH, NPT, NPT,
        0, CN, 2*CN, 1.f, bmh, nullptr, nullptr, 0, nullptr, 0, 0);

    // 11) hc = relu(bn(wc1 @ cat + bc1))
    gemm_k<false,false><<<ggrid(2*CCH,NPT,BSZ), 256>>>(
        wc1, cat, hc, 2*CCH, NPT, 2*CCH, 2*CCH, NPT, NPT,
        0, 2*CN, 2*CN, 1.f, bc1, cg, cbe, 1, nullptr, 0, 0);

    // 12) out = agg + wc2 @ hc + bc2
    gemm_k<false,false><<<ggrid(CCH,NPT,BSZ), 256>>>(
        wc2, hc, out, CCH, NPT, 2*CCH, 2*CCH, NPT, NPT,
        0, 2*CN, CN, 1.f, bc2, nullptr, nullptr, 0, agg, CN, NPT);
}

// round 6
// speedup vs baseline: 1.7608x; 1.0782x over previous
#include <cuda_runtime.h>
#include <math.h>

#define BSZ   4
#define CCH   128
#define NPT   2000
#define KNNK  9
#define NHEAD 4
#define HD    32
#define BN_EPS 1e-5f

// ---------------- scratch ------------------------------------------------
__device__ float g_w1sb[2*CCH*CCH];   // [w1a+w1b ; w1b] (256x128)
__device__ float g_wkv [2*CCH*CCH];   // [wk ; wv]
__device__ float g_bkv [2*CCH];
__device__ float g_gram[(size_t)BSZ*NPT*NPT];
__device__ float g_xx[BSZ*NPT];
__device__ int   g_idx[BSZ*NPT*KNNK];
__device__ float g_uv[BSZ*2*CCH*NPT];            // u rows 0..127, v rows 128..255
__device__ float g_h [(size_t)BSZ*CCH*NPT*KNNK];
__device__ float g_h2[(size_t)BSZ*CCH*NPT*KNNK];
__device__ float g_agg[BSZ*CCH*NPT];
__device__ float g_q  [BSZ*CCH*NPT];
__device__ float g_kv [BSZ*2*CCH*NPT];
__device__ float g_add[BSZ*CCH*NPT];
__device__ float g_cat[BSZ*2*CCH*NPT];
__device__ float g_hc [BSZ*2*CCH*NPT];

// ---------------- generic tiled SGEMM (reg-prefetch double buffer) --------
#define TM 128
#define TN 128
#define TK 8

template<bool TA, bool TB>
__global__ void __launch_bounds__(256) gemm_k(
    const float* __restrict__ A, const float* __restrict__ B, float* __restrict__ Cm,
    int M, int Nc, int Kc, int lda, int ldb, int ldc,
    long long sA, long long sB, long long sC,
    float alpha,
    const float* __restrict__ bias,
    const float* __restrict__ gamma, const float* __restrict__ beta,
    int relu,
    const float* __restrict__ resid, long long sR, int ldr)
{
    int bz = blockIdx.z;
    A  += (long long)bz * sA;
    B  += (long long)bz * sB;
    Cm += (long long)bz * sC;
    if (resid) resid += (long long)bz * sR;

    __shared__ float As[TK][TM];
    __shared__ float Bs[TK][TN];

    int m0 = blockIdx.y * TM;
    int n0 = blockIdx.x * TN;
    int tid = threadIdx.x;
    int tx = tid % 16, ty = tid / 16;

    float acc[8][8];
    #pragma unroll
    for (int i=0;i<8;i++)
        #pragma unroll
        for (int j=0;j<8;j++) acc[i][j] = 0.f;

    float ra[4], rb[4];

#define GK_LOAD(KT0) {                                                     \
    _Pragma("unroll")                                                      \
    for (int it=0; it<4; it++){                                            \
        int e = tid + it*256; int m_,k_;                                   \
        if (TA){ m_ = e % TM; k_ = e / TM; } else { k_ = e % TK; m_ = e / TK; } \
        int gm = m0+m_, gk = (KT0)+k_;                                     \
        ra[it] = (gm<M && gk<Kc) ? (TA ? A[(long long)gk*lda+gm]           \
                                       : A[(long long)gm*lda+gk]) : 0.f;   \
    }                                                                      \
    _Pragma("unroll")                                                      \
    for (int it=0; it<4; it++){                                            \
        int e = tid + it*256; int n_,k_;                                   \
        if (TB){ k_ = e % TK; n_ = e / TK; } else { n_ = e % TN; k_ = e / TN; } \
        int gn = n0+n_, gk = (KT0)+k_;                                     \
        rb[it] = (gn<Nc && gk<Kc) ? (TB ? B[(long long)gn*ldb+gk]          \
                                        : B[(long long)gk*ldb+gn]) : 0.f;  \
    } }

#define GK_STORE() {                                                       \
    _Pragma("unroll")                                                      \
    for (int it=0; it<4; it++){                                            \
        int e = tid + it*256; int m_,k_;                                   \
        if (TA){ m_ = e % TM; k_ = e / TM; } else { k_ = e % TK; m_ = e / TK; } \
        As[k_][m_] = ra[it];                                               \
    }                                                                      \
    _Pragma("unroll")                                                      \
    for (int it=0; it<4; it++){                                            \
        int e = tid + it*256; int n_,k_;                                   \
        if (TB){ k_ = e % TK; n_ = e / TK; } else { n_ = e % TN; k_ = e / TN; } \
        Bs[k_][n_] = rb[it];                                               \
    } }

#define GK_COMPUTE() {                                                     \
    _Pragma("unroll")                                                      \
    for (int kk=0; kk<TK; kk++){                                           \
        float4 a0 = *(const float4*)&As[kk][ty*8];                         \
        float4 a1 = *(const float4*)&As[kk][ty*8+4];                       \
        float4 b0 = *(const float4*)&Bs[kk][tx*8];                         \
        float4 b1 = *(const float4*)&Bs[kk][tx*8+4];                       \
        float av[8] = {a0.x,a0.y,a0.z,a0.w,a1.x,a1.y,a1.z,a1.w};           \
        float bv8[8] = {b0.x,b0.y,b0.z,b0.w,b1.x,b1.y,b1.z,b1.w};          \
        _Pragma("unroll")                                                  \
        for (int i=0;i<8;i++)                                              \
            _Pragma("unroll")                                              \
            for (int j=0;j<8;j++) acc[i][j] += av[i]*bv8[j];               \
    } }

    GK_LOAD(0);
    GK_STORE();
    for (int kt = TK; kt < Kc; kt += TK) {
        __syncthreads();
        GK_LOAD(kt);
        GK_COMPUTE();
        __syncthreads();
        GK_STORE();
    }
    __syncthreads();
    GK_COMPUTE();

    const float invs = rsqrtf(1.0f + BN_EPS);
    #pragma unroll
    for (int i=0;i<8;i++) {
        int gm = m0 + ty*8 + i;
        if (gm >= M) continue;
        float bi = bias  ? bias[gm]       : 0.f;
        float ga = gamma ? gamma[gm]*invs : 1.f;
        float be = beta  ? beta[gm]       : 0.f;
        #pragma unroll
        for (int j=0;j<8;j++) {
            int gn = n0 + tx*8 + j;
            if (gn >= Nc) continue;
            float r = acc[i][j]*alpha + bi;
            if (gamma) r = r*ga + be;
            if (relu)  r = fmaxf(r, 0.f);
            if (resid) r += resid[(long long)gm*ldr + gn];
            Cm[(long long)gm*ldc + gn] = r;
        }
    }
#undef GK_LOAD
#undef GK_STORE
#undef GK_COMPUTE
}

// ---------------- TN=64 variant for underfilled GEMMs (128 threads) --------
#define TN2 64

__global__ void __launch_bounds__(128) gemm_k64(
    const float* __restrict__ A, const float* __restrict__ B, float* __restrict__ Cm,
    int M, int Nc, int Kc, int lda, int ldb, int ldc,
    long long sA, long long sB, long long sC,
    const float* __restrict__ bias,
    const float* __restrict__ gamma, const float* __restrict__ beta,
    int relu,
    const float* __restrict__ resid, long long sR, int ldr)
{
    int bz = blockIdx.z;
    A  += (long long)bz * sA;
    B  += (long long)bz * sB;
    Cm += (long long)bz * sC;
    if (resid) resid += (long long)bz * sR;

    __shared__ float As[TK][TM];
    __shared__ float Bs[TK][TN2];

    int m0 = blockIdx.y * TM;
    int n0 = blockIdx.x * TN2;
    int tid = threadIdx.x;
    int tx = tid % 8, ty = tid / 8;   // 8 x 16

    float acc[8][8];
    #pragma unroll
    for (int i=0;i<8;i++)
        #pragma unroll
        for (int j=0;j<8;j++) acc[i][j] = 0.f;

    float ra[8], rb[4];

#define GQ_LOAD(KT0) {                                                     \
    _Pragma("unroll")                                                      \
    for (int it=0; it<8; it++){                                            \
        int e = tid + it*128;                                              \
        int k_ = e % TK, m_ = e / TK;                                      \
        int gm = m0+m_, gk = (KT0)+k_;                                     \
        ra[it] = (gm<M && gk<Kc) ? A[(long long)gm*lda+gk] : 0.f;          \
    }                                                                      \
    _Pragma("unroll")                                                      \
    for (int it=0; it<4; it++){                                            \
        int e = tid + it*128;                                              \
        int n_ = e % TN2, k_ = e / TN2;                                    \
        int gn = n0+n_, gk = (KT0)+k_;                                     \
        rb[it] = (gn<Nc && gk<Kc) ? B[(long long)gk*ldb+gn] : 0.f;         \
    } }

#define GQ_STORE() {                                                       \
    _Pragma("unroll")                                                      \
    for (int it=0; it<8; it++){                                            \
        int e = tid + it*128;                                              \
        int k_ = e % TK, m_ = e / TK;                                      \
        As[k_][m_] = ra[it];                                               \
    }                                                                      \
    _Pragma("unroll")                                                      \
    for (int it=0; it<4; it++){                                            \
        int e = tid + it*128;                                              \
        int n_ = e % TN2, k_ = e / TN2;                                    \
        Bs[k_][n_] = rb[it];                                               \
    } }

#define GQ_COMPUTE() {                                                     \
    _Pragma("unroll")                                                      \
    for (int kk=0; kk<TK; kk++){                                           \
        float4 a0 = *(const float4*)&As[kk][ty*8];                         \
        float4 a1 = *(const float4*)&As[kk][ty*8+4];                       \
        float4 b0 = *(const float4*)&Bs[kk][tx*8];                         \
        float4 b1 = *(const float4*)&Bs[kk][tx*8+4];                       \
        float av[8] = {a0.x,a0.y,a0.z,a0.w,a1.x,a1.y,a1.z,a1.w};           \
        float bv8[8] = {b0.x,b0.y,b0.z,b0.w,b1.x,b1.y,b1.z,b1.w};          \
        _Pragma("unroll")                                                  \
        for (int i=0;i<8;i++)                                              \
            _Pragma("unroll")                                              \
            for (int j=0;j<8;j++) acc[i][j] += av[i]*bv8[j];               \
    } }

    GQ_LOAD(0);
    GQ_STORE();
    for (int kt = TK; kt < Kc; kt += TK) {
        __syncthreads();
        GQ_LOAD(kt);
        GQ_COMPUTE();
        __syncthreads();
        GQ_STORE();
    }
    __syncthreads();
    GQ_COMPUTE();

    const float invs = rsqrtf(1.0f + BN_EPS);
    #pragma unroll
    for (int i=0;i<8;i++) {
        int gm = m0 + ty*8 + i;
        if (gm >= M) continue;
        float bi = bias  ? bias[gm]       : 0.f;
        float ga = gamma ? gamma[gm]*invs : 1.f;
        float be = beta  ? beta[gm]       : 0.f;
        #pragma unroll
        for (int j=0;j<8;j++) {
            int gn = n0 + tx*8 + j;
            if (gn >= Nc) continue;
            float r = acc[i][j] + bi;
            if (gamma) r = r*ga + be;
            if (relu)  r = fmaxf(r, 0.f);
            if (resid) r += resid[(long long)gm*ldr + gn];
            Cm[(long long)gm*ldc + gn] = r;
        }
    }
#undef GQ_LOAD
#undef GQ_STORE
#undef GQ_COMPUTE
}

// ---------------- symmetric Gram: upper-triangle tiles + mirrored store ----
__global__ void __launch_bounds__(256) gram_kernel(
    const float* __restrict__ x,     // [B][C][N]
    float* __restrict__ gram,        // [B][N][N]
    float* __restrict__ xx)          // [B][N]
{
    __shared__ float As[TK][TM];
    __shared__ float Bs[TK][TN];
    __shared__ float Ts[16][132];

    int b = blockIdx.z;
    const float* xb = x + (long long)b*CCH*NPT;
    float* gb = gram + (long long)b*NPT*NPT;

    // map linear tile id -> (bi, bj) with bi <= bj
    int t = blockIdx.x;
    int bj = 0;
    while ((bj+1)*(bj+2)/2 <= t) bj++;
    int bi = t - bj*(bj+1)/2;

    int m0 = bi * TM;        // rows
    int n0 = bj * TN;        // cols (>= rows tile)
    int tid = threadIdx.x;
    int tx = tid % 16, ty = tid / 16;

    float acc[8][8];
    #pragma unroll
    for (int i=0;i<8;i++)
        #pragma unroll
        for (int j=0;j<8;j++) acc[i][j] = 0.f;

    float ra[4], rb[4];

#define GR_LOAD(KT0) {                                                     \
    _Pragma("unroll")                                                      \
    for (int it=0; it<4; it++){                                            \
        int e = tid + it*256;                                              \
        int m_ = e % TM, k_ = e / TM;                                      \
        int gm = m0+m_;                                                    \
        ra[it] = (gm<NPT) ? xb[(long long)((KT0)+k_)*NPT+gm] : 0.f;        \
    }                                                                      \
    _Pragma("unroll")                                                      \
    for (int it=0; it<4; it++){                                            \
        int e = tid + it*256;                                              \
        int n_ = e % TN, k_ = e / TN;                                      \
        int gn = n0+n_;                                                    \
        rb[it] = (gn<NPT) ? xb[(long long)((KT0)+k_)*NPT+gn] : 0.f;        \
    } }

#define GR_STORE() {                                                       \
    _Pragma("unroll")                                                      \
    for (int it=0; it<4; it++){                                            \
        int e = tid + it*256;                                              \
        int m_ = e % TM, k_ = e / TM;                                      \
        As[k_][m_] = ra[it];                                               \
    }                                                                      \
    _Pragma("unroll")                                                      \
    for (int it=0; it<4; it++){                                            \
        int e = tid + it*256;                                              \
        int n_ = e % TN, k_ = e / TN;                                      \
        Bs[k_][n_] = rb[it];                                               \
    } }

#define GR_COMPUTE() {                                                     \
    _Pragma("unroll")                                                      \
    for (int kk=0; kk<TK; kk++){                                           \
        float4 a0 = *(const float4*)&As[kk][ty*8];                         \
        float4 a1 = *(const float4*)&As[kk][ty*8+4];                       \
        float4 b0 = *(const float4*)&Bs[kk][tx*8];                         \
        float4 b1 = *(const float4*)&Bs[kk][tx*8+4];                       \
        float av[8] = {a0.x,a0.y,a0.z,a0.w,a1.x,a1.y,a1.z,a1.w};           \
        float bv8[8] = {b0.x,b0.y,b0.z,b0.w,b1.x,b1.y,b1.z,b1.w};          \
        _Pragma("unroll")                                                  \
        for (int i=0;i<8;i++)                                              \
            _Pragma("unroll")                                              \
            for (int j=0;j<8;j++) acc[i][j] += av[i]*bv8[j];               \
    } }

    GR_LOAD(0);
    GR_STORE();
    for (int kt = TK; kt < CCH; kt += TK) {
        __syncthreads();
        GR_LOAD(kt);
        GR_COMPUTE();
        __syncthreads();
        GR_STORE();
    }
    __syncthreads();
    GR_COMPUTE();

    // direct (upper) store + diag
    #pragma unroll
    for (int i=0;i<8;i++) {
        int gm = m0 + ty*8 + i;
        if (gm >= NPT) continue;
        #pragma unroll
        for (int j=0;j<8;j++) {
            int gn = n0 + tx*8 + j;
            if (gn >= NPT) continue;
            gb[(long long)gm*NPT + gn] = acc[i][j];
            if (bi == bj && gm == gn) xx[b*NPT + gm] = acc[i][j];
        }
    }

    // mirrored (lower) store via smem transpose staging, 16 rows per chunk
    if (bi != bj) {
        #pragma unroll
        for (int c = 0; c < 8; c++) {
            __syncthreads();
            if ((tx >> 1) == c) {
                int jb = (tx & 1) * 8;            // 0 or 8 column offset in chunk
                #pragma unroll
                for (int i=0;i<8;i++)
                    #pragma unroll
                    for (int j=0;j<8;j++)
                        Ts[jb + j][ty*8 + i] = acc[i][j];
            }
            __syncthreads();
            #pragma unroll
            for (int it=0; it<8; it++) {
                int e = tid + it*256;
                int nl = e >> 7, ml = e & 127;
                int gn2 = n0 + c*16 + nl;
                int gm2 = m0 + ml;
                if (gn2 < NPT && gm2 < NPT)
                    gb[(long long)gn2*NPT + gm2] = Ts[nl][ml];
            }
        }
    }
#undef GR_LOAD
#undef GR_STORE
#undef GR_COMPUTE
}

// ---------------- prep ------------------------------------------------------
__global__ void prep_kernel(const float* __restrict__ w1,
                            const float* __restrict__ wk, const float* __restrict__ wv,
                            const float* __restrict__ bk, const float* __restrict__ bv,
                            float* __restrict__ w1sb, float* __restrict__ wkv,
                            float* __restrict__ bkv)
{
    int i = blockIdx.x*blockDim.x + threadIdx.x;
    if (i < CCH*CCH) {
        int o = i / CCH, c = i % CCH;
        float a  = w1[o*2*CCH + c];
        float bb = w1[o*2*CCH + CCH + c];
        w1sb[i] = a + bb;
        w1sb[CCH*CCH + i] = bb;
        wkv[i] = wk[i];
        wkv[CCH*CCH + i] = wv[i];
    }
    if (i < 2*CCH) bkv[i] = (i < CCH) ? bk[i] : bv[i - CCH];
}

// ---------------- topk: lane sort-8 + warp k-way merge -----------------------
__global__ void __launch_bounds__(256) topk_kernel(const float* __restrict__ gram,
                                                   const float* __restrict__ xx,
                                                   int* __restrict__ idx)
{
    int n = blockIdx.x, b = blockIdx.y;
    const float* row = gram + ((long long)(b*NPT+n))*NPT;
    const float* xb  = xx + b*NPT;
    int tid = threadIdx.x, w = tid >> 5, l = tid & 31;

    float v[8]; int id[8];
    #pragma unroll
    for (int j=0;j<8;j++){
        int m = w*256 + j*32 + l;
        bool ok = m < NPT;
        v[j]  = ok ? (2.f*row[m] - xb[m]) : -INFINITY;
        id[j] = ok ? m : 0x7fffffff;
    }
#define CSWP(a,bb) { bool sw = (v[a]<v[bb]) || (v[a]==v[bb] && id[a]>id[bb]); \
    float tv = sw?v[bb]:v[a]; float uv2 = sw?v[a]:v[bb]; v[a]=tv; v[bb]=uv2;   \
    int ti = sw?id[bb]:id[a]; int ui = sw?id[a]:id[bb]; id[a]=ti; id[bb]=ui; }
    CSWP(0,1) CSWP(2,3) CSWP(4,5) CSWP(6,7)
    CSWP(0,2) CSWP(1,3) CSWP(4,6) CSWP(5,7)
    CSWP(1,2) CSWP(5,6)
    CSWP(0,4) CSWP(1,5) CSWP(2,6) CSWP(3,7)
    CSWP(2,4) CSWP(3,5)
    CSWP(1,2) CSWP(3,4) CSWP(5,6)
#undef CSWP

    __shared__ float wv[8][12];
    __shared__ int   wi[8][12];

    float hv = v[0]; int hi = id[0];
    #pragma unroll
    for (int t=0;t<KNNK;t++){
        float bvv = hv; int bii = hi;
        #pragma unroll
        for (int s=16; s>0; s>>=1){
            float ov = __shfl_xor_sync(0xffffffffu, bvv, s);
            int   oi = __shfl_xor_sync(0xffffffffu, bii, s);
            if (ov > bvv || (ov == bvv && oi < bii)) { bvv = ov; bii = oi; }
        }
        if (l == 0) { wv[w][t] = bvv; wi[w][t] = bii; }
        if (hi == bii) {
            #pragma unroll
            for (int j=0;j<7;j++){ v[j]=v[j+1]; id[j]=id[j+1]; }
            v[7] = -INFINITY; id[7] = 0x7fffffff;
            hv = v[0]; hi = id[0];
        }
    }
    __syncthreads();

    if (w == 0){
        int ptr = 0;
        float hv2 = (l < 8) ? wv[l][0] : -INFINITY;
        int   hi2 = (l < 8) ? wi[l][0] : 0x7fffffff;
        int* outp = idx + (b*NPT+n)*KNNK;
        #pragma unroll
        for (int t=0;t<KNNK;t++){
            float bvv = hv2; int bii = hi2;
            #pragma unroll
            for (int s=16; s>0; s>>=1){
                float ov = __shfl_xor_sync(0xffffffffu, bvv, s);
                int   oi = __shfl_xor_sync(0xffffffffu, bii, s);
                if (ov > bvv || (ov == bvv && oi < bii)) { bvv = ov; bii = oi; }
            }
            if (l == 0) outp[t] = bii;
            if (hi2 == bii){
                ptr++;
                hv2 = (ptr < KNNK && l < 8) ? wv[l][ptr] : -INFINITY;
                hi2 = (ptr < KNNK && l < 8) ? wi[l][ptr] : 0x7fffffff;
            }
        }
    }
}

// h[b,c,n*9+k] = relu( bn( u[b,c,n] - v[b,c,idx] + b1[c] ) )
__global__ void gather_h_kernel(const float* __restrict__ uv,
                                const int* __restrict__ idx,
                                const float* __restrict__ b1, const float* __restrict__ g1,
                                const float* __restrict__ be1, float* __restrict__ h)
{
    long long i = (long long)blockIdx.x*blockDim.x + threadIdx.x;
    const long long total = (long long)BSZ*CCH*NPT*KNNK;
    if (i >= total) return;
    int k = (int)(i % KNNK);
    long long r = i / KNNK;
    int n = (int)(r % NPT); r /= NPT;
    int c = (int)(r % CCH);
    int b = (int)(r / CCH);
    int j = idx[(b*NPT+n)*KNNK + k];
    const float* ub = uv + (long long)b*2*CCH*NPT + (long long)c*NPT;
    float uvv = ub[n];
    float vg  = ub[(long long)CCH*NPT + j];
    const float invs = rsqrtf(1.f + BN_EPS);
    float val = (uvv - vg + b1[c]) * (g1[c]*invs) + be1[c];
    h[((long long)(b*CCH+c))*NPT*KNNK + (long long)n*KNNK + k] = fmaxf(val, 0.f);
}

// agg[b,c,n] = max_k h2[...]; also writes top half of cat
__global__ void maxk_kernel(const float* __restrict__ h2,
                            float* __restrict__ agg, float* __restrict__ cat)
{
    int i = blockIdx.x*blockDim.x + threadIdx.x;
    if (i >= BSZ*CCH*NPT) return;
    int n = i % NPT;
    int c = (i / NPT) % CCH;
    int b = i / (NPT*CCH);
    const float* p = h2 + ((long long)(b*CCH+c))*NPT*KNNK + (long long)n*KNNK;
    float m = p[0];
    #pragma unroll
    for (int k = 1; k < KNNK; k++) m = fmaxf(m, p[k]);
    agg[i] = m;
    cat[(long long)b*2*CCH*NPT + (long long)c*NPT + n] = m;
}

// ---------------- flash attention (R2 proven version) -------------------------
#define QT 128
#define KT 64
#define QST_LD 132
#define VT_LD  36
#define PS_LD  68

__global__ void __launch_bounds__(256,2) flash_kernel(
    const float* __restrict__ q,   // [B][C][N]
    const float* __restrict__ kv,  // [B][2C][N]
    float* __restrict__ add)       // [B][C][N]
{
    extern __shared__ float sm[];
    float* Qst = sm;                         // [32][132]
    float* Ks  = Qst + HD*QST_LD;            // [32][64]
    float* Vt  = Ks  + HD*KT;                // [64][36]
    float* Ps  = Vt  + KT*VT_LD;             // [128][68]

    int n0 = blockIdx.x * QT;
    int h  = blockIdx.y;
    int b  = blockIdx.z;
    const float* qh = q  + ((long long)b*CCH   + h*HD)*NPT;
    const float* kh = kv + ((long long)b*2*CCH + h*HD)*NPT;
    const float* vh = kv + ((long long)b*2*CCH + CCH + h*HD)*NPT;
    float* oh = add + ((long long)b*CCH + h*HD)*NPT;

    int tid = threadIdx.x;
    for (int e = tid; e < HD*QT; e += 256) {
        int d = e >> 7, r = e & 127;
        int n = n0 + r;
        Qst[d*QST_LD + r] = (n < NPT) ? qh[d*NPT + n] : 0.f;
    }

    int ty = tid >> 4, tx = tid & 15;
    int rr = tid >> 1, part = tid & 1;

    float mrow = -INFINITY, lrow = 0.f;
    float O[HD];
    #pragma unroll
    for (int d=0; d<HD; d++) O[d] = 0.f;

    const float scale = 0.17677669529663689f;
    const int ntiles = (NPT + KT - 1)/KT;

    for (int t = 0; t < ntiles; t++) {
        int m0 = t*KT;
        __syncthreads();
        #pragma unroll
        for (int e = tid; e < HD*KT; e += 256) {
            int d = e >> 6, c = e & 63;
            int m = m0 + c;
            float kvld = (m < NPT) ? kh[d*NPT + m] : 0.f;
            float vvld = (m < NPT) ? vh[d*NPT + m] : 0.f;
            Ks[d*KT + c]  = kvld;
            Vt[c*VT_LD + d] = vvld;
        }
        __syncthreads();

        float acc[8][4];
        #pragma unroll
        for (int i=0;i<8;i++)
            #pragma unroll
            for (int j=0;j<4;j++) acc[i][j] = 0.f;
        #pragma unroll
        for (int kk=0; kk<HD; kk++) {
            float4 a0 = *(const float4*)&Qst[kk*QST_LD + ty*8];
            float4 a1 = *(const float4*)&Qst[kk*QST_LD + ty*8 + 4];
            float4 b4 = *(const float4*)&Ks[kk*KT + tx*4];
            float a[8] = {a0.x,a0.y,a0.z,a0.w,a1.x,a1.y,a1.z,a1.w};
            float bb[4] = {b4.x,b4.y,b4.z,b4.w};
            #pragma unroll
            for (int i=0;i<8;i++)
                #pragma unroll
                for (int j=0;j<4;j++) acc[i][j] += a[i]*bb[j];
        }
        #pragma unroll
        for (int i=0;i<8;i++)
            #pragma unroll
            for (int j=0;j<4;j++)
                Ps[(ty*8+i)*PS_LD + tx*4+j] = acc[i][j]*scale;
        __syncthreads();

        int mvalid = NPT - m0;
        float sv[32];
        float lm = -INFINITY;
        #pragma unroll
        for (int j=0;j<32;j++) {
            int m = part*32 + j;
            float s = Ps[rr*PS_LD + m];
            sv[j] = s;
            if (m < mvalid) lm = fmaxf(lm, s);
        }
        lm = fmaxf(lm, __shfl_xor_sync(0xffffffffu, lm, 1));
        float mnew = fmaxf(mrow, lm);
        float alpha = __expf(mrow - mnew);
        mrow = mnew;
        float ls = 0.f;
        #pragma unroll
        for (int j=0;j<32;j++) {
            int m = part*32 + j;
            float e = (m < mvalid) ? __expf(sv[j] - mnew) : 0.f;
            Ps[rr*PS_LD + m] = e;
            ls += e;
        }
        lrow = lrow*alpha + ls;
        #pragma unroll
        for (int d=0;d<HD;d++) O[d] *= alpha;

        #pragma unroll 8
        for (int ii=0; ii<32; ii++) {
            int m = ((ii + part) & 31) + part*32;
            float p = Ps[rr*PS_LD + m];
            const float* vrow = &Vt[m*VT_LD];
            #pragma unroll
            for (int d=0; d<HD; d+=4) {
                float4 v4 = *(const float4*)&vrow[d];
                O[d]   += p*v4.x;
                O[d+1] += p*v4.y;
                O[d+2] += p*v4.z;
                O[d+3] += p*v4.w;
            }
        }
    }

    float lt = lrow + __shfl_xor_sync(0xffffffffu, lrow, 1);
    float inv = 1.f / lt;
    int n = n0 + rr;
    #pragma unroll
    for (int d=0; d<HD; d++) {
        float o = O[d] + __shfl_xor_sync(0xffffffffu, O[d], 1);
        int mine = (part == 0) ? (d < 16) : (d >= 16);
        if (mine && n < NPT) oh[d*NPT + n] = o*inv;
    }
}

// ---------------- launch ------------------------------------------------------
static inline dim3 ggrid(int M, int Nc, int batches) {
    return dim3((Nc + TN - 1)/TN, (M + TM - 1)/TM, batches);
}
static inline dim3 ggrid64(int M, int Nc, int batches) {
    return dim3((Nc + TN2 - 1)/TN2, (M + TM - 1)/TM, batches);
}

extern "C" void kernel_launch(void* const* d_in, const int* in_sizes, int n_in,
                              void* d_out, int out_size)
{
    const float* x    = (const float*)d_in[0];
    const float* y    = (const float*)d_in[1];
    const float* dgw1 = (const float*)d_in[2];
    const float* dgb1 = (const float*)d_in[3];
    const float* dgg1 = (const float*)d_in[4];
    const float* dgbe1= (const float*)d_in[5];
    const float* dgw2 = (const float*)d_in[6];
    const float* dgb2 = (const float*)d_in[7];
    const float* dgg2 = (const float*)d_in[8];
    const float* dgbe2= (const float*)d_in[9];
    const float* wq   = (const float*)d_in[10];
    const float* bq   = (const float*)d_in[11];
    const float* wk   = (const float*)d_in[12];
    const float* bk   = (const float*)d_in[13];
    const float* wv   = (const float*)d_in[14];
    const float* bv   = (const float*)d_in[15];
    const float* wmh  = (const float*)d_in[16];
    const float* bmh  = (const float*)d_in[17];
    const float* wc1  = (const float*)d_in[18];
    const float* bc1  = (const float*)d_in[19];
    const float* cg   = (const float*)d_in[20];
    const float* cbe  = (const float*)d_in[21];
    const float* wc2  = (const float*)d_in[22];
    const float* bc2  = (const float*)d_in[23];
    float* out = (float*)d_out;

    float *w1sb,*wkv,*bkv,*gram,*xx,*uv,*h,*h2,*agg,*q,*kvb,*add,*cat,*hc;
    int* idx;
    cudaGetSymbolAddress((void**)&w1sb, g_w1sb);
    cudaGetSymbolAddress((void**)&wkv,  g_wkv);
    cudaGetSymbolAddress((void**)&bkv,  g_bkv);
    cudaGetSymbolAddress((void**)&gram, g_gram);
    cudaGetSymbolAddress((void**)&xx,   g_xx);
    cudaGetSymbolAddress((void**)&idx,  g_idx);
    cudaGetSymbolAddress((void**)&uv,   g_uv);
    cudaGetSymbolAddress((void**)&h,    g_h);
    cudaGetSymbolAddress((void**)&h2,   g_h2);
    cudaGetSymbolAddress((void**)&agg,  g_agg);
    cudaGetSymbolAddress((void**)&q,    g_q);
    cudaGetSymbolAddress((void**)&kvb,  g_kv);
    cudaGetSymbolAddress((void**)&add,  g_add);
    cudaGetSymbolAddress((void**)&cat,  g_cat);
    cudaGetSymbolAddress((void**)&hc,   g_hc);

    const long long CN  = (long long)CCH*NPT;
    const long long CNK = (long long)CCH*NPT*KNNK;
    const int FLASH_SMEM = (HD*QST_LD + HD*KT + KT*VT_LD + QT*PS_LD) * 4;
    const int NTILES = (NPT + TM - 1)/TM;                 // 16
    const int NTRI = NTILES*(NTILES+1)/2;                 // 136

    cudaFuncSetAttribute(flash_kernel, cudaFuncAttributeMaxDynamicSharedMemorySize, FLASH_SMEM);

    // 1) prep
    prep_kernel<<<(CCH*CCH+255)/256, 256>>>(dgw1, wk, wv, bk, bv, w1sb, wkv, bkv);

    // 2) gram[b] = x^T x  (triangular tiles + mirror) ; diag -> xx
    gram_kernel<<<dim3(NTRI, 1, BSZ), 256>>>(x, gram, xx);

    // 3) top-9
    topk_kernel<<<dim3(NPT, BSZ), 256>>>(gram, xx, idx);

    // 4) uv = [w1s; w1b] @ x   (M=256)
    gemm_k64<<<ggrid64(2*CCH,NPT,BSZ), 128>>>(
        w1sb, x, uv, 2*CCH, NPT, CCH, CCH, NPT, NPT,
        0, CN, 2*CN, nullptr, nullptr, nullptr, 0, nullptr, 0, 0);

    // 5) edge features -> h (bias+bn+relu fused)
    {
        long long total = (long long)BSZ*CNK;
        gather_h_kernel<<<(unsigned)((total+255)/256), 256>>>(uv, idx, dgb1, dgg1, dgbe1, h);
    }

    // 6) conv2 over 18000 cols, fused bn+relu
    gemm_k<false,false><<<ggrid(CCH, NPT*KNNK, BSZ), 256>>>(
        dgw2, h, h2, CCH, NPT*KNNK, CCH, CCH, NPT*KNNK, NPT*KNNK,
        0, CNK, CNK, 1.f, dgb2, dgg2, dgbe2, 1, nullptr, 0, 0);

    // 7) max over k -> agg (+ top half of cat)
    maxk_kernel<<<(BSZ*CCH*NPT+255)/256, 256>>>(h2, agg, cat);

    // 8) q = wq@agg + bq ; kv = [wk;wv]@y + [bk;bv]
    gemm_k64<<<ggrid64(CCH,NPT,BSZ), 128>>>(
        wq, agg, q, CCH, NPT, CCH, CCH, NPT, NPT,
        0, CN, CN, bq, nullptr, nullptr, 0, nullptr, 0, 0);
    gemm_k64<<<ggrid64(2*CCH,NPT,BSZ), 128>>>(
        wkv, y, kvb, 2*CCH, NPT, CCH, CCH, NPT, NPT,
        0, CN, 2*CN, bkv, nullptr, nullptr, 0, nullptr, 0, 0);

    // 9) fused attention -> add
    {
        dim3 grid((NPT + QT - 1)/QT, NHEAD, BSZ);
        flash_kernel<<<grid, 256, FLASH_SMEM>>>(q, kvb, add);
    }

    // 10) mh conv -> bottom half of cat
    gemm_k64<<<ggrid64(CCH,NPT,BSZ), 128>>>(
        wmh, add, cat + CN, CCH, NPT, CCH, CCH, NPT, NPT,
        0, CN, 2*CN, bmh, nullptr, nullptr, 0, nullptr, 0, 0);

    // 11) hc = relu(bn(wc1 @ cat + bc1))
    gemm_k64<<<ggrid64(2*CCH,NPT,BSZ), 128>>>(
        wc1, cat, hc, 2*CCH, NPT, 2*CCH, 2*CCH, NPT, NPT,
        0, 2*CN, 2*CN, bc1, cg, cbe, 1, nullptr, 0, 0);

    // 12) out = agg + wc2 @ hc + bc2
    gemm_k64<<<ggrid64(CCH,NPT,BSZ), 128>>>(
        wc2, hc, out, CCH, NPT, 2*CCH, 2*CCH, NPT, NPT,
        0, 2*CN, CN, bc2, nullptr, nullptr, 0, agg, CN, NPT);
}

// round 7
// speedup vs baseline: 2.3118x; 1.3129x over previous
#include <cuda_runtime.h>
#include <math.h>
#include <stdint.h>

#define BSZ   4
#define CCH   128
#define NPT   2000
#define KNNK  9
#define NHEAD 4
#define HD    32
#define BN_EPS 1e-5f

// ---------------- scratch ------------------------------------------------
__device__ float g_w1sb[2*CCH*CCH];
__device__ float g_wkv [2*CCH*CCH];
__device__ float g_bkv [2*CCH];
__device__ float g_gram[(size_t)BSZ*NPT*NPT];
__device__ float g_xx[BSZ*NPT];
__device__ int   g_idx[BSZ*NPT*KNNK];
__device__ float g_uv[BSZ*2*CCH*NPT];
__device__ float g_h [(size_t)BSZ*CCH*NPT*KNNK];
__device__ float g_h2[(size_t)BSZ*CCH*NPT*KNNK];
__device__ float g_agg[BSZ*CCH*NPT];
__device__ float g_q  [BSZ*CCH*NPT];
__device__ float g_kv [BSZ*2*CCH*NPT];
__device__ float g_add[BSZ*CCH*NPT];
__device__ float g_cat[BSZ*2*CCH*NPT];
__device__ float g_hc [BSZ*2*CCH*NPT];

// ---------------- generic tiled SGEMM (reg-prefetch double buffer) --------
#define TM 128
#define TN 128
#define TK 8

template<bool TA, bool TB>
__global__ void __launch_bounds__(256) gemm_k(
    const float* __restrict__ A, const float* __restrict__ B, float* __restrict__ Cm,
    int M, int Nc, int Kc, int lda, int ldb, int ldc,
    long long sA, long long sB, long long sC,
    float alpha,
    const float* __restrict__ bias,
    const float* __restrict__ gamma, const float* __restrict__ beta,
    int relu,
    const float* __restrict__ resid, long long sR, int ldr)
{
    int bz = blockIdx.z;
    A  += (long long)bz * sA;
    B  += (long long)bz * sB;
    Cm += (long long)bz * sC;
    if (resid) resid += (long long)bz * sR;

    __shared__ float As[TK][TM];
    __shared__ float Bs[TK][TN];

    int m0 = blockIdx.y * TM;
    int n0 = blockIdx.x * TN;
    int tid = threadIdx.x;
    int tx = tid % 16, ty = tid / 16;

    float acc[8][8];
    #pragma unroll
    for (int i=0;i<8;i++)
        #pragma unroll
        for (int j=0;j<8;j++) acc[i][j] = 0.f;

    float ra[4], rb[4];

#define GK_LOAD(KT0) {                                                     \
    _Pragma("unroll")                                                      \
    for (int it=0; it<4; it++){                                            \
        int e = tid + it*256; int m_,k_;                                   \
        if (TA){ m_ = e % TM; k_ = e / TM; } else { k_ = e % TK; m_ = e / TK; } \
        int gm = m0+m_, gk = (KT0)+k_;                                     \
        ra[it] = (gm<M && gk<Kc) ? (TA ? A[(long long)gk*lda+gm]           \
                                       : A[(long long)gm*lda+gk]) : 0.f;   \
    }                                                                      \
    _Pragma("unroll")                                                      \
    for (int it=0; it<4; it++){                                            \
        int e = tid + it*256; int n_,k_;                                   \
        if (TB){ k_ = e % TK; n_ = e / TK; } else { n_ = e % TN; k_ = e / TN; } \
        int gn = n0+n_, gk = (KT0)+k_;                                     \
        rb[it] = (gn<Nc && gk<Kc) ? (TB ? B[(long long)gn*ldb+gk]          \
                                        : B[(long long)gk*ldb+gn]) : 0.f;  \
    } }

#define GK_STORE() {                                                       \
    _Pragma("unroll")                                                      \
    for (int it=0; it<4; it++){                                            \
        int e = tid + it*256; int m_,k_;                                   \
        if (TA){ m_ = e % TM; k_ = e / TM; } else { k_ = e % TK; m_ = e / TK; } \
        As[k_][m_] = ra[it];                                               \
    }                                                                      \
    _Pragma("unroll")                                                      \
    for (int it=0; it<4; it++){                                            \
        int e = tid + it*256; int n_,k_;                                   \
        if (TB){ k_ = e % TK; n_ = e / TK; } else { n_ = e % TN; k_ = e / TN; } \
        Bs[k_][n_] = rb[it];                                               \
    } }

#define GK_COMPUTE() {                                                     \
    _Pragma("unroll")                                                      \
    for (int kk=0; kk<TK; kk++){                                           \
        float4 a0 = *(const float4*)&As[kk][ty*8];                         \
        float4 a1 = *(const float4*)&As[kk][ty*8+4];                       \
        float4 b0 = *(const float4*)&Bs[kk][tx*8];                         \
        float4 b1 = *(const float4*)&Bs[kk][tx*8+4];                       \
        float av[8] = {a0.x,a0.y,a0.z,a0.w,a1.x,a1.y,a1.z,a1.w};           \
        float bv8[8] = {b0.x,b0.y,b0.z,b0.w,b1.x,b1.y,b1.z,b1.w};          \
        _Pragma("unroll")                                                  \
        for (int i=0;i<8;i++)                                              \
            _Pragma("unroll")                                              \
            for (int j=0;j<8;j++) acc[i][j] += av[i]*bv8[j];               \
    } }

    GK_LOAD(0);
    GK_STORE();
    for (int kt = TK; kt < Kc; kt += TK) {
        __syncthreads();
        GK_LOAD(kt);
        GK_COMPUTE();
        __syncthreads();
        GK_STORE();
    }
    __syncthreads();
    GK_COMPUTE();

    const float invs = rsqrtf(1.0f + BN_EPS);
    #pragma unroll
    for (int i=0;i<8;i++) {
        int gm = m0 + ty*8 + i;
        if (gm >= M) continue;
        float bi = bias  ? bias[gm]       : 0.f;
        float ga = gamma ? gamma[gm]*invs : 1.f;
        float be = beta  ? beta[gm]       : 0.f;
        #pragma unroll
        for (int j=0;j<8;j++) {
            int gn = n0 + tx*8 + j;
            if (gn >= Nc) continue;
            float r = acc[i][j]*alpha + bi;
            if (gamma) r = r*ga + be;
            if (relu)  r = fmaxf(r, 0.f);
            if (resid) r += resid[(long long)gm*ldr + gn];
            Cm[(long long)gm*ldc + gn] = r;
        }
    }
#undef GK_LOAD
#undef GK_STORE
#undef GK_COMPUTE
}

// ---------------- TN=64, 256-thread variant (low reg pressure) ------------
#define TN2 64

__global__ void __launch_bounds__(256) gemm_k64b(
    const float* __restrict__ A, const float* __restrict__ B, float* __restrict__ Cm,
    int M, int Nc, int Kc, int lda, int ldb, int ldc,
    long long sA, long long sB, long long sC,
    const float* __restrict__ bias,
    const float* __restrict__ gamma, const float* __restrict__ beta,
    int relu,
    const float* __restrict__ resid, long long sR, int ldr)
{
    int bz = blockIdx.z;
    A  += (long long)bz * sA;
    B  += (long long)bz * sB;
    Cm += (long long)bz * sC;
    if (resid) resid += (long long)bz * sR;

    __shared__ float As[TK][TM];
    __shared__ float Bs[TK][TN2];

    int m0 = blockIdx.y * TM;
    int n0 = blockIdx.x * TN2;
    int tid = threadIdx.x;
    int tx = tid % 16, ty = tid / 16;   // cols tx*4, rows ty*8

    float acc[8][4];
    #pragma unroll
    for (int i=0;i<8;i++)
        #pragma unroll
        for (int j=0;j<4;j++) acc[i][j] = 0.f;

    float ra[4], rb[2];

#define GB_LOAD(KT0) {                                                     \
    _Pragma("unroll")                                                      \
    for (int it=0; it<4; it++){                                            \
        int e = tid + it*256;                                              \
        int k_ = e % TK, m_ = e / TK;                                      \
        int gm = m0+m_, gk = (KT0)+k_;                                     \
        ra[it] = (gm<M && gk<Kc) ? A[(long long)gm*lda+gk] : 0.f;          \
    }                                                                      \
    _Pragma("unroll")                                                      \
    for (int it=0; it<2; it++){                                            \
        int e = tid + it*256;                                              \
        int n_ = e % TN2, k_ = e / TN2;                                    \
        int gn = n0+n_, gk = (KT0)+k_;                                     \
        rb[it] = (gn<Nc && gk<Kc) ? B[(long long)gk*ldb+gn] : 0.f;         \
    } }

#define GB_STORE() {                                                       \
    _Pragma("unroll")                                                      \
    for (int it=0; it<4; it++){                                            \
        int e = tid + it*256;                                              \
        int k_ = e % TK, m_ = e / TK;                                      \
        As[k_][m_] = ra[it];                                               \
    }                                                                      \
    _Pragma("unroll")                                                      \
    for (int it=0; it<2; it++){                                            \
        int e = tid + it*256;                                              \
        int n_ = e % TN2, k_ = e / TN2;                                    \
        Bs[k_][n_] = rb[it];                                               \
    } }

#define GB_COMPUTE() {                                                     \
    _Pragma("unroll")                                                      \
    for (int kk=0; kk<TK; kk++){                                           \
        float4 a0 = *(const float4*)&As[kk][ty*8];                         \
        float4 a1 = *(const float4*)&As[kk][ty*8+4];                       \
        float4 b0 = *(const float4*)&Bs[kk][tx*4];                         \
        float av[8] = {a0.x,a0.y,a0.z,a0.w,a1.x,a1.y,a1.z,a1.w};           \
        float bv4[4] = {b0.x,b0.y,b0.z,b0.w};                              \
        _Pragma("unroll")                                                  \
        for (int i=0;i<8;i++)                                              \
            _Pragma("unroll")                                              \
            for (int j=0;j<4;j++) acc[i][j] += av[i]*bv4[j];               \
    } }

    GB_LOAD(0);
    GB_STORE();
    for (int kt = TK; kt < Kc; kt += TK) {
        __syncthreads();
        GB_LOAD(kt);
        GB_COMPUTE();
        __syncthreads();
        GB_STORE();
    }
    __syncthreads();
    GB_COMPUTE();

    const float invs = rsqrtf(1.0f + BN_EPS);
    #pragma unroll
    for (int i=0;i<8;i++) {
        int gm = m0 + ty*8 + i;
        if (gm >= M) continue;
        float bi = bias  ? bias[gm]       : 0.f;
        float ga = gamma ? gamma[gm]*invs : 1.f;
        float be = beta  ? beta[gm]       : 0.f;
        #pragma unroll
        for (int j=0;j<4;j++) {
            int gn = n0 + tx*4 + j;
            if (gn >= Nc) continue;
            float r = acc[i][j] + bi;
            if (gamma) r = r*ga + be;
            if (relu)  r = fmaxf(r, 0.f);
            if (resid) r += resid[(long long)gm*ldr + gn];
            Cm[(long long)gm*ldc + gn] = r;
        }
    }
#undef GB_LOAD
#undef GB_STORE
#undef GB_COMPUTE
}

// ---------------- symmetric Gram: upper-triangle tiles + mirrored store ----
__global__ void __launch_bounds__(256) gram_kernel(
    const float* __restrict__ x,
    float* __restrict__ gram,
    float* __restrict__ xx)
{
    __shared__ float As[TK][TM];
    __shared__ float Bs[TK][TN];
    __shared__ float Ts[16][132];

    int b = blockIdx.z;
    const float* xb = x + (long long)b*CCH*NPT;
    float* gb = gram + (long long)b*NPT*NPT;

    int t = blockIdx.x;
    int bj = 0;
    while ((bj+1)*(bj+2)/2 <= t) bj++;
    int bi = t - bj*(bj+1)/2;

    int m0 = bi * TM;
    int n0 = bj * TN;
    int tid = threadIdx.x;
    int tx = tid % 16, ty = tid / 16;

    float acc[8][8];
    #pragma unroll
    for (int i=0;i<8;i++)
        #pragma unroll
        for (int j=0;j<8;j++) acc[i][j] = 0.f;

    float ra[4], rb[4];

#define GR_LOAD(KT0) {                                                     \
    _Pragma("unroll")                                                      \
    for (int it=0; it<4; it++){                                            \
        int e = tid + it*256;                                              \
        int m_ = e % TM, k_ = e / TM;                                      \
        int gm = m0+m_;                                                    \
        ra[it] = (gm<NPT) ? xb[(long long)((KT0)+k_)*NPT+gm] : 0.f;        \
    }                                                                      \
    _Pragma("unroll")                                                      \
    for (int it=0; it<4; it++){                                            \
        int e = tid + it*256;                                              \
        int n_ = e % TN, k_ = e / TN;                                      \
        int gn = n0+n_;                                                    \
        rb[it] = (gn<NPT) ? xb[(long long)((KT0)+k_)*NPT+gn] : 0.f;        \
    } }

#define GR_STORE() {                                                       \
    _Pragma("unroll")                                                      \
    for (int it=0; it<4; it++){                                            \
        int e = tid + it*256;                                              \
        int m_ = e % TM, k_ = e / TM;                                      \
        As[k_][m_] = ra[it];                                               \
    }                                                                      \
    _Pragma("unroll")                                                      \
    for (int it=0; it<4; it++){                                            \
        int e = tid + it*256;                                              \
        int n_ = e % TN, k_ = e / TN;                                      \
        Bs[k_][n_] = rb[it];                                               \
    } }

#define GR_COMPUTE() {                                                     \
    _Pragma("unroll")                                                      \
    for (int kk=0; kk<TK; kk++){                                           \
        float4 a0 = *(const float4*)&As[kk][ty*8];                         \
        float4 a1 = *(const float4*)&As[kk][ty*8+4];                       \
        float4 b0 = *(const float4*)&Bs[kk][tx*8];                         \
        float4 b1 = *(const float4*)&Bs[kk][tx*8+4];                       \
        float av[8] = {a0.x,a0.y,a0.z,a0.w,a1.x,a1.y,a1.z,a1.w};           \
        float bv8[8] = {b0.x,b0.y,b0.z,b0.w,b1.x,b1.y,b1.z,b1.w};          \
        _Pragma("unroll")                                                  \
        for (int i=0;i<8;i++)                                              \
            _Pragma("unroll")                                              \
            for (int j=0;j<8;j++) acc[i][j] += av[i]*bv8[j];               \
    } }

    GR_LOAD(0);
    GR_STORE();
    for (int kt = TK; kt < CCH; kt += TK) {
        __syncthreads();
        GR_LOAD(kt);
        GR_COMPUTE();
        __syncthreads();
        GR_STORE();
    }
    __syncthreads();
    GR_COMPUTE();

    #pragma unroll
    for (int i=0;i<8;i++) {
        int gm = m0 + ty*8 + i;
        if (gm >= NPT) continue;
        #pragma unroll
        for (int j=0;j<8;j++) {
            int gn = n0 + tx*8 + j;
            if (gn >= NPT) continue;
            gb[(long long)gm*NPT + gn] = acc[i][j];
            if (bi == bj && gm == gn) xx[b*NPT + gm] = acc[i][j];
        }
    }

    if (bi != bj) {
        #pragma unroll
        for (int c = 0; c < 8; c++) {
            __syncthreads();
            if ((tx >> 1) == c) {
                int jb = (tx & 1) * 8;
                #pragma unroll
                for (int i=0;i<8;i++)
                    #pragma unroll
                    for (int j=0;j<8;j++)
                        Ts[jb + j][ty*8 + i] = acc[i][j];
            }
            __syncthreads();
            #pragma unroll
            for (int it=0; it<8; it++) {
                int e = tid + it*256;
                int nl = e >> 7, ml = e & 127;
                int gn2 = n0 + c*16 + nl;
                int gm2 = m0 + ml;
                if (gn2 < NPT && gm2 < NPT)
                    gb[(long long)gn2*NPT + gm2] = Ts[nl][ml];
            }
        }
    }
#undef GR_LOAD
#undef GR_STORE
#undef GR_COMPUTE
}

// ---------------- prep ------------------------------------------------------
__global__ void prep_kernel(const float* __restrict__ w1,
                            const float* __restrict__ wk, const float* __restrict__ wv,
                            const float* __restrict__ bk, const float* __restrict__ bv,
                            float* __restrict__ w1sb, float* __restrict__ wkv,
                            float* __restrict__ bkv)
{
    int i = blockIdx.x*blockDim.x + threadIdx.x;
    if (i < CCH*CCH) {
        int o = i / CCH, c = i % CCH;
        float a  = w1[o*2*CCH + c];
        float bb = w1[o*2*CCH + CCH + c];
        w1sb[i] = a + bb;
        w1sb[CCH*CCH + i] = bb;
        wkv[i] = wk[i];
        wkv[CCH*CCH + i] = wv[i];
    }
    if (i < 2*CCH) bkv[i] = (i < CCH) ? bk[i] : bv[i - CCH];
}

// ---------------- topk: lane sort-8 + warp k-way merge -----------------------
__global__ void __launch_bounds__(256) topk_kernel(const float* __restrict__ gram,
                                                   const float* __restrict__ xx,
                                                   int* __restrict__ idx)
{
    int n = blockIdx.x, b = blockIdx.y;
    const float* row = gram + ((long long)(b*NPT+n))*NPT;
    const float* xb  = xx + b*NPT;
    int tid = threadIdx.x, w = tid >> 5, l = tid & 31;

    float v[8]; int id[8];
    #pragma unroll
    for (int j=0;j<8;j++){
        int m = w*256 + j*32 + l;
        bool ok = m < NPT;
        v[j]  = ok ? (2.f*row[m] - xb[m]) : -INFINITY;
        id[j] = ok ? m : 0x7fffffff;
    }
#define CSWP(a,bb) { bool sw = (v[a]<v[bb]) || (v[a]==v[bb] && id[a]>id[bb]); \
    float tv = sw?v[bb]:v[a]; float uv2 = sw?v[a]:v[bb]; v[a]=tv; v[bb]=uv2;   \
    int ti = sw?id[bb]:id[a]; int ui = sw?id[a]:id[bb]; id[a]=ti; id[bb]=ui; }
    CSWP(0,1) CSWP(2,3) CSWP(4,5) CSWP(6,7)
    CSWP(0,2) CSWP(1,3) CSWP(4,6) CSWP(5,7)
    CSWP(1,2) CSWP(5,6)
    CSWP(0,4) CSWP(1,5) CSWP(2,6) CSWP(3,7)
    CSWP(2,4) CSWP(3,5)
    CSWP(1,2) CSWP(3,4) CSWP(5,6)
#undef CSWP

    __shared__ float wv[8][12];
    __shared__ int   wi[8][12];

    float hv = v[0]; int hi = id[0];
    #pragma unroll
    for (int t=0;t<KNNK;t++){
        float bvv = hv; int bii = hi;
        #pragma unroll
        for (int s=16; s>0; s>>=1){
            float ov = __shfl_xor_sync(0xffffffffu, bvv, s);
            int   oi = __shfl_xor_sync(0xffffffffu, bii, s);
            if (ov > bvv || (ov == bvv && oi < bii)) { bvv = ov; bii = oi; }
        }
        if (l == 0) { wv[w][t] = bvv; wi[w][t] = bii; }
        if (hi == bii) {
            #pragma unroll
            for (int j=0;j<7;j++){ v[j]=v[j+1]; id[j]=id[j+1]; }
            v[7] = -INFINITY; id[7] = 0x7fffffff;
            hv = v[0]; hi = id[0];
        }
    }
    __syncthreads();

    if (w == 0){
        int ptr = 0;
        float hv2 = (l < 8) ? wv[l][0] : -INFINITY;
        int   hi2 = (l < 8) ? wi[l][0] : 0x7fffffff;
        int* outp = idx + (b*NPT+n)*KNNK;
        #pragma unroll
        for (int t=0;t<KNNK;t++){
            float bvv = hv2; int bii = hi2;
            #pragma unroll
            for (int s=16; s>0; s>>=1){
                float ov = __shfl_xor_sync(0xffffffffu, bvv, s);
                int   oi = __shfl_xor_sync(0xffffffffu, bii, s);
                if (ov > bvv || (ov == bvv && oi < bii)) { bvv = ov; bii = oi; }
            }
            if (l == 0) outp[t] = bii;
            if (hi2 == bii){
                ptr++;
                hv2 = (ptr < KNNK && l < 8) ? wv[l][ptr] : -INFINITY;
                hi2 = (ptr < KNNK && l < 8) ? wi[l][ptr] : 0x7fffffff;
            }
        }
    }
}

// h[b,c,n*9+k] = relu( bn( u[b,c,n] - v[b,c,idx] + b1[c] ) )
__global__ void gather_h_kernel(const float* __restrict__ uv,
                                const int* __restrict__ idx,
                                const float* __restrict__ b1, const float* __restrict__ g1,
                                const float* __restrict__ be1, float* __restrict__ h)
{
    long long i = (long long)blockIdx.x*blockDim.x + threadIdx.x;
    const long long total = (long long)BSZ*CCH*NPT*KNNK;
    if (i >= total) return;
    int k = (int)(i % KNNK);
    long long r = i / KNNK;
    int n = (int)(r % NPT); r /= NPT;
    int c = (int)(r % CCH);
    int b = (int)(r / CCH);
    int j = idx[(b*NPT+n)*KNNK + k];
    const float* ub = uv + (long long)b*2*CCH*NPT + (long long)c*NPT;
    float uvv = ub[n];
    float vg  = ub[(long long)CCH*NPT + j];
    const float invs = rsqrtf(1.f + BN_EPS);
    float val = (uvv - vg + b1[c]) * (g1[c]*invs) + be1[c];
    h[((long long)(b*CCH+c))*NPT*KNNK + (long long)n*KNNK + k] = fmaxf(val, 0.f);
}

// agg[b,c,n] = max_k h2[...]; also writes top half of cat
__global__ void maxk_kernel(const float* __restrict__ h2,
                            float* __restrict__ agg, float* __restrict__ cat)
{
    int i = blockIdx.x*blockDim.x + threadIdx.x;
    if (i >= BSZ*CCH*NPT) return;
    int n = i % NPT;
    int c = (i / NPT) % CCH;
    int b = i / (NPT*CCH);
    const float* p = h2 + ((long long)(b*CCH+c))*NPT*KNNK + (long long)n*KNNK;
    float m = p[0];
    #pragma unroll
    for (int k = 1; k < KNNK; k++) m = fmaxf(m, p[k]);
    agg[i] = m;
    cat[(long long)b*2*CCH*NPT + (long long)c*NPT + n] = m;
}

// ---------------- flash attention with tf32 mma.sync --------------------------
// Per CTA: 256 thr = 8 warps, 128 q-rows (16/warp), 64-key tiles.
// QK^T uses split-tf32 (3 mma: qh*kh + qh*kl + ql*kh) for fp32-like scores.
// PV uses plain tf32 (P in [0,1], error ~5e-4 relative).

__device__ __forceinline__ uint32_t f2tf32(float x){
    uint32_t r;
    asm("cvt.rna.tf32.f32 %0, %1;" : "=r"(r) : "f"(x));
    return r;
}
__device__ __forceinline__ void mma_tf32(float* d, const uint32_t* a, uint32_t b0, uint32_t b1){
    asm volatile(
        "mma.sync.aligned.m16n8k8.row.col.f32.tf32.tf32.f32 "
        "{%0,%1,%2,%3},{%4,%5,%6,%7},{%8,%9},{%0,%1,%2,%3};"
        : "+f"(d[0]), "+f"(d[1]), "+f"(d[2]), "+f"(d[3])
        : "r"(a[0]), "r"(a[1]), "r"(a[2]), "r"(a[3]), "r"(b0), "r"(b1));
}

#define FQT 128
#define FKT 64
#define QS_LD 36
#define KD_LD 72
#define VT_LD2 40
// smem float offsets
#define OF_QH 0
#define OF_QL (FQT*QS_LD)                  // 4608
#define OF_KH (OF_QL + FQT*QS_LD)          // 9216
#define OF_KL (OF_KH + HD*KD_LD)           // 11520
#define OF_VT (OF_KL + HD*KD_LD)           // 13824
#define FLASH_SM_FLOATS (OF_VT + FKT*VT_LD2)   // 16384

__global__ void __launch_bounds__(256,2) flash_mma(
    const float* __restrict__ q,   // [B][C][N]
    const float* __restrict__ kv,  // [B][2C][N]
    float* __restrict__ add)       // [B][C][N]
{
    extern __shared__ float sm[];
    float* Qsh = sm + OF_QH;
    float* Qsl = sm + OF_QL;
    float* Kdh = sm + OF_KH;
    float* Kdl = sm + OF_KL;
    float* Vt  = sm + OF_VT;

    int n0 = blockIdx.x * FQT;
    int h  = blockIdx.y;
    int b  = blockIdx.z;
    const float* qp = q  + ((long long)b*CCH   + h*HD)*NPT;
    const float* kp = kv + ((long long)b*2*CCH + h*HD)*NPT;
    const float* vp = kv + ((long long)b*2*CCH + CCH + h*HD)*NPT;
    float* oh = add + ((long long)b*CCH + h*HD)*NPT;

    int tid = threadIdx.x;
    const float scale = 0.17677669529663689f;  // 1/sqrt(32), folded into Q

    // Q load: scale, split hi/lo, store [row][d]
    #pragma unroll
    for (int e = tid; e < FQT*HD; e += 256) {
        int d = e >> 7, r = e & 127;
        int n = n0 + r;
        float qv = (n < NPT) ? qp[d*NPT + n]*scale : 0.f;
        float hf = __uint_as_float(f2tf32(qv));
        Qsh[r*QS_LD + d] = hf;
        Qsl[r*QS_LD + d] = __uint_as_float(f2tf32(qv - hf));
    }

    int w = tid >> 5, lane = tid & 31;
    int g = lane >> 2, t = lane & 3;
    int row = w*16 + g;

    float O[4][4];
    #pragma unroll
    for (int i=0;i<4;i++)
        #pragma unroll
        for (int j=0;j<4;j++) O[i][j] = 0.f;
    float m0r = -INFINITY, m1r = -INFINITY, l0r = 0.f, l1r = 0.f;

    const int NT = (NPT + FKT - 1)/FKT;   // 32

    for (int ti = 0; ti < NT; ti++) {
        int m0 = ti*FKT;
        __syncthreads();
        // load K (split) + V (tf32-rounded)
        #pragma unroll
        for (int e = tid; e < HD*FKT; e += 256) {
            int d = e >> 6, c = e & 63;
            int m = m0 + c;
            float kvv = (m < NPT) ? kp[d*NPT + m] : 0.f;
            float hf = __uint_as_float(f2tf32(kvv));
            Kdh[d*KD_LD + c] = hf;
            Kdl[d*KD_LD + c] = __uint_as_float(f2tf32(kvv - hf));
            float vv = (m < NPT) ? vp[d*NPT + m] : 0.f;
            Vt[c*VT_LD2 + d] = __uint_as_float(f2tf32(vv));
        }
        __syncthreads();

        // Q fragments (hi + lo), 4 ksteps
        uint32_t qa[4][4], ql[4][4];
        #pragma unroll
        for (int ks=0; ks<4; ks++){
            int c0 = ks*8;
            qa[ks][0] = __float_as_uint(Qsh[(row  )*QS_LD + c0 + t]);
            qa[ks][1] = __float_as_uint(Qsh[(row+8)*QS_LD + c0 + t]);
            qa[ks][2] = __float_as_uint(Qsh[(row  )*QS_LD + c0 + t + 4]);
            qa[ks][3] = __float_as_uint(Qsh[(row+8)*QS_LD + c0 + t + 4]);
            ql[ks][0] = __float_as_uint(Qsl[(row  )*QS_LD + c0 + t]);
            ql[ks][1] = __float_as_uint(Qsl[(row+8)*QS_LD + c0 + t]);
            ql[ks][2] = __float_as_uint(Qsl[(row  )*QS_LD + c0 + t + 4]);
            ql[ks][3] = __float_as_uint(Qsl[(row+8)*QS_LD + c0 + t + 4]);
        }

        // S = Q K^T  (split-tf32, 3 mma per k-step)
        float S[8][4];
        #pragma unroll
        for (int nt=0; nt<8; nt++){
            S[nt][0]=0.f; S[nt][1]=0.f; S[nt][2]=0.f; S[nt][3]=0.f;
            #pragma unroll
            for (int ks=0; ks<4; ks++){
                int kr = ks*8 + t;
                int cidx = nt*8 + g;
                uint32_t bh0 = __float_as_uint(Kdh[(kr  )*KD_LD + cidx]);
                uint32_t bh1 = __float_as_uint(Kdh[(kr+4)*KD_LD + cidx]);
                uint32_t bl0 = __float_as_uint(Kdl[(kr  )*KD_LD + cidx]);
                uint32_t bl1 = __float_as_uint(Kdl[(kr+4)*KD_LD + cidx]);
                mma_tf32(S[nt], qa[ks], bh0, bh1);
                mma_tf32(S[nt], qa[ks], bl0, bl1);
                mma_tf32(S[nt], ql[ks], bh0, bh1);
            }
        }

        // online softmax (rows: row, row+8; cols per thread: nt*8+2t, +1)
        int mval = NPT - m0;
        float lm0 = -INFINITY, lm1 = -INFINITY;
        #pragma unroll
        for (int nt=0; nt<8; nt++){
            int c0 = nt*8 + 2*t, c1 = c0 + 1;
            if (c0 < mval){ lm0 = fmaxf(lm0, S[nt][0]); lm1 = fmaxf(lm1, S[nt][2]); }
            if (c1 < mval){ lm0 = fmaxf(lm0, S[nt][1]); lm1 = fmaxf(lm1, S[nt][3]); }
        }
        lm0 = fmaxf(lm0, __shfl_xor_sync(0xffffffffu, lm0, 1));
        lm0 = fmaxf(lm0, __shfl_xor_sync(0xffffffffu, lm0, 2));
        lm1 = fmaxf(lm1, __shfl_xor_sync(0xffffffffu, lm1, 1));
        lm1 = fmaxf(lm1, __shfl_xor_sync(0xffffffffu, lm1, 2));

        float mn0 = fmaxf(m0r, lm0), mn1 = fmaxf(m1r, lm1);
        float al0 = __expf(m0r - mn0), al1 = __expf(m1r - mn1);
        m0r = mn0; m1r = mn1;

        float ls0 = 0.f, ls1 = 0.f;
        #pragma unroll
        for (int nt=0; nt<8; nt++){
            int c0 = nt*8 + 2*t, c1 = c0 + 1;
            float e0 = (c0 < mval) ? __expf(S[nt][0] - mn0) : 0.f;
            float e1 = (c1 < mval) ? __expf(S[nt][1] - mn0) : 0.f;
            float e2 = (c0 < mval) ? __expf(S[nt][2] - mn1) : 0.f;
            float e3 = (c1 < mval) ? __expf(S[nt][3] - mn1) : 0.f;
            S[nt][0]=e0; S[nt][1]=e1; S[nt][2]=e2; S[nt][3]=e3;
            ls0 += e0 + e1; ls1 += e2 + e3;
        }
        ls0 += __shfl_xor_sync(0xffffffffu, ls0, 1);
        ls0 += __shfl_xor_sync(0xffffffffu, ls0, 2);
        ls1 += __shfl_xor_sync(0xffffffffu, ls1, 1);
        ls1 += __shfl_xor_sync(0xffffffffu, ls1, 2);
        l0r = l0r*al0 + ls0;
        l1r = l1r*al1 + ls1;
        #pragma unroll
        for (int nd=0; nd<4; nd++){
            O[nd][0] *= al0; O[nd][1] *= al0;
            O[nd][2] *= al1; O[nd][3] *= al1;
        }

        // PV: P fragments via intra-group shuffles (C-layout -> A-layout)
        int s1 = g*4 + (t>>1), s2 = s1 + 2;
        bool odd = (t & 1);
        #pragma unroll
        for (int kt2=0; kt2<8; kt2++){
            float x0 = __shfl_sync(0xffffffffu, S[kt2][0], s1);
            float x1 = __shfl_sync(0xffffffffu, S[kt2][1], s1);
            float x2 = __shfl_sync(0xffffffffu, S[kt2][2], s1);
            float x3 = __shfl_sync(0xffffffffu, S[kt2][3], s1);
            float y0 = __shfl_sync(0xffffffffu, S[kt2][0], s2);
            float y1 = __shfl_sync(0xffffffffu, S[kt2][1], s2);
            float y2 = __shfl_sync(0xffffffffu, S[kt2][2], s2);
            float y3 = __shfl_sync(0xffffffffu, S[kt2][3], s2);
            uint32_t pa[4];
            pa[0] = f2tf32(odd ? x1 : x0);
            pa[1] = f2tf32(odd ? x3 : x2);
            pa[2] = f2tf32(odd ? y1 : y0);
            pa[3] = f2tf32(odd ? y3 : y2);
            #pragma unroll
            for (int nd=0; nd<4; nd++){
                uint32_t b0 = __float_as_uint(Vt[(kt2*8 + t    )*VT_LD2 + nd*8 + g]);
                uint32_t b1 = __float_as_uint(Vt[(kt2*8 + t + 4)*VT_LD2 + nd*8 + g]);
                mma_tf32(O[nd], pa, b0, b1);
            }
        }
    }

    float inv0 = 1.f / l0r, inv1 = 1.f / l1r;
    int q0 = n0 + row, q1 = q0 + 8;
    #pragma unroll
    for (int nd=0; nd<4; nd++){
        int d0 = nd*8 + 2*t, d1 = d0 + 1;
        if (q0 < NPT){
            oh[(long long)d0*NPT + q0] = O[nd][0]*inv0;
            oh[(long long)d1*NPT + q0] = O[nd][1]*inv0;
        }
        if (q1 < NPT){
            oh[(long long)d0*NPT + q1] = O[nd][2]*inv1;
            oh[(long long)d1*NPT + q1] = O[nd][3]*inv1;
        }
    }
}

// ---------------- launch ------------------------------------------------------
static inline dim3 ggrid(int M, int Nc, int batches) {
    return dim3((Nc + TN - 1)/TN, (M + TM - 1)/TM, batches);
}
static inline dim3 ggrid64(int M, int Nc, int batches) {
    return dim3((Nc + TN2 - 1)/TN2, (M + TM - 1)/TM, batches);
}

extern "C" void kernel_launch(void* const* d_in, const int* in_sizes, int n_in,
                              void* d_out, int out_size)
{
    const float* x    = (const float*)d_in[0];
    const float* y    = (const float*)d_in[1];
    const float* dgw1 = (const float*)d_in[2];
    const float* dgb1 = (const float*)d_in[3];
    const float* dgg1 = (const float*)d_in[4];
    const float* dgbe1= (const float*)d_in[5];
    const float* dgw2 = (const float*)d_in[6];
    const float* dgb2 = (const float*)d_in[7];
    const float* dgg2 = (const float*)d_in[8];
    const float* dgbe2= (const float*)d_in[9];
    const float* wq   = (const float*)d_in[10];
    const float* bq   = (const float*)d_in[11];
    const float* wk   = (const float*)d_in[12];
    const float* bk   = (const float*)d_in[13];
    const float* wv   = (const float*)d_in[14];
    const float* bv   = (const float*)d_in[15];
    const float* wmh  = (const float*)d_in[16];
    const float* bmh  = (const float*)d_in[17];
    const float* wc1  = (const float*)d_in[18];
    const float* bc1  = (const float*)d_in[19];
    const float* cg   = (const float*)d_in[20];
    const float* cbe  = (const float*)d_in[21];
    const float* wc2  = (const float*)d_in[22];
    const float* bc2  = (const float*)d_in[23];
    float* out = (float*)d_out;

    float *w1sb,*wkv,*bkv,*gram,*xx,*uv,*h,*h2,*agg,*q,*kvb,*add,*cat,*hc;
    int* idx;
    cudaGetSymbolAddress((void**)&w1sb, g_w1sb);
    cudaGetSymbolAddress((void**)&wkv,  g_wkv);
    cudaGetSymbolAddress((void**)&bkv,  g_bkv);
    cudaGetSymbolAddress((void**)&gram, g_gram);
    cudaGetSymbolAddress((void**)&xx,   g_xx);
    cudaGetSymbolAddress((void**)&idx,  g_idx);
    cudaGetSymbolAddress((void**)&uv,   g_uv);
    cudaGetSymbolAddress((void**)&h,    g_h);
    cudaGetSymbolAddress((void**)&h2,   g_h2);
    cudaGetSymbolAddress((void**)&agg,  g_agg);
    cudaGetSymbolAddress((void**)&q,    g_q);
    cudaGetSymbolAddress((void**)&kvb,  g_kv);
    cudaGetSymbolAddress((void**)&add,  g_add);
    cudaGetSymbolAddress((void**)&cat,  g_cat);
    cudaGetSymbolAddress((void**)&hc,   g_hc);

    const long long CN  = (long long)CCH*NPT;
    const long long CNK = (long long)CCH*NPT*KNNK;
    const int FLASH_SMEM = FLASH_SM_FLOATS * 4;
    const int NTILES = (NPT + TM - 1)/TM;
    const int NTRI = NTILES*(NTILES+1)/2;

    cudaFuncSetAttribute(flash_mma, cudaFuncAttributeMaxDynamicSharedMemorySize, FLASH_SMEM);

    // 1) prep
    prep_kernel<<<(CCH*CCH+255)/256, 256>>>(dgw1, wk, wv, bk, bv, w1sb, wkv, bkv);

    // 2) gram[b] = x^T x (triangular + mirror); diag -> xx
    gram_kernel<<<dim3(NTRI, 1, BSZ), 256>>>(x, gram, xx);

    // 3) top-9
    topk_kernel<<<dim3(NPT, BSZ), 256>>>(gram, xx, idx);

    // 4) uv = [w1s; w1b] @ x
    gemm_k64b<<<ggrid64(2*CCH,NPT,BSZ), 256>>>(
        w1sb, x, uv, 2*CCH, NPT, CCH, CCH, NPT, NPT,
        0, CN, 2*CN, nullptr, nullptr, nullptr, 0, nullptr, 0, 0);

    // 5) edge features -> h
    {
        long long total = (long long)BSZ*CNK;
        gather_h_kernel<<<(unsigned)((total+255)/256), 256>>>(uv, idx, dgb1, dgg1, dgbe1, h);
    }

    // 6) conv2, fused bn+relu
    gemm_k<false,false><<<ggrid(CCH, NPT*KNNK, BSZ), 256>>>(
        dgw2, h, h2, CCH, NPT*KNNK, CCH, CCH, NPT*KNNK, NPT*KNNK,
        0, CNK, CNK, 1.f, dgb2, dgg2, dgbe2, 1, nullptr, 0, 0);

    // 7) max over k
    maxk_kernel<<<(BSZ*CCH*NPT+255)/256, 256>>>(h2, agg, cat);

    // 8) q, kv projections
    gemm_k64b<<<ggrid64(CCH,NPT,BSZ), 256>>>(
        wq, agg, q, CCH, NPT, CCH, CCH, NPT, NPT,
        0, CN, CN, bq, nullptr, nullptr, 0, nullptr, 0, 0);
    gemm_k64b<<<ggrid64(2*CCH,NPT,BSZ), 256>>>(
        wkv, y, kvb, 2*CCH, NPT, CCH, CCH, NPT, NPT,
        0, CN, 2*CN, bkv, nullptr, nullptr, 0, nullptr, 0, 0);

    // 9) fused attention (tf32 mma) -> add
    {
        dim3 grid((NPT + FQT - 1)/FQT, NHEAD, BSZ);
        flash_mma<<<grid, 256, FLASH_SMEM>>>(q, kvb, add);
    }

    // 10) mh conv -> bottom half of cat
    gemm_k64b<<<ggrid64(CCH,NPT,BSZ), 256>>>(
        wmh, add, cat + CN, CCH, NPT, CCH, CCH, NPT, NPT,
        0, CN, 2*CN, bmh, nullptr, nullptr, 0, nullptr, 0, 0);

    // 11) hc = relu(bn(wc1 @ cat + bc1))
    gemm_k64b<<<ggrid64(2*CCH,NPT,BSZ), 256>>>(
        wc1, cat, hc, 2*CCH, NPT, 2*CCH, 2*CCH, NPT, NPT,
        0, 2*CN, 2*CN, bc1, cg, cbe, 1, nullptr, 0, 0);

    // 12) out = agg + wc2 @ hc + bc2
    gemm_k64b<<<ggrid64(CCH,NPT,BSZ), 256>>>(
        wc2, hc, out, CCH, NPT, 2*CCH, 2*CCH, NPT, NPT,
        0, 2*CN, CN, bc2, nullptr, nullptr, 0, agg, CN, NPT);
}

// round 8
// speedup vs baseline: 2.5559x; 1.1056x over previous
#include <cuda_runtime.h>
#include <math.h>
#include <stdint.h>

#define BSZ   4
#define CCH   128
#define NPT   2000
#define KNNK  9
#define NHEAD 4
#define HD    32
#define BN_EPS 1e-5f

// ---------------- scratch ------------------------------------------------
__device__ float g_w1sb[2*CCH*CCH];
__device__ float g_wkv [2*CCH*CCH];
__device__ float g_bkv [2*CCH];
__device__ float g_gram[(size_t)BSZ*NPT*NPT];
__device__ float g_xx[BSZ*NPT];
__device__ int   g_idx[BSZ*NPT*KNNK];
__device__ float g_uv[BSZ*2*CCH*NPT];
__device__ float g_h [(size_t)BSZ*CCH*NPT*KNNK];
__device__ float g_h2[(size_t)BSZ*CCH*NPT*KNNK];
__device__ float g_agg[BSZ*CCH*NPT];
__device__ float g_q  [BSZ*CCH*NPT];
__device__ float g_kv [BSZ*2*CCH*NPT];
__device__ float g_add[BSZ*CCH*NPT];
__device__ float g_cat[BSZ*2*CCH*NPT];
__device__ float g_hc [BSZ*2*CCH*NPT];

// ---------------- tf32 helpers -------------------------------------------
__device__ __forceinline__ uint32_t f2tf32(float x){
    uint32_t r;
    asm("cvt.rna.tf32.f32 %0, %1;" : "=r"(r) : "f"(x));
    return r;
}
__device__ __forceinline__ void mma_tf32(float* d, const uint32_t* a, uint32_t b0, uint32_t b1){
    asm volatile(
        "mma.sync.aligned.m16n8k8.row.col.f32.tf32.tf32.f32 "
        "{%0,%1,%2,%3},{%4,%5,%6,%7},{%8,%9},{%0,%1,%2,%3};"
        : "+f"(d[0]), "+f"(d[1]), "+f"(d[2]), "+f"(d[3])
        : "r"(a[0]), "r"(a[1]), "r"(a[2]), "r"(a[3]), "r"(b0), "r"(b1));
}

// ---------------- split-tf32 MMA GEMM --------------------------------------
// C[m,n] = sum_k A[m,k]*B[k,n] + epilogue. A row-major [M][K], B row-major [K][N].
// CTA tile 128x64, warp tile 16x64, K chunks of 16. 3-mma split-tf32 (~fp32).
#define GM_TM 128
#define GM_TN 64
#define GA_LD 20
#define GB_LD 72

__global__ void __launch_bounds__(256) gemm_mma(
    const float* __restrict__ A, const float* __restrict__ B, float* __restrict__ Cm,
    int M, int Nc, int Kc, int lda, int ldb, int ldc,
    long long sA, long long sB, long long sC,
    const float* __restrict__ bias,
    const float* __restrict__ gamma, const float* __restrict__ beta,
    int relu,
    const float* __restrict__ resid, long long sR, int ldr)
{
    int bz = blockIdx.z;
    A  += (long long)bz * sA;
    B  += (long long)bz * sB;
    Cm += (long long)bz * sC;
    if (resid) resid += (long long)bz * sR;

    __shared__ float AH[GM_TM*GA_LD], AL[GM_TM*GA_LD];
    __shared__ float BH[16*GB_LD],    BL[16*GB_LD];

    int m0 = blockIdx.y * GM_TM;
    int n0 = blockIdx.x * GM_TN;
    int tid = threadIdx.x;
    int w = tid >> 5, lane = tid & 31;
    int g = lane >> 2, t = lane & 3;
    int row = w*16;

    float acc[8][4];
    #pragma unroll
    for (int i=0;i<8;i++)
        #pragma unroll
        for (int j=0;j<4;j++) acc[i][j] = 0.f;

    for (int kc = 0; kc < Kc; kc += 16) {
        // A chunk: 128 rows x 16 k
        #pragma unroll
        for (int it=0; it<8; it++){
            int e = tid + it*256;
            int kk = e & 15, r = e >> 4;
            int gm = m0 + r;
            float av = (gm < M) ? A[(long long)gm*lda + kc + kk] : 0.f;
            float ah = __uint_as_float(f2tf32(av));
            AH[r*GA_LD + kk] = ah;
            AL[r*GA_LD + kk] = __uint_as_float(f2tf32(av - ah));
        }
        // B chunk: 16 k x 64 n
        #pragma unroll
        for (int it=0; it<4; it++){
            int e = tid + it*256;
            int n_ = e & 63, k_ = e >> 6;
            int gn = n0 + n_;
            float bv = (gn < Nc) ? B[(long long)(kc + k_)*ldb + gn] : 0.f;
            float bh = __uint_as_float(f2tf32(bv));
            BH[k_*GB_LD + n_] = bh;
            BL[k_*GB_LD + n_] = __uint_as_float(f2tf32(bv - bh));
        }
        __syncthreads();

        #pragma unroll
        for (int ks=0; ks<2; ks++){
            int c0 = ks*8;
            uint32_t ah[4], al[4];
            ah[0] = __float_as_uint(AH[(row+g  )*GA_LD + c0 + t]);
            ah[1] = __float_as_uint(AH[(row+8+g)*GA_LD + c0 + t]);
            ah[2] = __float_as_uint(AH[(row+g  )*GA_LD + c0 + t + 4]);
            ah[3] = __float_as_uint(AH[(row+8+g)*GA_LD + c0 + t + 4]);
            al[0] = __float_as_uint(AL[(row+g  )*GA_LD + c0 + t]);
            al[1] = __float_as_uint(AL[(row+8+g)*GA_LD + c0 + t]);
            al[2] = __float_as_uint(AL[(row+g  )*GA_LD + c0 + t + 4]);
            al[3] = __float_as_uint(AL[(row+8+g)*GA_LD + c0 + t + 4]);
            int kr = ks*8 + t;
            #pragma unroll
            for (int nt=0; nt<8; nt++){
                int cidx = nt*8 + g;
                uint32_t bh0 = __float_as_uint(BH[(kr  )*GB_LD + cidx]);
                uint32_t bh1 = __float_as_uint(BH[(kr+4)*GB_LD + cidx]);
                uint32_t bl0 = __float_as_uint(BL[(kr  )*GB_LD + cidx]);
                uint32_t bl1 = __float_as_uint(BL[(kr+4)*GB_LD + cidx]);
                mma_tf32(acc[nt], ah, bh0, bh1);
                mma_tf32(acc[nt], ah, bl0, bl1);
                mma_tf32(acc[nt], al, bh0, bh1);
            }
        }
        __syncthreads();
    }

    const float invs = rsqrtf(1.0f + BN_EPS);
    #pragma unroll
    for (int half=0; half<2; half++){
        int gm = m0 + row + half*8 + g;
        if (gm >= M) continue;
        float bi = bias  ? bias[gm]       : 0.f;
        float ga = gamma ? gamma[gm]*invs : 1.f;
        float be = beta  ? beta[gm]       : 0.f;
        #pragma unroll
        for (int nt=0; nt<8; nt++){
            int c0 = n0 + nt*8 + 2*t;
            #pragma unroll
            for (int jj=0; jj<2; jj++){
                int gn = c0 + jj;
                if (gn >= Nc) continue;
                float r = acc[nt][half*2 + jj] + bi;
                if (gamma) r = r*ga + be;
                if (relu)  r = fmaxf(r, 0.f);
                if (resid) r += resid[(long long)gm*ldr + gn];
                Cm[(long long)gm*ldc + gn] = r;
            }
        }
    }
}

// ---------------- symmetric Gram: upper-triangle tiles + mirrored store ----
#define TM 128
#define TN 128
#define TK 8

__global__ void __launch_bounds__(256) gram_kernel(
    const float* __restrict__ x,
    float* __restrict__ gram,
    float* __restrict__ xx)
{
    __shared__ float As[TK][TM];
    __shared__ float Bs[TK][TN];
    __shared__ float Ts[16][132];

    int b = blockIdx.z;
    const float* xb = x + (long long)b*CCH*NPT;
    float* gb = gram + (long long)b*NPT*NPT;

    int t = blockIdx.x;
    int bj = 0;
    while ((bj+1)*(bj+2)/2 <= t) bj++;
    int bi = t - bj*(bj+1)/2;

    int m0 = bi * TM;
    int n0 = bj * TN;
    int tid = threadIdx.x;
    int tx = tid % 16, ty = tid / 16;

    float acc[8][8];
    #pragma unroll
    for (int i=0;i<8;i++)
        #pragma unroll
        for (int j=0;j<8;j++) acc[i][j] = 0.f;

    float ra[4], rb[4];

#define GR_LOAD(KT0) {                                                     \
    _Pragma("unroll")                                                      \
    for (int it=0; it<4; it++){                                            \
        int e = tid + it*256;                                              \
        int m_ = e % TM, k_ = e / TM;                                      \
        int gm = m0+m_;                                                    \
        ra[it] = (gm<NPT) ? xb[(long long)((KT0)+k_)*NPT+gm] : 0.f;        \
    }                                                                      \
    _Pragma("unroll")                                                      \
    for (int it=0; it<4; it++){                                            \
        int e = tid + it*256;                                              \
        int n_ = e % TN, k_ = e / TN;                                      \
        int gn = n0+n_;                                                    \
        rb[it] = (gn<NPT) ? xb[(long long)((KT0)+k_)*NPT+gn] : 0.f;        \
    } }

#define GR_STORE() {                                                       \
    _Pragma("unroll")                                                      \
    for (int it=0; it<4; it++){                                            \
        int e = tid + it*256;                                              \
        int m_ = e % TM, k_ = e / TM;                                      \
        As[k_][m_] = ra[it];                                               \
    }                                                                      \
    _Pragma("unroll")                                                      \
    for (int it=0; it<4; it++){                                            \
        int e = tid + it*256;                                              \
        int n_ = e % TN, k_ = e / TN;                                      \
        Bs[k_][n_] = rb[it];                                               \
    } }

#define GR_COMPUTE() {                                                     \
    _Pragma("unroll")                                                      \
    for (int kk=0; kk<TK; kk++){                                           \
        float4 a0 = *(const float4*)&As[kk][ty*8];                         \
        float4 a1 = *(const float4*)&As[kk][ty*8+4];                       \
        float4 b0 = *(const float4*)&Bs[kk][tx*8];                         \
        float4 b1 = *(const float4*)&Bs[kk][tx*8+4];                       \
        float av[8] = {a0.x,a0.y,a0.z,a0.w,a1.x,a1.y,a1.z,a1.w};           \
        float bv8[8] = {b0.x,b0.y,b0.z,b0.w,b1.x,b1.y,b1.z,b1.w};          \
        _Pragma("unroll")                                                  \
        for (int i=0;i<8;i++)                                              \
            _Pragma("unroll")                                              \
            for (int j=0;j<8;j++) acc[i][j] += av[i]*bv8[j];               \
    } }

    GR_LOAD(0);
    GR_STORE();
    for (int kt = TK; kt < CCH; kt += TK) {
        __syncthreads();
        GR_LOAD(kt);
        GR_COMPUTE();
        __syncthreads();
        GR_STORE();
    }
    __syncthreads();
    GR_COMPUTE();

    #pragma unroll
    for (int i=0;i<8;i++) {
        int gm = m0 + ty*8 + i;
        if (gm >= NPT) continue;
        #pragma unroll
        for (int j=0;j<8;j++) {
            int gn = n0 + tx*8 + j;
            if (gn >= NPT) continue;
            gb[(long long)gm*NPT + gn] = acc[i][j];
            if (bi == bj && gm == gn) xx[b*NPT + gm] = acc[i][j];
        }
    }

    if (bi != bj) {
        #pragma unroll
        for (int c = 0; c < 8; c++) {
            __syncthreads();
            if ((tx >> 1) == c) {
                int jb = (tx & 1) * 8;
                #pragma unroll
                for (int i=0;i<8;i++)
                    #pragma unroll
                    for (int j=0;j<8;j++)
                        Ts[jb + j][ty*8 + i] = acc[i][j];
            }
            __syncthreads();
            #pragma unroll
            for (int it=0; it<8; it++) {
                int e = tid + it*256;
                int nl = e >> 7, ml = e & 127;
                int gn2 = n0 + c*16 + nl;
                int gm2 = m0 + ml;
                if (gn2 < NPT && gm2 < NPT)
                    gb[(long long)gn2*NPT + gm2] = Ts[nl][ml];
            }
        }
    }
#undef GR_LOAD
#undef GR_STORE
#undef GR_COMPUTE
}

// ---------------- prep ------------------------------------------------------
__global__ void prep_kernel(const float* __restrict__ w1,
                            const float* __restrict__ wk, const float* __restrict__ wv,
                            const float* __restrict__ bk, const float* __restrict__ bv,
                            float* __restrict__ w1sb, float* __restrict__ wkv,
                            float* __restrict__ bkv)
{
    int i = blockIdx.x*blockDim.x + threadIdx.x;
    if (i < CCH*CCH) {
        int o = i / CCH, c = i % CCH;
        float a  = w1[o*2*CCH + c];
        float bb = w1[o*2*CCH + CCH + c];
        w1sb[i] = a + bb;
        w1sb[CCH*CCH + i] = bb;
        wkv[i] = wk[i];
        wkv[CCH*CCH + i] = wv[i];
    }
    if (i < 2*CCH) bkv[i] = (i < CCH) ? bk[i] : bv[i - CCH];
}

// ---------------- topk: lane sort-8 + warp k-way merge -----------------------
__global__ void __launch_bounds__(256) topk_kernel(const float* __restrict__ gram,
                                                   const float* __restrict__ xx,
                                                   int* __restrict__ idx)
{
    int n = blockIdx.x, b = blockIdx.y;
    const float* row = gram + ((long long)(b*NPT+n))*NPT;
    const float* xb  = xx + b*NPT;
    int tid = threadIdx.x, w = tid >> 5, l = tid & 31;

    float v[8]; int id[8];
    #pragma unroll
    for (int j=0;j<8;j++){
        int m = w*256 + j*32 + l;
        bool ok = m < NPT;
        v[j]  = ok ? (2.f*row[m] - xb[m]) : -INFINITY;
        id[j] = ok ? m : 0x7fffffff;
    }
#define CSWP(a,bb) { bool sw = (v[a]<v[bb]) || (v[a]==v[bb] && id[a]>id[bb]); \
    float tv = sw?v[bb]:v[a]; float uv2 = sw?v[a]:v[bb]; v[a]=tv; v[bb]=uv2;   \
    int ti = sw?id[bb]:id[a]; int ui = sw?id[a]:id[bb]; id[a]=ti; id[bb]=ui; }
    CSWP(0,1) CSWP(2,3) CSWP(4,5) CSWP(6,7)
    CSWP(0,2) CSWP(1,3) CSWP(4,6) CSWP(5,7)
    CSWP(1,2) CSWP(5,6)
    CSWP(0,4) CSWP(1,5) CSWP(2,6) CSWP(3,7)
    CSWP(2,4) CSWP(3,5)
    CSWP(1,2) CSWP(3,4) CSWP(5,6)
#undef CSWP

    __shared__ float wv[8][12];
    __shared__ int   wi[8][12];

    float hv = v[0]; int hi = id[0];
    #pragma unroll
    for (int t=0;t<KNNK;t++){
        float bvv = hv; int bii = hi;
        #pragma unroll
        for (int s=16; s>0; s>>=1){
            float ov = __shfl_xor_sync(0xffffffffu, bvv, s);
            int   oi = __shfl_xor_sync(0xffffffffu, bii, s);
            if (ov > bvv || (ov == bvv && oi < bii)) { bvv = ov; bii = oi; }
        }
        if (l == 0) { wv[w][t] = bvv; wi[w][t] = bii; }
        if (hi == bii) {
            #pragma unroll
            for (int j=0;j<7;j++){ v[j]=v[j+1]; id[j]=id[j+1]; }
            v[7] = -INFINITY; id[7] = 0x7fffffff;
            hv = v[0]; hi = id[0];
        }
    }
    __syncthreads();

    if (w == 0){
        int ptr = 0;
        float hv2 = (l < 8) ? wv[l][0] : -INFINITY;
        int   hi2 = (l < 8) ? wi[l][0] : 0x7fffffff;
        int* outp = idx + (b*NPT+n)*KNNK;
        #pragma unroll
        for (int t=0;t<KNNK;t++){
            float bvv = hv2; int bii = hi2;
            #pragma unroll
            for (int s=16; s>0; s>>=1){
                float ov = __shfl_xor_sync(0xffffffffu, bvv, s);
                int   oi = __shfl_xor_sync(0xffffffffu, bii, s);
                if (ov > bvv || (ov == bvv && oi < bii)) { bvv = ov; bii = oi; }
            }
            if (l == 0) outp[t] = bii;
            if (hi2 == bii){
                ptr++;
                hv2 = (ptr < KNNK && l < 8) ? wv[l][ptr] : -INFINITY;
                hi2 = (ptr < KNNK && l < 8) ? wi[l][ptr] : 0x7fffffff;
            }
        }
    }
}

// h[b,c,n*9+k] = relu( bn( u[b,c,n] - v[b,c,idx] + b1[c] ) )
__global__ void gather_h_kernel(const float* __restrict__ uv,
                                const int* __restrict__ idx,
                                const float* __restrict__ b1, const float* __restrict__ g1,
                                const float* __restrict__ be1, float* __restrict__ h)
{
    long long i = (long long)blockIdx.x*blockDim.x + threadIdx.x;
    const long long total = (long long)BSZ*CCH*NPT*KNNK;
    if (i >= total) return;
    int k = (int)(i % KNNK);
    long long r = i / KNNK;
    int n = (int)(r % NPT); r /= NPT;
    int c = (int)(r % CCH);
    int b = (int)(r / CCH);
    int j = idx[(b*NPT+n)*KNNK + k];
    const float* ub = uv + (long long)b*2*CCH*NPT + (long long)c*NPT;
    float uvv = ub[n];
    float vg  = ub[(long long)CCH*NPT + j];
    const float invs = rsqrtf(1.f + BN_EPS);
    float val = (uvv - vg + b1[c]) * (g1[c]*invs) + be1[c];
    h[((long long)(b*CCH+c))*NPT*KNNK + (long long)n*KNNK + k] = fmaxf(val, 0.f);
}

// agg[b,c,n] = max_k h2[...]; also writes top half of cat
__global__ void maxk_kernel(const float* __restrict__ h2,
                            float* __restrict__ agg, float* __restrict__ cat)
{
    int i = blockIdx.x*blockDim.x + threadIdx.x;
    if (i >= BSZ*CCH*NPT) return;
    int n = i % NPT;
    int c = (i / NPT) % CCH;
    int b = i / (NPT*CCH);
    const float* p = h2 + ((long long)(b*CCH+c))*NPT*KNNK + (long long)n*KNNK;
    float m = p[0];
    #pragma unroll
    for (int k = 1; k < KNNK; k++) m = fmaxf(m, p[k]);
    agg[i] = m;
    cat[(long long)b*2*CCH*NPT + (long long)c*NPT + n] = m;
}

// ---------------- flash attention with tf32 mma.sync (R7 proven) -------------
#define FQT 128
#define FKT 64
#define QS_LD 36
#define KD_LD 72
#define VT_LD2 40
#define OF_QH 0
#define OF_QL (FQT*QS_LD)
#define OF_KH (OF_QL + FQT*QS_LD)
#define OF_KL (OF_KH + HD*KD_LD)
#define OF_VT (OF_KL + HD*KD_LD)
#define FLASH_SM_FLOATS (OF_VT + FKT*VT_LD2)

__global__ void __launch_bounds__(256,2) flash_mma(
    const float* __restrict__ q,
    const float* __restrict__ kv,
    float* __restrict__ add)
{
    extern __shared__ float sm[];
    float* Qsh = sm + OF_QH;
    float* Qsl = sm + OF_QL;
    float* Kdh = sm + OF_KH;
    float* Kdl = sm + OF_KL;
    float* Vt  = sm + OF_VT;

    int n0 = blockIdx.x * FQT;
    int h  = blockIdx.y;
    int b  = blockIdx.z;
    const float* qp = q  + ((long long)b*CCH   + h*HD)*NPT;
    const float* kp = kv + ((long long)b*2*CCH + h*HD)*NPT;
    const float* vp = kv + ((long long)b*2*CCH + CCH + h*HD)*NPT;
    float* oh = add + ((long long)b*CCH + h*HD)*NPT;

    int tid = threadIdx.x;
    const float scale = 0.17677669529663689f;

    #pragma unroll
    for (int e = tid; e < FQT*HD; e += 256) {
        int d = e >> 7, r = e & 127;
        int n = n0 + r;
        float qv = (n < NPT) ? qp[d*NPT + n]*scale : 0.f;
        float hf = __uint_as_float(f2tf32(qv));
        Qsh[r*QS_LD + d] = hf;
        Qsl[r*QS_LD + d] = __uint_as_float(f2tf32(qv - hf));
    }

    int w = tid >> 5, lane = tid & 31;
    int g = lane >> 2, t = lane & 3;
    int row = w*16 + g;

    float O[4][4];
    #pragma unroll
    for (int i=0;i<4;i++)
        #pragma unroll
        for (int j=0;j<4;j++) O[i][j] = 0.f;
    float m0r = -INFINITY, m1r = -INFINITY, l0r = 0.f, l1r = 0.f;

    const int NT = (NPT + FKT - 1)/FKT;

    for (int ti = 0; ti < NT; ti++) {
        int m0 = ti*FKT;
        __syncthreads();
        #pragma unroll
        for (int e = tid; e < HD*FKT; e += 256) {
            int d = e >> 6, c = e & 63;
            int m = m0 + c;
            float kvv = (m < NPT) ? kp[d*NPT + m] : 0.f;
            float hf = __uint_as_float(f2tf32(kvv));
            Kdh[d*KD_LD + c] = hf;
            Kdl[d*KD_LD + c] = __uint_as_float(f2tf32(kvv - hf));
            float vv = (m < NPT) ? vp[d*NPT + m] : 0.f;
            Vt[c*VT_LD2 + d] = __uint_as_float(f2tf32(vv));
        }
        __syncthreads();

        uint32_t qa[4][4], ql[4][4];
        #pragma unroll
        for (int ks=0; ks<4; ks++){
            int c0 = ks*8;
            qa[ks][0] = __float_as_uint(Qsh[(row  )*QS_LD + c0 + t]);
            qa[ks][1] = __float_as_uint(Qsh[(row+8)*QS_LD + c0 + t]);
            qa[ks][2] = __float_as_uint(Qsh[(row  )*QS_LD + c0 + t + 4]);
            qa[ks][3] = __float_as_uint(Qsh[(row+8)*QS_LD + c0 + t + 4]);
            ql[ks][0] = __float_as_uint(Qsl[(row  )*QS_LD + c0 + t]);
            ql[ks][1] = __float_as_uint(Qsl[(row+8)*QS_LD + c0 + t]);
            ql[ks][2] = __float_as_uint(Qsl[(row  )*QS_LD + c0 + t + 4]);
            ql[ks][3] = __float_as_uint(Qsl[(row+8)*QS_LD + c0 + t + 4]);
        }

        float S[8][4];
        #pragma unroll
        for (int nt=0; nt<8; nt++){
            S[nt][0]=0.f; S[nt][1]=0.f; S[nt][2]=0.f; S[nt][3]=0.f;
            #pragma unroll
            for (int ks=0; ks<4; ks++){
                int kr = ks*8 + t;
                int cidx = nt*8 + g;
                uint32_t bh0 = __float_as_uint(Kdh[(kr  )*KD_LD + cidx]);
                uint32_t bh1 = __float_as_uint(Kdh[(kr+4)*KD_LD + cidx]);
                uint32_t bl0 = __float_as_uint(Kdl[(kr  )*KD_LD + cidx]);
                uint32_t bl1 = __float_as_uint(Kdl[(kr+4)*KD_LD + cidx]);
                mma_tf32(S[nt], qa[ks], bh0, bh1);
                mma_tf32(S[nt], qa[ks], bl0, bl1);
                mma_tf32(S[nt], ql[ks], bh0, bh1);
            }
        }

        int mval = NPT - m0;
        float lm0 = -INFINITY, lm1 = -INFINITY;
        #pragma unroll
        for (int nt=0; nt<8; nt++){
            int c0 = nt*8 + 2*t, c1 = c0 + 1;
            if (c0 < mval){ lm0 = fmaxf(lm0, S[nt][0]); lm1 = fmaxf(lm1, S[nt][2]); }
            if (c1 < mval){ lm0 = fmaxf(lm0, S[nt][1]); lm1 = fmaxf(lm1, S[nt][3]); }
        }
        lm0 = fmaxf(lm0, __shfl_xor_sync(0xffffffffu, lm0, 1));
        lm0 = fmaxf(lm0, __shfl_xor_sync(0xffffffffu, lm0, 2));
        lm1 = fmaxf(lm1, __shfl_xor_sync(0xffffffffu, lm1, 1));
        lm1 = fmaxf(lm1, __shfl_xor_sync(0xffffffffu, lm1, 2));

        float mn0 = fmaxf(m0r, lm0), mn1 = fmaxf(m1r, lm1);
        float al0 = __expf(m0r - mn0), al1 = __expf(m1r - mn1);
        m0r = mn0; m1r = mn1;

        float ls0 = 0.f, ls1 = 0.f;
        #pragma unroll
        for (int nt=0; nt<8; nt++){
            int c0 = nt*8 + 2*t, c1 = c0 + 1;
            float e0 = (c0 < mval) ? __expf(S[nt][0] - mn0) : 0.f;
            float e1 = (c1 < mval) ? __expf(S[nt][1] - mn0) : 0.f;
            float e2 = (c0 < mval) ? __expf(S[nt][2] - mn1) : 0.f;
            float e3 = (c1 < mval) ? __expf(S[nt][3] - mn1) : 0.f;
            S[nt][0]=e0; S[nt][1]=e1; S[nt][2]=e2; S[nt][3]=e3;
            ls0 += e0 + e1; ls1 += e2 + e3;
        }
        ls0 += __shfl_xor_sync(0xffffffffu, ls0, 1);
        ls0 += __shfl_xor_sync(0xffffffffu, ls0, 2);
        ls1 += __shfl_xor_sync(0xffffffffu, ls1, 1);
        ls1 += __shfl_xor_sync(0xffffffffu, ls1, 2);
        l0r = l0r*al0 + ls0;
        l1r = l1r*al1 + ls1;
        #pragma unroll
        for (int nd=0; nd<4; nd++){
            O[nd][0] *= al0; O[nd][1] *= al0;
            O[nd][2] *= al1; O[nd][3] *= al1;
        }

        int s1 = g*4 + (t>>1), s2 = s1 + 2;
        bool odd = (t & 1);
        #pragma unroll
        for (int kt2=0; kt2<8; kt2++){
            float x0 = __shfl_sync(0xffffffffu, S[kt2][0], s1);
            float x1 = __shfl_sync(0xffffffffu, S[kt2][1], s1);
            float x2 = __shfl_sync(0xffffffffu, S[kt2][2], s1);
            float x3 = __shfl_sync(0xffffffffu, S[kt2][3], s1);
            float y0 = __shfl_sync(0xffffffffu, S[kt2][0], s2);
            float y1 = __shfl_sync(0xffffffffu, S[kt2][1], s2);
            float y2 = __shfl_sync(0xffffffffu, S[kt2][2], s2);
            float y3 = __shfl_sync(0xffffffffu, S[kt2][3], s2);
            uint32_t pa[4];
            pa[0] = f2tf32(odd ? x1 : x0);
            pa[1] = f2tf32(odd ? x3 : x2);
            pa[2] = f2tf32(odd ? y1 : y0);
            pa[3] = f2tf32(odd ? y3 : y2);
            #pragma unroll
            for (int nd=0; nd<4; nd++){
                uint32_t b0 = __float_as_uint(Vt[(kt2*8 + t    )*VT_LD2 + nd*8 + g]);
                uint32_t b1 = __float_as_uint(Vt[(kt2*8 + t + 4)*VT_LD2 + nd*8 + g]);
                mma_tf32(O[nd], pa, b0, b1);
            }
        }
    }

    float inv0 = 1.f / l0r, inv1 = 1.f / l1r;
    int q0 = n0 + row, q1 = q0 + 8;
    #pragma unroll
    for (int nd=0; nd<4; nd++){
        int d0 = nd*8 + 2*t, d1 = d0 + 1;
        if (q0 < NPT){
            oh[(long long)d0*NPT + q0] = O[nd][0]*inv0;
            oh[(long long)d1*NPT + q0] = O[nd][1]*inv0;
        }
        if (q1 < NPT){
            oh[(long long)d0*NPT + q1] = O[nd][2]*inv1;
            oh[(long long)d1*NPT + q1] = O[nd][3]*inv1;
        }
    }
}

// ---------------- launch ------------------------------------------------------
static inline dim3 gmma(int M, int Nc, int batches) {
    return dim3((Nc + GM_TN - 1)/GM_TN, (M + GM_TM - 1)/GM_TM, batches);
}

extern "C" void kernel_launch(void* const* d_in, const int* in_sizes, int n_in,
                              void* d_out, int out_size)
{
    const float* x    = (const float*)d_in[0];
    const float* y    = (const float*)d_in[1];
    const float* dgw1 = (const float*)d_in[2];
    const float* dgb1 = (const float*)d_in[3];
    const float* dgg1 = (const float*)d_in[4];
    const float* dgbe1= (const float*)d_in[5];
    const float* dgw2 = (const float*)d_in[6];
    const float* dgb2 = (const float*)d_in[7];
    const float* dgg2 = (const float*)d_in[8];
    const float* dgbe2= (const float*)d_in[9];
    const float* wq   = (const float*)d_in[10];
    const float* bq   = (const float*)d_in[11];
    const float* wk   = (const float*)d_in[12];
    const float* bk   = (const float*)d_in[13];
    const float* wv   = (const float*)d_in[14];
    const float* bv   = (const float*)d_in[15];
    const float* wmh  = (const float*)d_in[16];
    const float* bmh  = (const float*)d_in[17];
    const float* wc1  = (const float*)d_in[18];
    const float* bc1  = (const float*)d_in[19];
    const float* cg   = (const float*)d_in[20];
    const float* cbe  = (const float*)d_in[21];
    const float* wc2  = (const float*)d_in[22];
    const float* bc2  = (const float*)d_in[23];
    float* out = (float*)d_out;

    float *w1sb,*wkv,*bkv,*gram,*xx,*uv,*h,*h2,*agg,*q,*kvb,*add,*cat,*hc;
    int* idx;
    cudaGetSymbolAddress((void**)&w1sb, g_w1sb);
    cudaGetSymbolAddress((void**)&wkv,  g_wkv);
    cudaGetSymbolAddress((void**)&bkv,  g_bkv);
    cudaGetSymbolAddress((void**)&gram, g_gram);
    cudaGetSymbolAddress((void**)&xx,   g_xx);
    cudaGetSymbolAddress((void**)&idx,  g_idx);
    cudaGetSymbolAddress((void**)&uv,   g_uv);
    cudaGetSymbolAddress((void**)&h,    g_h);
    cudaGetSymbolAddress((void**)&h2,   g_h2);
    cudaGetSymbolAddress((void**)&agg,  g_agg);
    cudaGetSymbolAddress((void**)&q,    g_q);
    cudaGetSymbolAddress((void**)&kvb,  g_kv);
    cudaGetSymbolAddress((void**)&add,  g_add);
    cudaGetSymbolAddress((void**)&cat,  g_cat);
    cudaGetSymbolAddress((void**)&hc,   g_hc);

    const long long CN  = (long long)CCH*NPT;
    const long long CNK = (long long)CCH*NPT*KNNK;
    const int FLASH_SMEM = FLASH_SM_FLOATS * 4;
    const int NTILES = (NPT + TM - 1)/TM;
    const int NTRI = NTILES*(NTILES+1)/2;

    cudaFuncSetAttribute(flash_mma, cudaFuncAttributeMaxDynamicSharedMemorySize, FLASH_SMEM);

    // 1) prep
    prep_kernel<<<(CCH*CCH+255)/256, 256>>>(dgw1, wk, wv, bk, bv, w1sb, wkv, bkv);

    // 2) gram[b] = x^T x (triangular + mirror); diag -> xx
    gram_kernel<<<dim3(NTRI, 1, BSZ), 256>>>(x, gram, xx);

    // 3) top-9
    topk_kernel<<<dim3(NPT, BSZ), 256>>>(gram, xx, idx);

    // 4) uv = [w1s; w1b] @ x
    gemm_mma<<<gmma(2*CCH,NPT,BSZ), 256>>>(
        w1sb, x, uv, 2*CCH, NPT, CCH, CCH, NPT, NPT,
        0, CN, 2*CN, nullptr, nullptr, nullptr, 0, nullptr, 0, 0);

    // 5) edge features -> h
    {
        long long total = (long long)BSZ*CNK;
        gather_h_kernel<<<(unsigned)((total+255)/256), 256>>>(uv, idx, dgb1, dgg1, dgbe1, h);
    }

    // 6) conv2, fused bn+relu
    gemm_mma<<<gmma(CCH, NPT*KNNK, BSZ), 256>>>(
        dgw2, h, h2, CCH, NPT*KNNK, CCH, CCH, NPT*KNNK, NPT*KNNK,
        0, CNK, CNK, dgb2, dgg2, dgbe2, 1, nullptr, 0, 0);

    // 7) max over k
    maxk_kernel<<<(BSZ*CCH*NPT+255)/256, 256>>>(h2, agg, cat);

    // 8) q, kv projections
    gemm_mma<<<gmma(CCH,NPT,BSZ), 256>>>(
        wq, agg, q, CCH, NPT, CCH, CCH, NPT, NPT,
        0, CN, CN, bq, nullptr, nullptr, 0, nullptr, 0, 0);
    gemm_mma<<<gmma(2*CCH,NPT,BSZ), 256>>>(
        wkv, y, kvb, 2*CCH, NPT, CCH, CCH, NPT, NPT,
        0, CN, 2*CN, bkv, nullptr, nullptr, 0, nullptr, 0, 0);

    // 9) fused attention (tf32 mma) -> add
    {
        dim3 grid((NPT + FQT - 1)/FQT, NHEAD, BSZ);
        flash_mma<<<grid, 256, FLASH_SMEM>>>(q, kvb, add);
    }

    // 10) mh conv -> bottom half of cat
    gemm_mma<<<gmma(CCH,NPT,BSZ), 256>>>(
        wmh, add, cat + CN, CCH, NPT, CCH, CCH, NPT, NPT,
        0, CN, 2*CN, bmh, nullptr, nullptr, 0, nullptr, 0, 0);

    // 11) hc = relu(bn(wc1 @ cat + bc1))
    gemm_mma<<<gmma(2*CCH,NPT,BSZ), 256>>>(
        wc1, cat, hc, 2*CCH, NPT, 2*CCH, 2*CCH, NPT, NPT,
        0, 2*CN, 2*CN, bc1, cg, cbe, 1, nullptr, 0, 0);

    // 12) out = agg + wc2 @ hc + bc2
    gemm_mma<<<gmma(CCH,NPT,BSZ), 256>>>(
        wc2, hc, out, CCH, NPT, 2*CCH, 2*CCH, NPT, NPT,
        0, 2*CN, CN, bc2, nullptr, nullptr, 0, agg, CN, NPT);
}

// round 9
// speedup vs baseline: 2.6160x; 1.0235x over previous
#include <cuda_runtime.h>
#include <math.h>
#include <stdint.h>

#define BSZ   4
#define CCH   128
#define NPT   2000
#define KNNK  9
#define NHEAD 4
#define HD    32
#define BN_EPS 1e-5f

// ---------------- scratch ------------------------------------------------
__device__ float g_w1sb[2*CCH*CCH];
__device__ float g_wkv [2*CCH*CCH];
__device__ float g_bkv [2*CCH];
__device__ float g_gram[(size_t)BSZ*NPT*NPT];
__device__ float g_xx[BSZ*NPT];
__device__ int   g_idx[BSZ*NPT*KNNK];
__device__ float g_uv[BSZ*2*CCH*NPT];
__device__ float g_h [(size_t)BSZ*CCH*NPT*KNNK];
__device__ float g_h2[(size_t)BSZ*CCH*NPT*KNNK];
__device__ float g_agg[BSZ*CCH*NPT];
__device__ float g_q  [BSZ*CCH*NPT];
__device__ float g_kv [BSZ*2*CCH*NPT];
__device__ float g_add[BSZ*CCH*NPT];
__device__ float g_cat[BSZ*2*CCH*NPT];
__device__ float g_hc [BSZ*2*CCH*NPT];

// ---------------- tf32 helpers -------------------------------------------
__device__ __forceinline__ uint32_t f2tf32(float x){
    uint32_t r;
    asm("cvt.rna.tf32.f32 %0, %1;" : "=r"(r) : "f"(x));
    return r;
}
__device__ __forceinline__ void mma_tf32(float* d, const uint32_t* a, uint32_t b0, uint32_t b1){
    asm volatile(
        "mma.sync.aligned.m16n8k8.row.col.f32.tf32.tf32.f32 "
        "{%0,%1,%2,%3},{%4,%5,%6,%7},{%8,%9},{%0,%1,%2,%3};"
        : "+f"(d[0]), "+f"(d[1]), "+f"(d[2]), "+f"(d[3])
        : "r"(a[0]), "r"(a[1]), "r"(a[2]), "r"(a[3]), "r"(b0), "r"(b1));
}

// ---------------- split-tf32 MMA GEMM (R8 proven) ---------------------------
#define GM_TM 128
#define GM_TN 64
#define GA_LD 20
#define GB_LD 72

__global__ void __launch_bounds__(256) gemm_mma(
    const float* __restrict__ A, const float* __restrict__ B, float* __restrict__ Cm,
    int M, int Nc, int Kc, int lda, int ldb, int ldc,
    long long sA, long long sB, long long sC,
    const float* __restrict__ bias,
    const float* __restrict__ gamma, const float* __restrict__ beta,
    int relu,
    const float* __restrict__ resid, long long sR, int ldr)
{
    int bz = blockIdx.z;
    A  += (long long)bz * sA;
    B  += (long long)bz * sB;
    Cm += (long long)bz * sC;
    if (resid) resid += (long long)bz * sR;

    __shared__ float AH[GM_TM*GA_LD], AL[GM_TM*GA_LD];
    __shared__ float BH[16*GB_LD],    BL[16*GB_LD];

    int m0 = blockIdx.y * GM_TM;
    int n0 = blockIdx.x * GM_TN;
    int tid = threadIdx.x;
    int w = tid >> 5, lane = tid & 31;
    int g = lane >> 2, t = lane & 3;
    int row = w*16;

    float acc[8][4];
    #pragma unroll
    for (int i=0;i<8;i++)
        #pragma unroll
        for (int j=0;j<4;j++) acc[i][j] = 0.f;

    for (int kc = 0; kc < Kc; kc += 16) {
        #pragma unroll
        for (int it=0; it<8; it++){
            int e = tid + it*256;
            int kk = e & 15, r = e >> 4;
            int gm = m0 + r;
            float av = (gm < M) ? A[(long long)gm*lda + kc + kk] : 0.f;
            float ah = __uint_as_float(f2tf32(av));
            AH[r*GA_LD + kk] = ah;
            AL[r*GA_LD + kk] = __uint_as_float(f2tf32(av - ah));
        }
        #pragma unroll
        for (int it=0; it<4; it++){
            int e = tid + it*256;
            int n_ = e & 63, k_ = e >> 6;
            int gn = n0 + n_;
            float bv = (gn < Nc) ? B[(long long)(kc + k_)*ldb + gn] : 0.f;
            float bh = __uint_as_float(f2tf32(bv));
            BH[k_*GB_LD + n_] = bh;
            BL[k_*GB_LD + n_] = __uint_as_float(f2tf32(bv - bh));
        }
        __syncthreads();

        #pragma unroll
        for (int ks=0; ks<2; ks++){
            int c0 = ks*8;
            uint32_t ah[4], al[4];
            ah[0] = __float_as_uint(AH[(row+g  )*GA_LD + c0 + t]);
            ah[1] = __float_as_uint(AH[(row+8+g)*GA_LD + c0 + t]);
            ah[2] = __float_as_uint(AH[(row+g  )*GA_LD + c0 + t + 4]);
            ah[3] = __float_as_uint(AH[(row+8+g)*GA_LD + c0 + t + 4]);
            al[0] = __float_as_uint(AL[(row+g  )*GA_LD + c0 + t]);
            al[1] = __float_as_uint(AL[(row+8+g)*GA_LD + c0 + t]);
            al[2] = __float_as_uint(AL[(row+g  )*GA_LD + c0 + t + 4]);
            al[3] = __float_as_uint(AL[(row+8+g)*GA_LD + c0 + t + 4]);
            int kr = ks*8 + t;
            #pragma unroll
            for (int nt=0; nt<8; nt++){
                int cidx = nt*8 + g;
                uint32_t bh0 = __float_as_uint(BH[(kr  )*GB_LD + cidx]);
                uint32_t bh1 = __float_as_uint(BH[(kr+4)*GB_LD + cidx]);
                uint32_t bl0 = __float_as_uint(BL[(kr  )*GB_LD + cidx]);
                uint32_t bl1 = __float_as_uint(BL[(kr+4)*GB_LD + cidx]);
                mma_tf32(acc[nt], ah, bh0, bh1);
                mma_tf32(acc[nt], ah, bl0, bl1);
                mma_tf32(acc[nt], al, bh0, bh1);
            }
        }
        __syncthreads();
    }

    const float invs = rsqrtf(1.0f + BN_EPS);
    #pragma unroll
    for (int half=0; half<2; half++){
        int gm = m0 + row + half*8 + g;
        if (gm >= M) continue;
        float bi = bias  ? bias[gm]       : 0.f;
        float ga = gamma ? gamma[gm]*invs : 1.f;
        float be = beta  ? beta[gm]       : 0.f;
        #pragma unroll
        for (int nt=0; nt<8; nt++){
            int c0 = n0 + nt*8 + 2*t;
            #pragma unroll
            for (int jj=0; jj<2; jj++){
                int gn = c0 + jj;
                if (gn >= Nc) continue;
                float r = acc[nt][half*2 + jj] + bi;
                if (gamma) r = r*ga + be;
                if (relu)  r = fmaxf(r, 0.f);
                if (resid) r += resid[(long long)gm*ldr + gn];
                Cm[(long long)gm*ldc + gn] = r;
            }
        }
    }
}

// ---------------- Gram via split-tf32 MMA: triangular tiles + mirror ---------
// Tile 128x64 over (bi, bj2) with bj2 >= 2*bi. acc(m,n) == acc(n,m), so
// direct + mirrored stores are always consistent (incl. diagonal tiles).
#define GRA_LD 17

__global__ void __launch_bounds__(256) gram_mma(
    const float* __restrict__ x,     // [B][C][N]
    float* __restrict__ gram,        // [B][N][N]
    float* __restrict__ xx)          // [B][N]
{
    __shared__ float AH[GM_TM*GRA_LD], AL[GM_TM*GRA_LD];
    __shared__ float BH[16*GB_LD],    BL[16*GB_LD];

    int b = blockIdx.z;
    const float* xb = x + (long long)b*CCH*NPT;
    float* gb = gram + (long long)b*NPT*NPT;

    // decode triangular tile id -> (bi, bj2)
    int tt = blockIdx.x;
    int bi = 0;
    while ((32*(bi+1) - (bi+1)*bi) <= tt) bi++;
    int bj2 = 2*bi + (tt - (32*bi - bi*(bi-1)));

    int m0 = bi * GM_TM;
    int n0 = bj2 * GM_TN;
    int tid = threadIdx.x;
    int w = tid >> 5, lane = tid & 31;
    int g = lane >> 2, t = lane & 3;
    int row = w*16;

    float acc[8][4];
    #pragma unroll
    for (int i=0;i<8;i++)
        #pragma unroll
        for (int j=0;j<4;j++) acc[i][j] = 0.f;

    for (int kc = 0; kc < CCH; kc += 16) {
        // A chunk: x is k-major -> coalesce along m (r = e&127)
        #pragma unroll
        for (int it=0; it<8; it++){
            int e = tid + it*256;
            int r = e & 127, kk = e >> 7;
            int gm = m0 + r;
            float av = (gm < NPT) ? xb[(long long)(kc+kk)*NPT + gm] : 0.f;
            float ah = __uint_as_float(f2tf32(av));
            AH[r*GRA_LD + kk] = ah;
            AL[r*GRA_LD + kk] = __uint_as_float(f2tf32(av - ah));
        }
        // B chunk: coalesced along n
        #pragma unroll
        for (int it=0; it<4; it++){
            int e = tid + it*256;
            int n_ = e & 63, k_ = e >> 6;
            int gn = n0 + n_;
            float bv = (gn < NPT) ? xb[(long long)(kc + k_)*NPT + gn] : 0.f;
            float bh = __uint_as_float(f2tf32(bv));
            BH[k_*GB_LD + n_] = bh;
            BL[k_*GB_LD + n_] = __uint_as_float(f2tf32(bv - bh));
        }
        __syncthreads();

        #pragma unroll
        for (int ks=0; ks<2; ks++){
            int c0 = ks*8;
            uint32_t ah[4], al[4];
            ah[0] = __float_as_uint(AH[(row+g  )*GRA_LD + c0 + t]);
            ah[1] = __float_as_uint(AH[(row+8+g)*GRA_LD + c0 + t]);
            ah[2] = __float_as_uint(AH[(row+g  )*GRA_LD + c0 + t + 4]);
            ah[3] = __float_as_uint(AH[(row+8+g)*GRA_LD + c0 + t + 4]);
            al[0] = __float_as_uint(AL[(row+g  )*GRA_LD + c0 + t]);
            al[1] = __float_as_uint(AL[(row+8+g)*GRA_LD + c0 + t]);
            al[2] = __float_as_uint(AL[(row+g  )*GRA_LD + c0 + t + 4]);
            al[3] = __float_as_uint(AL[(row+8+g)*GRA_LD + c0 + t + 4]);
            int kr = ks*8 + t;
            #pragma unroll
            for (int nt=0; nt<8; nt++){
                int cidx = nt*8 + g;
                uint32_t bh0 = __float_as_uint(BH[(kr  )*GB_LD + cidx]);
                uint32_t bh1 = __float_as_uint(BH[(kr+4)*GB_LD + cidx]);
                uint32_t bl0 = __float_as_uint(BL[(kr  )*GB_LD + cidx]);
                uint32_t bl1 = __float_as_uint(BL[(kr+4)*GB_LD + cidx]);
                mma_tf32(acc[nt], ah, bh0, bh1);
                mma_tf32(acc[nt], ah, bl0, bl1);
                mma_tf32(acc[nt], al, bh0, bh1);
            }
        }
        __syncthreads();
    }

    bool diagtile = (bj2 >> 1) == bi;
    #pragma unroll
    for (int half=0; half<2; half++){
        int gm = m0 + row + half*8 + g;
        if (gm >= NPT) continue;
        #pragma unroll
        for (int nt=0; nt<8; nt++){
            #pragma unroll
            for (int jj=0; jj<2; jj++){
                int gn = n0 + nt*8 + 2*t + jj;
                if (gn >= NPT) continue;
                float val = acc[nt][half*2 + jj];
                gb[(long long)gm*NPT + gn] = val;       // direct
                gb[(long long)gn*NPT + gm] = val;       // mirror (consistent)
                if (diagtile && gm == gn) xx[b*NPT + gm] = val;
            }
        }
    }
}

// ---------------- prep ------------------------------------------------------
__global__ void prep_kernel(const float* __restrict__ w1,
                            const float* __restrict__ wk, const float* __restrict__ wv,
                            const float* __restrict__ bk, const float* __restrict__ bv,
                            float* __restrict__ w1sb, float* __restrict__ wkv,
                            float* __restrict__ bkv)
{
    int i = blockIdx.x*blockDim.x + threadIdx.x;
    if (i < CCH*CCH) {
        int o = i / CCH, c = i % CCH;
        float a  = w1[o*2*CCH + c];
        float bb = w1[o*2*CCH + CCH + c];
        w1sb[i] = a + bb;
        w1sb[CCH*CCH + i] = bb;
        wkv[i] = wk[i];
        wkv[CCH*CCH + i] = wv[i];
    }
    if (i < 2*CCH) bkv[i] = (i < CCH) ? bk[i] : bv[i - CCH];
}

// ---------------- topk: lane sort-8 + warp k-way merge -----------------------
__global__ void __launch_bounds__(256) topk_kernel(const float* __restrict__ gram,
                                                   const float* __restrict__ xx,
                                                   int* __restrict__ idx)
{
    int n = blockIdx.x, b = blockIdx.y;
    const float* row = gram + ((long long)(b*NPT+n))*NPT;
    const float* xb  = xx + b*NPT;
    int tid = threadIdx.x, w = tid >> 5, l = tid & 31;

    float v[8]; int id[8];
    #pragma unroll
    for (int j=0;j<8;j++){
        int m = w*256 + j*32 + l;
        bool ok = m < NPT;
        v[j]  = ok ? (2.f*row[m] - xb[m]) : -INFINITY;
        id[j] = ok ? m : 0x7fffffff;
    }
#define CSWP(a,bb) { bool sw = (v[a]<v[bb]) || (v[a]==v[bb] && id[a]>id[bb]); \
    float tv = sw?v[bb]:v[a]; float uv2 = sw?v[a]:v[bb]; v[a]=tv; v[bb]=uv2;   \
    int ti = sw?id[bb]:id[a]; int ui = sw?id[a]:id[bb]; id[a]=ti; id[bb]=ui; }
    CSWP(0,1) CSWP(2,3) CSWP(4,5) CSWP(6,7)
    CSWP(0,2) CSWP(1,3) CSWP(4,6) CSWP(5,7)
    CSWP(1,2) CSWP(5,6)
    CSWP(0,4) CSWP(1,5) CSWP(2,6) CSWP(3,7)
    CSWP(2,4) CSWP(3,5)
    CSWP(1,2) CSWP(3,4) CSWP(5,6)
#undef CSWP

    __shared__ float wv[8][12];
    __shared__ int   wi[8][12];

    float hv = v[0]; int hi = id[0];
    #pragma unroll
    for (int t=0;t<KNNK;t++){
        float bvv = hv; int bii = hi;
        #pragma unroll
        for (int s=16; s>0; s>>=1){
            float ov = __shfl_xor_sync(0xffffffffu, bvv, s);
            int   oi = __shfl_xor_sync(0xffffffffu, bii, s);
            if (ov > bvv || (ov == bvv && oi < bii)) { bvv = ov; bii = oi; }
        }
        if (l == 0) { wv[w][t] = bvv; wi[w][t] = bii; }
        if (hi == bii) {
            #pragma unroll
            for (int j=0;j<7;j++){ v[j]=v[j+1]; id[j]=id[j+1]; }
            v[7] = -INFINITY; id[7] = 0x7fffffff;
            hv = v[0]; hi = id[0];
        }
    }
    __syncthreads();

    if (w == 0){
        int ptr = 0;
        float hv2 = (l < 8) ? wv[l][0] : -INFINITY;
        int   hi2 = (l < 8) ? wi[l][0] : 0x7fffffff;
        int* outp = idx + (b*NPT+n)*KNNK;
        #pragma unroll
        for (int t=0;t<KNNK;t++){
            float bvv = hv2; int bii = hi2;
            #pragma unroll
            for (int s=16; s>0; s>>=1){
                float ov = __shfl_xor_sync(0xffffffffu, bvv, s);
                int   oi = __shfl_xor_sync(0xffffffffu, bii, s);
                if (ov > bvv || (ov == bvv && oi < bii)) { bvv = ov; bii = oi; }
            }
            if (l == 0) outp[t] = bii;
            if (hi2 == bii){
                ptr++;
                hv2 = (ptr < KNNK && l < 8) ? wv[l][ptr] : -INFINITY;
                hi2 = (ptr < KNNK && l < 8) ? wi[l][ptr] : 0x7fffffff;
            }
        }
    }
}

// h[b,c,n*9+k] = relu( bn( u[b,c,n] - v[b,c,idx] + b1[c] ) )
__global__ void gather_h_kernel(const float* __restrict__ uv,
                                const int* __restrict__ idx,
                                const float* __restrict__ b1, const float* __restrict__ g1,
                                const float* __restrict__ be1, float* __restrict__ h)
{
    long long i = (long long)blockIdx.x*blockDim.x + threadIdx.x;
    const long long total = (long long)BSZ*CCH*NPT*KNNK;
    if (i >= total) return;
    int k = (int)(i % KNNK);
    long long r = i / KNNK;
    int n = (int)(r % NPT); r /= NPT;
    int c = (int)(r % CCH);
    int b = (int)(r / CCH);
    int j = idx[(b*NPT+n)*KNNK + k];
    const float* ub = uv + (long long)b*2*CCH*NPT + (long long)c*NPT;
    float uvv = ub[n];
    float vg  = ub[(long long)CCH*NPT + j];
    const float invs = rsqrtf(1.f + BN_EPS);
    float val = (uvv - vg + b1[c]) * (g1[c]*invs) + be1[c];
    h[((long long)(b*CCH+c))*NPT*KNNK + (long long)n*KNNK + k] = fmaxf(val, 0.f);
}

// agg[b,c,n] = max_k h2[...]; also writes top half of cat
__global__ void maxk_kernel(const float* __restrict__ h2,
                            float* __restrict__ agg, float* __restrict__ cat)
{
    int i = blockIdx.x*blockDim.x + threadIdx.x;
    if (i >= BSZ*CCH*NPT) return;
    int n = i % NPT;
    int c = (i / NPT) % CCH;
    int b = i / (NPT*CCH);
    const float* p = h2 + ((long long)(b*CCH+c))*NPT*KNNK + (long long)n*KNNK;
    float m = p[0];
    #pragma unroll
    for (int k = 1; k < KNNK; k++) m = fmaxf(m, p[k]);
    agg[i] = m;
    cat[(long long)b*2*CCH*NPT + (long long)c*NPT + n] = m;
}

// ---------------- flash attention with tf32 mma.sync (R7 proven) -------------
#define FQT 128
#define FKT 64
#define QS_LD 36
#define KD_LD 72
#define VT_LD2 40
#define OF_QH 0
#define OF_QL (FQT*QS_LD)
#define OF_KH (OF_QL + FQT*QS_LD)
#define OF_KL (OF_KH + HD*KD_LD)
#define OF_VT (OF_KL + HD*KD_LD)
#define FLASH_SM_FLOATS (OF_VT + FKT*VT_LD2)

__global__ void __launch_bounds__(256,2) flash_mma(
    const float* __restrict__ q,
    const float* __restrict__ kv,
    float* __restrict__ add)
{
    extern __shared__ float sm[];
    float* Qsh = sm + OF_QH;
    float* Qsl = sm + OF_QL;
    float* Kdh = sm + OF_KH;
    float* Kdl = sm + OF_KL;
    float* Vt  = sm + OF_VT;

    int n0 = blockIdx.x * FQT;
    int h  = blockIdx.y;
    int b  = blockIdx.z;
    const float* qp = q  + ((long long)b*CCH   + h*HD)*NPT;
    const float* kp = kv + ((long long)b*2*CCH + h*HD)*NPT;
    const float* vp = kv + ((long long)b*2*CCH + CCH + h*HD)*NPT;
    float* oh = add + ((long long)b*CCH + h*HD)*NPT;

    int tid = threadIdx.x;
    const float scale = 0.17677669529663689f;

    #pragma unroll
    for (int e = tid; e < FQT*HD; e += 256) {
        int d = e >> 7, r = e & 127;
        int n = n0 + r;
        float qv = (n < NPT) ? qp[d*NPT + n]*scale : 0.f;
        float hf = __uint_as_float(f2tf32(qv));
        Qsh[r*QS_LD + d] = hf;
        Qsl[r*QS_LD + d] = __uint_as_float(f2tf32(qv - hf));
    }

    int w = tid >> 5, lane = tid & 31;
    int g = lane >> 2, t = lane & 3;
    int row = w*16 + g;

    float O[4][4];
    #pragma unroll
    for (int i=0;i<4;i++)
        #pragma unroll
        for (int j=0;j<4;j++) O[i][j] = 0.f;
    float m0r = -INFINITY, m1r = -INFINITY, l0r = 0.f, l1r = 0.f;

    const int NT = (NPT + FKT - 1)/FKT;

    for (int ti = 0; ti < NT; ti++) {
        int m0 = ti*FKT;
        __syncthreads();
        #pragma unroll
        for (int e = tid; e < HD*FKT; e += 256) {
            int d = e >> 6, c = e & 63;
            int m = m0 + c;
            float kvv = (m < NPT) ? kp[d*NPT + m] : 0.f;
            float hf = __uint_as_float(f2tf32(kvv));
            Kdh[d*KD_LD + c] = hf;
            Kdl[d*KD_LD + c] = __uint_as_float(f2tf32(kvv - hf));
            float vv = (m < NPT) ? vp[d*NPT + m] : 0.f;
            Vt[c*VT_LD2 + d] = __uint_as_float(f2tf32(vv));
        }
        __syncthreads();

        uint32_t qa[4][4], ql[4][4];
        #pragma unroll
        for (int ks=0; ks<4; ks++){
            int c0 = ks*8;
            qa[ks][0] = __float_as_uint(Qsh[(row  )*QS_LD + c0 + t]);
            qa[ks][1] = __float_as_uint(Qsh[(row+8)*QS_LD + c0 + t]);
            qa[ks][2] = __float_as_uint(Qsh[(row  )*QS_LD + c0 + t + 4]);
            qa[ks][3] = __float_as_uint(Qsh[(row+8)*QS_LD + c0 + t + 4]);
            ql[ks][0] = __float_as_uint(Qsl[(row  )*QS_LD + c0 + t]);
            ql[ks][1] = __float_as_uint(Qsl[(row+8)*QS_LD + c0 + t]);
            ql[ks][2] = __float_as_uint(Qsl[(row  )*QS_LD + c0 + t + 4]);
            ql[ks][3] = __float_as_uint(Qsl[(row+8)*QS_LD + c0 + t + 4]);
        }

        float S[8][4];
        #pragma unroll
        for (int nt=0; nt<8; nt++){
            S[nt][0]=0.f; S[nt][1]=0.f; S[nt][2]=0.f; S[nt][3]=0.f;
            #pragma unroll
            for (int ks=0; ks<4; ks++){
                int kr = ks*8 + t;
                int cidx = nt*8 + g;
                uint32_t bh0 = __float_as_uint(Kdh[(kr  )*KD_LD + cidx]);
                uint32_t bh1 = __float_as_uint(Kdh[(kr+4)*KD_LD + cidx]);
                uint32_t bl0 = __float_as_uint(Kdl[(kr  )*KD_LD + cidx]);
                uint32_t bl1 = __float_as_uint(Kdl[(kr+4)*KD_LD + cidx]);
                mma_tf32(S[nt], qa[ks], bh0, bh1);
                mma_tf32(S[nt], qa[ks], bl0, bl1);
                mma_tf32(S[nt], ql[ks], bh0, bh1);
            }
        }

        int mval = NPT - m0;
        float lm0 = -INFINITY, lm1 = -INFINITY;
        #pragma unroll
        for (int nt=0; nt<8; nt++){
            int c0 = nt*8 + 2*t, c1 = c0 + 1;
            if (c0 < mval){ lm0 = fmaxf(lm0, S[nt][0]); lm1 = fmaxf(lm1, S[nt][2]); }
            if (c1 < mval){ lm0 = fmaxf(lm0, S[nt][1]); lm1 = fmaxf(lm1, S[nt][3]); }
        }
        lm0 = fmaxf(lm0, __shfl_xor_sync(0xffffffffu, lm0, 1));
        lm0 = fmaxf(lm0, __shfl_xor_sync(0xffffffffu, lm0, 2));
        lm1 = fmaxf(lm1, __shfl_xor_sync(0xffffffffu, lm1, 1));
        lm1 = fmaxf(lm1, __shfl_xor_sync(0xffffffffu, lm1, 2));

        float mn0 = fmaxf(m0r, lm0), mn1 = fmaxf(m1r, lm1);
        float al0 = __expf(m0r - mn0), al1 = __expf(m1r - mn1);
        m0r = mn0; m1r = mn1;

        float ls0 = 0.f, ls1 = 0.f;
        #pragma unroll
        for (int nt=0; nt<8; nt++){
            int c0 = nt*8 + 2*t, c1 = c0 + 1;
            float e0 = (c0 < mval) ? __expf(S[nt][0] - mn0) : 0.f;
            float e1 = (c1 < mval) ? __expf(S[nt][1] - mn0) : 0.f;
            float e2 = (c0 < mval) ? __expf(S[nt][2] - mn1) : 0.f;
            float e3 = (c1 < mval) ? __expf(S[nt][3] - mn1) : 0.f;
            S[nt][0]=e0; S[nt][1]=e1; S[nt][2]=e2; S[nt][3]=e3;
            ls0 += e0 + e1; ls1 += e2 + e3;
        }
        ls0 += __shfl_xor_sync(0xffffffffu, ls0, 1);
        ls0 += __shfl_xor_sync(0xffffffffu, ls0, 2);
        ls1 += __shfl_xor_sync(0xffffffffu, ls1, 1);
        ls1 += __shfl_xor_sync(0xffffffffu, ls1, 2);
        l0r = l0r*al0 + ls0;
        l1r = l1r*al1 + ls1;
        #pragma unroll
        for (int nd=0; nd<4; nd++){
            O[nd][0] *= al0; O[nd][1] *= al0;
            O[nd][2] *= al1; O[nd][3] *= al1;
        }

        int s1 = g*4 + (t>>1), s2 = s1 + 2;
        bool odd = (t & 1);
        #pragma unroll
        for (int kt2=0; kt2<8; kt2++){
            float x0 = __shfl_sync(0xffffffffu, S[kt2][0], s1);
            float x1 = __shfl_sync(0xffffffffu, S[kt2][1], s1);
            float x2 = __shfl_sync(0xffffffffu, S[kt2][2], s1);
            float x3 = __shfl_sync(0xffffffffu, S[kt2][3], s1);
            float y0 = __shfl_sync(0xffffffffu, S[kt2][0], s2);
            float y1 = __shfl_sync(0xffffffffu, S[kt2][1], s2);
            float y2 = __shfl_sync(0xffffffffu, S[kt2][2], s2);
            float y3 = __shfl_sync(0xffffffffu, S[kt2][3], s2);
            uint32_t pa[4];
            pa[0] = f2tf32(odd ? x1 : x0);
            pa[1] = f2tf32(odd ? x3 : x2);
            pa[2] = f2tf32(odd ? y1 : y0);
            pa[3] = f2tf32(odd ? y3 : y2);
            #pragma unroll
            for (int nd=0; nd<4; nd++){
                uint32_t b0 = __float_as_uint(Vt[(kt2*8 + t    )*VT_LD2 + nd*8 + g]);
                uint32_t b1 = __float_as_uint(Vt[(kt2*8 + t + 4)*VT_LD2 + nd*8 + g]);
                mma_tf32(O[nd], pa, b0, b1);
            }
        }
    }

    float inv0 = 1.f / l0r, inv1 = 1.f / l1r;
    int q0 = n0 + row, q1 = q0 + 8;
    #pragma unroll
    for (int nd=0; nd<4; nd++){
        int d0 = nd*8 + 2*t, d1 = d0 + 1;
        if (q0 < NPT){
            oh[(long long)d0*NPT + q0] = O[nd][0]*inv0;
            oh[(long long)d1*NPT + q0] = O[nd][1]*inv0;
        }
        if (q1 < NPT){
            oh[(long long)d0*NPT + q1] = O[nd][2]*inv1;
            oh[(long long)d1*NPT + q1] = O[nd][3]*inv1;
        }
    }
}

// ---------------- launch ------------------------------------------------------
static inline dim3 gmma(int M, int Nc, int batches) {
    return dim3((Nc + GM_TN - 1)/GM_TN, (M + GM_TM - 1)/GM_TM, batches);
}

extern "C" void kernel_launch(void* const* d_in, const int* in_sizes, int n_in,
                              void* d_out, int out_size)
{
    const float* x    = (const float*)d_in[0];
    const float* y    = (const float*)d_in[1];
    const float* dgw1 = (const float*)d_in[2];
    const float* dgb1 = (const float*)d_in[3];
    const float* dgg1 = (const float*)d_in[4];
    const float* dgbe1= (const float*)d_in[5];
    const float* dgw2 = (const float*)d_in[6];
    const float* dgb2 = (const float*)d_in[7];
    const float* dgg2 = (const float*)d_in[8];
    const float* dgbe2= (const float*)d_in[9];
    const float* wq   = (const float*)d_in[10];
    const float* bq   = (const float*)d_in[11];
    const float* wk   = (const float*)d_in[12];
    const float* bk   = (const float*)d_in[13];
    const float* wv   = (const float*)d_in[14];
    const float* bv   = (const float*)d_in[15];
    const float* wmh  = (const float*)d_in[16];
    const float* bmh  = (const float*)d_in[17];
    const float* wc1  = (const float*)d_in[18];
    const float* bc1  = (const float*)d_in[19];
    const float* cg   = (const float*)d_in[20];
    const float* cbe  = (const float*)d_in[21];
    const float* wc2  = (const float*)d_in[22];
    const float* bc2  = (const float*)d_in[23];
    float* out = (float*)d_out;

    float *w1sb,*wkv,*bkv,*gram,*xx,*uv,*h,*h2,*agg,*q,*kvb,*add,*cat,*hc;
    int* idx;
    cudaGetSymbolAddress((void**)&w1sb, g_w1sb);
    cudaGetSymbolAddress((void**)&wkv,  g_wkv);
    cudaGetSymbolAddress((void**)&bkv,  g_bkv);
    cudaGetSymbolAddress((void**)&gram, g_gram);
    cudaGetSymbolAddress((void**)&xx,   g_xx);
    cudaGetSymbolAddress((void**)&idx,  g_idx);
    cudaGetSymbolAddress((void**)&uv,   g_uv);
    cudaGetSymbolAddress((void**)&h,    g_h);
    cudaGetSymbolAddress((void**)&h2,   g_h2);
    cudaGetSymbolAddress((void**)&agg,  g_agg);
    cudaGetSymbolAddress((void**)&q,    g_q);
    cudaGetSymbolAddress((void**)&kvb,  g_kv);
    cudaGetSymbolAddress((void**)&add,  g_add);
    cudaGetSymbolAddress((void**)&cat,  g_cat);
    cudaGetSymbolAddress((void**)&hc,   g_hc);

    const long long CN  = (long long)CCH*NPT;
    const long long CNK = (long long)CCH*NPT*KNNK;
    const int FLASH_SMEM = FLASH_SM_FLOATS * 4;
    const int NTRI2 = 272;   // sum_{bi=0}^{15} (32 - 2*bi)

    cudaFuncSetAttribute(flash_mma, cudaFuncAttributeMaxDynamicSharedMemorySize, FLASH_SMEM);

    // 1) prep
    prep_kernel<<<(CCH*CCH+255)/256, 256>>>(dgw1, wk, wv, bk, bv, w1sb, wkv, bkv);

    // 2) gram[b] = x^T x (tf32 mma, triangular + mirror); diag -> xx
    gram_mma<<<dim3(NTRI2, 1, BSZ), 256>>>(x, gram, xx);

    // 3) top-9
    topk_kernel<<<dim3(NPT, BSZ), 256>>>(gram, xx, idx);

    // 4) uv = [w1s; w1b] @ x
    gemm_mma<<<gmma(2*CCH,NPT,BSZ), 256>>>(
        w1sb, x, uv, 2*CCH, NPT, CCH, CCH, NPT, NPT,
        0, CN, 2*CN, nullptr, nullptr, nullptr, 0, nullptr, 0, 0);

    // 5) edge features -> h
    {
        long long total = (long long)BSZ*CNK;
        gather_h_kernel<<<(unsigned)((total+255)/256), 256>>>(uv, idx, dgb1, dgg1, dgbe1, h);
    }

    // 6) conv2, fused bn+relu
    gemm_mma<<<gmma(CCH, NPT*KNNK, BSZ), 256>>>(
        dgw2, h, h2, CCH, NPT*KNNK, CCH, CCH, NPT*KNNK, NPT*KNNK,
        0, CNK, CNK, dgb2, dgg2, dgbe2, 1, nullptr, 0, 0);

    // 7) max over k
    maxk_kernel<<<(BSZ*CCH*NPT+255)/256, 256>>>(h2, agg, cat);

    // 8) q, kv projections
    gemm_mma<<<gmma(CCH,NPT,BSZ), 256>>>(
        wq, agg, q, CCH, NPT, CCH, CCH, NPT, NPT,
        0, CN, CN, bq, nullptr, nullptr, 0, nullptr, 0, 0);
    gemm_mma<<<gmma(2*CCH,NPT,BSZ), 256>>>(
        wkv, y, kvb, 2*CCH, NPT, CCH, CCH, NPT, NPT,
        0, CN, 2*CN, bkv, nullptr, nullptr, 0, nullptr, 0, 0);

    // 9) fused attention (tf32 mma) -> add
    {
        dim3 grid((NPT + FQT - 1)/FQT, NHEAD, BSZ);
        flash_mma<<<grid, 256, FLASH_SMEM>>>(q, kvb, add);
    }

    // 10) mh conv -> bottom half of cat
    gemm_mma<<<gmma(CCH,NPT,BSZ), 256>>>(
        wmh, add, cat + CN, CCH, NPT, CCH, CCH, NPT, NPT,
        0, CN, 2*CN, bmh, nullptr, nullptr, 0, nullptr, 0, 0);

    // 11) hc = relu(bn(wc1 @ cat + bc1))
    gemm_mma<<<gmma(2*CCH,NPT,BSZ), 256>>>(
        wc1, cat, hc, 2*CCH, NPT, 2*CCH, 2*CCH, NPT, NPT,
        0, 2*CN, 2*CN, bc1, cg, cbe, 1, nullptr, 0, 0);

    // 12) out = agg + wc2 @ hc + bc2
    gemm_mma<<<gmma(CCH,NPT,BSZ), 256>>>(
        wc2, hc, out, CCH, NPT, 2*CCH, 2*CCH, NPT, NPT,
        0, 2*CN, CN, bc2, nullptr, nullptr, 0, agg, CN, NPT);
}

// round 10
// speedup vs baseline: 2.6613x; 1.0173x over previous
#include <cuda_runtime.h>
#include <math.h>
#include <stdint.h>

#define BSZ   4
#define CCH   128
#define NPT   2000
#define KNNK  9
#define NHEAD 4
#define HD    32
#define BN_EPS 1e-5f

// ---------------- scratch ------------------------------------------------
__device__ float g_w1sb[2*CCH*CCH];
__device__ float g_wkv [2*CCH*CCH];
__device__ float g_bkv [2*CCH];
__device__ float g_gram[(size_t)BSZ*NPT*NPT];
__device__ float g_xx[BSZ*NPT];
__device__ int   g_idx[BSZ*NPT*KNNK];
__device__ float g_uv[BSZ*2*CCH*NPT];
__device__ float g_h [(size_t)BSZ*CCH*NPT*KNNK];
__device__ float g_h2[(size_t)BSZ*CCH*NPT*KNNK];
__device__ float g_agg[BSZ*CCH*NPT];
__device__ float g_q  [BSZ*CCH*NPT];
__device__ float g_kv [BSZ*2*CCH*NPT];
__device__ float g_add[BSZ*CCH*NPT];
__device__ float g_cat[BSZ*2*CCH*NPT];
__device__ float g_hc [BSZ*2*CCH*NPT];

// ---------------- tf32 helpers -------------------------------------------
__device__ __forceinline__ uint32_t f2tf32(float x){
    uint32_t r;
    asm("cvt.rna.tf32.f32 %0, %1;" : "=r"(r) : "f"(x));
    return r;
}
__device__ __forceinline__ void mma_tf32(float* d, const uint32_t* a, uint32_t b0, uint32_t b1){
    asm volatile(
        "mma.sync.aligned.m16n8k8.row.col.f32.tf32.tf32.f32 "
        "{%0,%1,%2,%3},{%4,%5,%6,%7},{%8,%9},{%0,%1,%2,%3};"
        : "+f"(d[0]), "+f"(d[1]), "+f"(d[2]), "+f"(d[3])
        : "r"(a[0]), "r"(a[1]), "r"(a[2]), "r"(a[3]), "r"(b0), "r"(b1));
}
__device__ __forceinline__ void cp_async16(uint32_t saddr, const float* g, bool pred){
    asm volatile("cp.async.cg.shared.global [%0], [%1], 16, %2;"
        :: "r"(saddr), "l"(g), "r"(pred ? 16 : 0));
}
__device__ __forceinline__ void split_tf32(float x, uint32_t& hi, uint32_t& lo){
    hi = f2tf32(x);
    lo = f2tf32(x - __uint_as_float(hi));
}

// ---------------- split-tf32 MMA GEMM, cp.async double-buffered --------------
#define GM_TM 128
#define GM_TN 64
#define GA_LD 20
#define GB_LD 72

__global__ void __launch_bounds__(256) gemm_mma(
    const float* __restrict__ A, const float* __restrict__ B, float* __restrict__ Cm,
    int M, int Nc, int Kc, int lda, int ldb, int ldc,
    long long sA, long long sB, long long sC,
    const float* __restrict__ bias,
    const float* __restrict__ gamma, const float* __restrict__ beta,
    int relu,
    const float* __restrict__ resid, long long sR, int ldr)
{
    int bz = blockIdx.z;
    A  += (long long)bz * sA;
    B  += (long long)bz * sB;
    Cm += (long long)bz * sC;
    if (resid) resid += (long long)bz * sR;

    __shared__ float As[2][GM_TM*GA_LD];
    __shared__ float Bs[2][16*GB_LD];

    int m0 = blockIdx.y * GM_TM;
    int n0 = blockIdx.x * GM_TN;
    int tid = threadIdx.x;
    int w = tid >> 5, lane = tid & 31;
    int g = lane >> 2, t = lane & 3;
    int row = w*16;

    // cp.async index precompute
    int a_k4 = tid & 3,  a_r  = tid >> 2;   // A: 2 iters (r, r+64)
    int b_n4 = tid & 15, b_k  = tid >> 4;   // B: 1 iter

    float acc[8][4];
    #pragma unroll
    for (int i=0;i<8;i++)
        #pragma unroll
        for (int j=0;j<4;j++) acc[i][j] = 0.f;

#define GMM_PREFETCH(KC, BUF) {                                              \
    _Pragma("unroll")                                                        \
    for (int it=0; it<2; it++){                                              \
        int r = a_r + it*64;                                                 \
        int gm = m0 + r;                                                     \
        uint32_t sa = (uint32_t)__cvta_generic_to_shared(                    \
            &As[BUF][r*GA_LD + a_k4*4]);                                     \
        cp_async16(sa, A + (long long)gm*lda + (KC) + a_k4*4, gm < M);       \
    }                                                                        \
    {                                                                        \
        int gn = n0 + b_n4*4;                                                \
        uint32_t sb = (uint32_t)__cvta_generic_to_shared(                    \
            &Bs[BUF][b_k*GB_LD + b_n4*4]);                                   \
        cp_async16(sb, B + (long long)((KC) + b_k)*ldb + gn, gn < Nc);       \
    }                                                                        \
    asm volatile("cp.async.commit_group;" ::: "memory"); }

#define GMM_COMPUTE(BUF) {                                                   \
    _Pragma("unroll")                                                        \
    for (int ks=0; ks<2; ks++){                                              \
        int c0 = ks*8;                                                       \
        uint32_t ah[4], al[4];                                               \
        {                                                                    \
            float a0 = As[BUF][(row+g  )*GA_LD + c0 + t];                    \
            float a1 = As[BUF][(row+8+g)*GA_LD + c0 + t];                    \
            float a2 = As[BUF][(row+g  )*GA_LD + c0 + t + 4];                \
            float a3 = As[BUF][(row+8+g)*GA_LD + c0 + t + 4];                \
            split_tf32(a0, ah[0], al[0]);                                    \
            split_tf32(a1, ah[1], al[1]);                                    \
            split_tf32(a2, ah[2], al[2]);                                    \
            split_tf32(a3, ah[3], al[3]);                                    \
        }                                                                    \
        int kr = ks*8 + t;                                                   \
        _Pragma("unroll")                                                    \
        for (int nt=0; nt<8; nt++){                                          \
            int cidx = nt*8 + g;                                             \
            float b0 = Bs[BUF][(kr  )*GB_LD + cidx];                         \
            float b1 = Bs[BUF][(kr+4)*GB_LD + cidx];                         \
            uint32_t bh0, bl0, bh1, bl1;                                     \
            split_tf32(b0, bh0, bl0);                                        \
            split_tf32(b1, bh1, bl1);                                        \
            mma_tf32(acc[nt], ah, bh0, bh1);                                 \
            mma_tf32(acc[nt], ah, bl0, bl1);                                 \
            mma_tf32(acc[nt], al, bh0, bh1);                                 \
        }                                                                    \
    } }

    const int NC = Kc >> 4;
    GMM_PREFETCH(0, 0);
    int buf = 0;
    for (int c = 0; c < NC; c++){
        if (c + 1 < NC){
            GMM_PREFETCH((c+1)*16, buf^1);
            asm volatile("cp.async.wait_group 1;" ::: "memory");
        } else {
            asm volatile("cp.async.wait_group 0;" ::: "memory");
        }
        __syncthreads();
        GMM_COMPUTE(buf);
        __syncthreads();
        buf ^= 1;
    }

    const float invs = rsqrtf(1.0f + BN_EPS);
    #pragma unroll
    for (int half=0; half<2; half++){
        int gm = m0 + row + half*8 + g;
        if (gm >= M) continue;
        float bi = bias  ? bias[gm]       : 0.f;
        float ga = gamma ? gamma[gm]*invs : 1.f;
        float be = beta  ? beta[gm]       : 0.f;
        #pragma unroll
        for (int nt=0; nt<8; nt++){
            int c0 = n0 + nt*8 + 2*t;
            #pragma unroll
            for (int jj=0; jj<2; jj++){
                int gn = c0 + jj;
                if (gn >= Nc) continue;
                float r = acc[nt][half*2 + jj] + bi;
                if (gamma) r = r*ga + be;
                if (relu)  r = fmaxf(r, 0.f);
                if (resid) r += resid[(long long)gm*ldr + gn];
                Cm[(long long)gm*ldc + gn] = r;
            }
        }
    }
#undef GMM_PREFETCH
#undef GMM_COMPUTE
}

// ---------------- Gram via split-tf32 MMA (R9 proven) ------------------------
#define GRA_LD 17

__global__ void __launch_bounds__(256) gram_mma(
    const float* __restrict__ x,     // [B][C][N]
    float* __restrict__ gram,        // [B][N][N]
    float* __restrict__ xx)          // [B][N]
{
    __shared__ float AH[GM_TM*GRA_LD], AL[GM_TM*GRA_LD];
    __shared__ float BH[16*GB_LD],    BL[16*GB_LD];

    int b = blockIdx.z;
    const float* xb = x + (long long)b*CCH*NPT;
    float* gb = gram + (long long)b*NPT*NPT;

    int tt = blockIdx.x;
    int bi = 0;
    while ((32*(bi+1) - (bi+1)*bi) <= tt) bi++;
    int bj2 = 2*bi + (tt - (32*bi - bi*(bi-1)));

    int m0 = bi * GM_TM;
    int n0 = bj2 * GM_TN;
    int tid = threadIdx.x;
    int w = tid >> 5, lane = tid & 31;
    int g = lane >> 2, t = lane & 3;
    int row = w*16;

    float acc[8][4];
    #pragma unroll
    for (int i=0;i<8;i++)
        #pragma unroll
        for (int j=0;j<4;j++) acc[i][j] = 0.f;

    for (int kc = 0; kc < CCH; kc += 16) {
        #pragma unroll
        for (int it=0; it<8; it++){
            int e = tid + it*256;
            int r = e & 127, kk = e >> 7;
            int gm = m0 + r;
            float av = (gm < NPT) ? xb[(long long)(kc+kk)*NPT + gm] : 0.f;
            float ah = __uint_as_float(f2tf32(av));
            AH[r*GRA_LD + kk] = ah;
            AL[r*GRA_LD + kk] = __uint_as_float(f2tf32(av - ah));
        }
        #pragma unroll
        for (int it=0; it<4; it++){
            int e = tid + it*256;
            int n_ = e & 63, k_ = e >> 6;
            int gn = n0 + n_;
            float bv = (gn < NPT) ? xb[(long long)(kc + k_)*NPT + gn] : 0.f;
            float bh = __uint_as_float(f2tf32(bv));
            BH[k_*GB_LD + n_] = bh;
            BL[k_*GB_LD + n_] = __uint_as_float(f2tf32(bv - bh));
        }
        __syncthreads();

        #pragma unroll
        for (int ks=0; ks<2; ks++){
            int c0 = ks*8;
            uint32_t ah[4], al[4];
            ah[0] = __float_as_uint(AH[(row+g  )*GRA_LD + c0 + t]);
            ah[1] = __float_as_uint(AH[(row+8+g)*GRA_LD + c0 + t]);
            ah[2] = __float_as_uint(AH[(row+g  )*GRA_LD + c0 + t + 4]);
            ah[3] = __float_as_uint(AH[(row+8+g)*GRA_LD + c0 + t + 4]);
            al[0] = __float_as_uint(AL[(row+g  )*GRA_LD + c0 + t]);
            al[1] = __float_as_uint(AL[(row+8+g)*GRA_LD + c0 + t]);
            al[2] = __float_as_uint(AL[(row+g  )*GRA_LD + c0 + t + 4]);
            al[3] = __float_as_uint(AL[(row+8+g)*GRA_LD + c0 + t + 4]);
            int kr = ks*8 + t;
            #pragma unroll
            for (int nt=0; nt<8; nt++){
                int cidx = nt*8 + g;
                uint32_t bh0 = __float_as_uint(BH[(kr  )*GB_LD + cidx]);
                uint32_t bh1 = __float_as_uint(BH[(kr+4)*GB_LD + cidx]);
                uint32_t bl0 = __float_as_uint(BL[(kr  )*GB_LD + cidx]);
                uint32_t bl1 = __float_as_uint(BL[(kr+4)*GB_LD + cidx]);
                mma_tf32(acc[nt], ah, bh0, bh1);
                mma_tf32(acc[nt], ah, bl0, bl1);
                mma_tf32(acc[nt], al, bh0, bh1);
            }
        }
        __syncthreads();
    }

    bool diagtile = (bj2 >> 1) == bi;
    #pragma unroll
    for (int half=0; half<2; half++){
        int gm = m0 + row + half*8 + g;
        if (gm >= NPT) continue;
        #pragma unroll
        for (int nt=0; nt<8; nt++){
            #pragma unroll
            for (int jj=0; jj<2; jj++){
                int gn = n0 + nt*8 + 2*t + jj;
                if (gn >= NPT) continue;
                float val = acc[nt][half*2 + jj];
                gb[(long long)gm*NPT + gn] = val;
                gb[(long long)gn*NPT + gm] = val;
                if (diagtile && gm == gn) xx[b*NPT + gm] = val;
            }
        }
    }
}

// ---------------- prep ------------------------------------------------------
__global__ void prep_kernel(const float* __restrict__ w1,
                            const float* __restrict__ wk, const float* __restrict__ wv,
                            const float* __restrict__ bk, const float* __restrict__ bv,
                            float* __restrict__ w1sb, float* __restrict__ wkv,
                            float* __restrict__ bkv)
{
    int i = blockIdx.x*blockDim.x + threadIdx.x;
    if (i < CCH*CCH) {
        int o = i / CCH, c = i % CCH;
        float a  = w1[o*2*CCH + c];
        float bb = w1[o*2*CCH + CCH + c];
        w1sb[i] = a + bb;
        w1sb[CCH*CCH + i] = bb;
        wkv[i] = wk[i];
        wkv[CCH*CCH + i] = wv[i];
    }
    if (i < 2*CCH) bkv[i] = (i < CCH) ? bk[i] : bv[i - CCH];
}

// ---------------- topk: lane sort-8 + warp k-way merge -----------------------
__global__ void __launch_bounds__(256) topk_kernel(const float* __restrict__ gram,
                                                   const float* __restrict__ xx,
                                                   int* __restrict__ idx)
{
    int n = blockIdx.x, b = blockIdx.y;
    const float* row = gram + ((long long)(b*NPT+n))*NPT;
    const float* xb  = xx + b*NPT;
    int tid = threadIdx.x, w = tid >> 5, l = tid & 31;

    float v[8]; int id[8];
    #pragma unroll
    for (int j=0;j<8;j++){
        int m = w*256 + j*32 + l;
        bool ok = m < NPT;
        v[j]  = ok ? (2.f*row[m] - xb[m]) : -INFINITY;
        id[j] = ok ? m : 0x7fffffff;
    }
#define CSWP(a,bb) { bool sw = (v[a]<v[bb]) || (v[a]==v[bb] && id[a]>id[bb]); \
    float tv = sw?v[bb]:v[a]; float uv2 = sw?v[a]:v[bb]; v[a]=tv; v[bb]=uv2;   \
    int ti = sw?id[bb]:id[a]; int ui = sw?id[a]:id[bb]; id[a]=ti; id[bb]=ui; }
    CSWP(0,1) CSWP(2,3) CSWP(4,5) CSWP(6,7)
    CSWP(0,2) CSWP(1,3) CSWP(4,6) CSWP(5,7)
    CSWP(1,2) CSWP(5,6)
    CSWP(0,4) CSWP(1,5) CSWP(2,6) CSWP(3,7)
    CSWP(2,4) CSWP(3,5)
    CSWP(1,2) CSWP(3,4) CSWP(5,6)
#undef CSWP

    __shared__ float wv[8][12];
    __shared__ int   wi[8][12];

    float hv = v[0]; int hi = id[0];
    #pragma unroll
    for (int t=0;t<KNNK;t++){
        float bvv = hv; int bii = hi;
        #pragma unroll
        for (int s=16; s>0; s>>=1){
            float ov = __shfl_xor_sync(0xffffffffu, bvv, s);
            int   oi = __shfl_xor_sync(0xffffffffu, bii, s);
            if (ov > bvv || (ov == bvv && oi < bii)) { bvv = ov; bii = oi; }
        }
        if (l == 0) { wv[w][t] = bvv; wi[w][t] = bii; }
        if (hi == bii) {
            #pragma unroll
            for (int j=0;j<7;j++){ v[j]=v[j+1]; id[j]=id[j+1]; }
            v[7] = -INFINITY; id[7] = 0x7fffffff;
            hv = v[0]; hi = id[0];
        }
    }
    __syncthreads();

    if (w == 0){
        int ptr = 0;
        float hv2 = (l < 8) ? wv[l][0] : -INFINITY;
        int   hi2 = (l < 8) ? wi[l][0] : 0x7fffffff;
        int* outp = idx + (b*NPT+n)*KNNK;
        #pragma unroll
        for (int t=0;t<KNNK;t++){
            float bvv = hv2; int bii = hi2;
            #pragma unroll
            for (int s=16; s>0; s>>=1){
                float ov = __shfl_xor_sync(0xffffffffu, bvv, s);
                int   oi = __shfl_xor_sync(0xffffffffu, bii, s);
                if (ov > bvv || (ov == bvv && oi < bii)) { bvv = ov; bii = oi; }
            }
            if (l == 0) outp[t] = bii;
            if (hi2 == bii){
                ptr++;
                hv2 = (ptr < KNNK && l < 8) ? wv[l][ptr] : -INFINITY;
                hi2 = (ptr < KNNK && l < 8) ? wi[l][ptr] : 0x7fffffff;
            }
        }
    }
}

// h[b,c,n*9+k] = relu( bn( u[b,c,n] - v[b,c,idx] + b1[c] ) )
__global__ void gather_h_kernel(const float* __restrict__ uv,
                                const int* __restrict__ idx,
                                const float* __restrict__ b1, const float* __restrict__ g1,
                                const float* __restrict__ be1, float* __restrict__ h)
{
    long long i = (long long)blockIdx.x*blockDim.x + threadIdx.x;
    const long long total = (long long)BSZ*CCH*NPT*KNNK;
    if (i >= total) return;
    int k = (int)(i % KNNK);
    long long r = i / KNNK;
    int n = (int)(r % NPT); r /= NPT;
    int c = (int)(r % CCH);
    int b = (int)(r / CCH);
    int j = idx[(b*NPT+n)*KNNK + k];
    const float* ub = uv + (long long)b*2*CCH*NPT + (long long)c*NPT;
    float uvv = ub[n];
    float vg  = ub[(long long)CCH*NPT + j];
    const float invs = rsqrtf(1.f + BN_EPS);
    float val = (uvv - vg + b1[c]) * (g1[c]*invs) + be1[c];
    h[((long long)(b*CCH+c))*NPT*KNNK + (long long)n*KNNK + k] = fmaxf(val, 0.f);
}

// agg[b,c,n] = max_k h2[...]; also writes top half of cat
__global__ void maxk_kernel(const float* __restrict__ h2,
                            float* __restrict__ agg, float* __restrict__ cat)
{
    int i = blockIdx.x*blockDim.x + threadIdx.x;
    if (i >= BSZ*CCH*NPT) return;
    int n = i % NPT;
    int c = (i / NPT) % CCH;
    int b = i / (NPT*CCH);
    const float* p = h2 + ((long long)(b*CCH+c))*NPT*KNNK + (long long)n*KNNK;
    float m = p[0];
    #pragma unroll
    for (int k = 1; k < KNNK; k++) m = fmaxf(m, p[k]);
    agg[i] = m;
    cat[(long long)b*2*CCH*NPT + (long long)c*NPT + n] = m;
}

// ---------------- flash attention with tf32 mma.sync (R7 proven) -------------
#define FQT 128
#define FKT 64
#define QS_LD 36
#define KD_LD 72
#define VT_LD2 40
#define OF_QH 0
#define OF_QL (FQT*QS_LD)
#define OF_KH (OF_QL + FQT*QS_LD)
#define OF_KL (OF_KH + HD*KD_LD)
#define OF_VT (OF_KL + HD*KD_LD)
#define FLASH_SM_FLOATS (OF_VT + FKT*VT_LD2)

__global__ void __launch_bounds__(256,2) flash_mma(
    const float* __restrict__ q,
    const float* __restrict__ kv,
    float* __restrict__ add)
{
    extern __shared__ float sm[];
    float* Qsh = sm + OF_QH;
    float* Qsl = sm + OF_QL;
    float* Kdh = sm + OF_KH;
    float* Kdl = sm + OF_KL;
    float* Vt  = sm + OF_VT;

    int n0 = blockIdx.x * FQT;
    int h  = blockIdx.y;
    int b  = blockIdx.z;
    const float* qp = q  + ((long long)b*CCH   + h*HD)*NPT;
    const float* kp = kv + ((long long)b*2*CCH + h*HD)*NPT;
    const float* vp = kv + ((long long)b*2*CCH + CCH + h*HD)*NPT;
    float* oh = add + ((long long)b*CCH + h*HD)*NPT;

    int tid = threadIdx.x;
    const float scale = 0.17677669529663689f;

    #pragma unroll
    for (int e = tid; e < FQT*HD; e += 256) {
        int d = e >> 7, r = e & 127;
        int n = n0 + r;
        float qv = (n < NPT) ? qp[d*NPT + n]*scale : 0.f;
        float hf = __uint_as_float(f2tf32(qv));
        Qsh[r*QS_LD + d] = hf;
        Qsl[r*QS_LD + d] = __uint_as_float(f2tf32(qv - hf));
    }

    int w = tid >> 5, lane = tid & 31;
    int g = lane >> 2, t = lane & 3;
    int row = w*16 + g;

    float O[4][4];
    #pragma unroll
    for (int i=0;i<4;i++)
        #pragma unroll
        for (int j=0;j<4;j++) O[i][j] = 0.f;
    float m0r = -INFINITY, m1r = -INFINITY, l0r = 0.f, l1r = 0.f;

    const int NT = (NPT + FKT - 1)/FKT;

    for (int ti = 0; ti < NT; ti++) {
        int m0 = ti*FKT;
        __syncthreads();
        #pragma unroll
        for (int e = tid; e < HD*FKT; e += 256) {
            int d = e >> 6, c = e & 63;
            int m = m0 + c;
            float kvv = (m < NPT) ? kp[d*NPT + m] : 0.f;
            float hf = __uint_as_float(f2tf32(kvv));
            Kdh[d*KD_LD + c] = hf;
            Kdl[d*KD_LD + c] = __uint_as_float(f2tf32(kvv - hf));
            float vv = (m < NPT) ? vp[d*NPT + m] : 0.f;
            Vt[c*VT_LD2 + d] = __uint_as_float(f2tf32(vv));
        }
        __syncthreads();

        uint32_t qa[4][4], ql[4][4];
        #pragma unroll
        for (int ks=0; ks<4; ks++){
            int c0 = ks*8;
            qa[ks][0] = __float_as_uint(Qsh[(row  )*QS_LD + c0 + t]);
            qa[ks][1] = __float_as_uint(Qsh[(row+8)*QS_LD + c0 + t]);
            qa[ks][2] = __float_as_uint(Qsh[(row  )*QS_LD + c0 + t + 4]);
            qa[ks][3] = __float_as_uint(Qsh[(row+8)*QS_LD + c0 + t + 4]);
            ql[ks][0] = __float_as_uint(Qsl[(row  )*QS_LD + c0 + t]);
            ql[ks][1] = __float_as_uint(Qsl[(row+8)*QS_LD + c0 + t]);
            ql[ks][2] = __float_as_uint(Qsl[(row  )*QS_LD + c0 + t + 4]);
            ql[ks][3] = __float_as_uint(Qsl[(row+8)*QS_LD + c0 + t + 4]);
        }

        float S[8][4];
        #pragma unroll
        for (int nt=0; nt<8; nt++){
            S[nt][0]=0.f; S[nt][1]=0.f; S[nt][2]=0.f; S[nt][3]=0.f;
            #pragma unroll
            for (int ks=0; ks<4; ks++){
                int kr = ks*8 + t;
                int cidx = nt*8 + g;
                uint32_t bh0 = __float_as_uint(Kdh[(kr  )*KD_LD + cidx]);
                uint32_t bh1 = __float_as_uint(Kdh[(kr+4)*KD_LD + cidx]);
                uint32_t bl0 = __float_as_uint(Kdl[(kr  )*KD_LD + cidx]);
                uint32_t bl1 = __float_as_uint(Kdl[(kr+4)*KD_LD + cidx]);
                mma_tf32(S[nt], qa[ks], bh0, bh1);
                mma_tf32(S[nt], qa[ks], bl0, bl1);
                mma_tf32(S[nt], ql[ks], bh0, bh1);
            }
        }

        int mval = NPT - m0;
        float lm0 = -INFINITY, lm1 = -INFINITY;
        #pragma unroll
        for (int nt=0; nt<8; nt++){
            int c0 = nt*8 + 2*t, c1 = c0 + 1;
            if (c0 < mval){ lm0 = fmaxf(lm0, S[nt][0]); lm1 = fmaxf(lm1, S[nt][2]); }
            if (c1 < mval){ lm0 = fmaxf(lm0, S[nt][1]); lm1 = fmaxf(lm1, S[nt][3]); }
        }
        lm0 = fmaxf(lm0, __shfl_xor_sync(0xffffffffu, lm0, 1));
        lm0 = fmaxf(lm0, __shfl_xor_sync(0xffffffffu, lm0, 2));
        lm1 = fmaxf(lm1, __shfl_xor_sync(0xffffffffu, lm1, 1));
        lm1 = fmaxf(lm1, __shfl_xor_sync(0xffffffffu, lm1, 2));

        float mn0 = fmaxf(m0r, lm0), mn1 = fmaxf(m1r, lm1);
        float al0 = __expf(m0r - mn0), al1 = __expf(m1r - mn1);
        m0r = mn0; m1r = mn1;

        float ls0 = 0.f, ls1 = 0.f;
        #pragma unroll
        for (int nt=0; nt<8; nt++){
            int c0 = nt*8 + 2*t, c1 = c0 + 1;
            float e0 = (c0 < mval) ? __expf(S[nt][0] - mn0) : 0.f;
            float e1 = (c1 < mval) ? __expf(S[nt][1] - mn0) : 0.f;
            float e2 = (c0 < mval) ? __expf(S[nt][2] - mn1) : 0.f;
            float e3 = (c1 < mval) ? __expf(S[nt][3] - mn1) : 0.f;
            S[nt][0]=e0; S[nt][1]=e1; S[nt][2]=e2; S[nt][3]=e3;
            ls0 += e0 + e1; ls1 += e2 + e3;
        }
        ls0 += __shfl_xor_sync(0xffffffffu, ls0, 1);
        ls0 += __shfl_xor_sync(0xffffffffu, ls0, 2);
        ls1 += __shfl_xor_sync(0xffffffffu, ls1, 1);
        ls1 += __shfl_xor_sync(0xffffffffu, ls1, 2);
        l0r = l0r*al0 + ls0;
        l1r = l1r*al1 + ls1;
        #pragma unroll
        for (int nd=0; nd<4; nd++){
            O[nd][0] *= al0; O[nd][1] *= al0;
            O[nd][2] *= al1; O[nd][3] *= al1;
        }

        int s1 = g*4 + (t>>1), s2 = s1 + 2;
        bool odd = (t & 1);
        #pragma unroll
        for (int kt2=0; kt2<8; kt2++){
            float x0 = __shfl_sync(0xffffffffu, S[kt2][0], s1);
            float x1 = __shfl_sync(0xffffffffu, S[kt2][1], s1);
            float x2 = __shfl_sync(0xffffffffu, S[kt2][2], s1);
            float x3 = __shfl_sync(0xffffffffu, S[kt2][3], s1);
            float y0 = __shfl_sync(0xffffffffu, S[kt2][0], s2);
            float y1 = __shfl_sync(0xffffffffu, S[kt2][1], s2);
            float y2 = __shfl_sync(0xffffffffu, S[kt2][2], s2);
            float y3 = __shfl_sync(0xffffffffu, S[kt2][3], s2);
            uint32_t pa[4];
            pa[0] = f2tf32(odd ? x1 : x0);
            pa[1] = f2tf32(odd ? x3 : x2);
            pa[2] = f2tf32(odd ? y1 : y0);
            pa[3] = f2tf32(odd ? y3 : y2);
            #pragma unroll
            for (int nd=0; nd<4; nd++){
                uint32_t b0 = __float_as_uint(Vt[(kt2*8 + t    )*VT_LD2 + nd*8 + g]);
                uint32_t b1 = __float_as_uint(Vt[(kt2*8 + t + 4)*VT_LD2 + nd*8 + g]);
                mma_tf32(O[nd], pa, b0, b1);
            }
        }
    }

    float inv0 = 1.f / l0r, inv1 = 1.f / l1r;
    int q0 = n0 + row, q1 = q0 + 8;
    #pragma unroll
    for (int nd=0; nd<4; nd++){
        int d0 = nd*8 + 2*t, d1 = d0 + 1;
        if (q0 < NPT){
            oh[(long long)d0*NPT + q0] = O[nd][0]*inv0;
            oh[(long long)d1*NPT + q0] = O[nd][1]*inv0;
        }
        if (q1 < NPT){
            oh[(long long)d0*NPT + q1] = O[nd][2]*inv1;
            oh[(long long)d1*NPT + q1] = O[nd][3]*inv1;
        }
    }
}

// ---------------- launch ------------------------------------------------------
static inline dim3 gmma(int M, int Nc, int batches) {
    return dim3((Nc + GM_TN - 1)/GM_TN, (M + GM_TM - 1)/GM_TM, batches);
}

extern "C" void kernel_launch(void* const* d_in, const int* in_sizes, int n_in,
                              void* d_out, int out_size)
{
    const float* x    = (const float*)d_in[0];
    const float* y    = (const float*)d_in[1];
    const float* dgw1 = (const float*)d_in[2];
    const float* dgb1 = (const float*)d_in[3];
    const float* dgg1 = (const float*)d_in[4];
    const float* dgbe1= (const float*)d_in[5];
    const float* dgw2 = (const float*)d_in[6];
    const float* dgb2 = (const float*)d_in[7];
    const float* dgg2 = (const float*)d_in[8];
    const float* dgbe2= (const float*)d_in[9];
    const float* wq   = (const float*)d_in[10];
    const float* bq   = (const float*)d_in[11];
    const float* wk   = (const float*)d_in[12];
    const float* bk   = (const float*)d_in[13];
    const float* wv   = (const float*)d_in[14];
    const float* bv   = (const float*)d_in[15];
    const float* wmh  = (const float*)d_in[16];
    const float* bmh  = (const float*)d_in[17];
    const float* wc1  = (const float*)d_in[18];
    const float* bc1  = (const float*)d_in[19];
    const float* cg   = (const float*)d_in[20];
    const float* cbe  = (const float*)d_in[21];
    const float* wc2  = (const float*)d_in[22];
    const float* bc2  = (const float*)d_in[23];
    float* out = (float*)d_out;

    float *w1sb,*wkv,*bkv,*gram,*xx,*uv,*h,*h2,*agg,*q,*kvb,*add,*cat,*hc;
    int* idx;
    cudaGetSymbolAddress((void**)&w1sb, g_w1sb);
    cudaGetSymbolAddress((void**)&wkv,  g_wkv);
    cudaGetSymbolAddress((void**)&bkv,  g_bkv);
    cudaGetSymbolAddress((void**)&gram, g_gram);
    cudaGetSymbolAddress((void**)&xx,   g_xx);
    cudaGetSymbolAddress((void**)&idx,  g_idx);
    cudaGetSymbolAddress((void**)&uv,   g_uv);
    cudaGetSymbolAddress((void**)&h,    g_h);
    cudaGetSymbolAddress((void**)&h2,   g_h2);
    cudaGetSymbolAddress((void**)&agg,  g_agg);
    cudaGetSymbolAddress((void**)&q,    g_q);
    cudaGetSymbolAddress((void**)&kvb,  g_kv);
    cudaGetSymbolAddress((void**)&add,  g_add);
    cudaGetSymbolAddress((void**)&cat,  g_cat);
    cudaGetSymbolAddress((void**)&hc,   g_hc);

    const long long CN  = (long long)CCH*NPT;
    const long long CNK = (long long)CCH*NPT*KNNK;
    const int FLASH_SMEM = FLASH_SM_FLOATS * 4;
    const int NTRI2 = 272;

    cudaFuncSetAttribute(flash_mma, cudaFuncAttributeMaxDynamicSharedMemorySize, FLASH_SMEM);

    // 1) prep
    prep_kernel<<<(CCH*CCH+255)/256, 256>>>(dgw1, wk, wv, bk, bv, w1sb, wkv, bkv);

    // 2) gram[b] = x^T x (tf32 mma, triangular + mirror); diag -> xx
    gram_mma<<<dim3(NTRI2, 1, BSZ), 256>>>(x, gram, xx);

    // 3) top-9
    topk_kernel<<<dim3(NPT, BSZ), 256>>>(gram, xx, idx);

    // 4) uv = [w1s; w1b] @ x
    gemm_mma<<<gmma(2*CCH,NPT,BSZ), 256>>>(
        w1sb, x, uv, 2*CCH, NPT, CCH, CCH, NPT, NPT,
        0, CN, 2*CN, nullptr, nullptr, nullptr, 0, nullptr, 0, 0);

    // 5) edge features -> h
    {
        long long total = (long long)BSZ*CNK;
        gather_h_kernel<<<(unsigned)((total+255)/256), 256>>>(uv, idx, dgb1, dgg1, dgbe1, h);
    }

    // 6) conv2, fused bn+relu
    gemm_mma<<<gmma(CCH, NPT*KNNK, BSZ), 256>>>(
        dgw2, h, h2, CCH, NPT*KNNK, CCH, CCH, NPT*KNNK, NPT*KNNK,
        0, CNK, CNK, dgb2, dgg2, dgbe2, 1, nullptr, 0, 0);

    // 7) max over k
    maxk_kernel<<<(BSZ*CCH*NPT+255)/256, 256>>>(h2, agg, cat);

    // 8) q, kv projections
    gemm_mma<<<gmma(CCH,NPT,BSZ), 256>>>(
        wq, agg, q, CCH, NPT, CCH, CCH, NPT, NPT,
        0, CN, CN, bq, nullptr, nullptr, 0, nullptr, 0, 0);
    gemm_mma<<<gmma(2*CCH,NPT,BSZ), 256>>>(
        wkv, y, kvb, 2*CCH, NPT, CCH, CCH, NPT, NPT,
        0, CN, 2*CN, bkv, nullptr, nullptr, 0, nullptr, 0, 0);

    // 9) fused attention (tf32 mma) -> add
    {
        dim3 grid((NPT + FQT - 1)/FQT, NHEAD, BSZ);
        flash_mma<<<grid, 256, FLASH_SMEM>>>(q, kvb, add);
    }

    // 10) mh conv -> bottom half of cat
    gemm_mma<<<gmma(CCH,NPT,BSZ), 256>>>(
        wmh, add, cat + CN, CCH, NPT, CCH, CCH, NPT, NPT,
        0, CN, 2*CN, bmh, nullptr, nullptr, 0, nullptr, 0, 0);

    // 11) hc = relu(bn(wc1 @ cat + bc1))
    gemm_mma<<<gmma(2*CCH,NPT,BSZ), 256>>>(
        wc1, cat, hc, 2*CCH, NPT, 2*CCH, 2*CCH, NPT, NPT,
        0, 2*CN, 2*CN, bc1, cg, cbe, 1, nullptr, 0, 0);

    // 12) out = agg + wc2 @ hc + bc2
    gemm_mma<<<gmma(CCH,NPT,BSZ), 256>>>(
        wc2, hc, out, CCH, NPT, 2*CCH, 2*CCH, NPT, NPT,
        0, 2*CN, CN, bc2, nullptr, nullptr, 0, agg, CN, NPT);
}

// round 11
// speedup vs baseline: 2.7238x; 1.0235x over previous
#include <cuda_runtime.h>
#include <math.h>
#include <stdint.h>

#define BSZ   4
#define CCH   128
#define NPT   2000
#define KNNK  9
#define NHEAD 4
#define HD    32
#define BN_EPS 1e-5f

// ---------------- scratch ------------------------------------------------
__device__ float g_w1sb[2*CCH*CCH];
__device__ float g_wkv [2*CCH*CCH];
__device__ float g_bkv [2*CCH];
__device__ float g_gram[(size_t)BSZ*NPT*NPT];
__device__ float g_xx[BSZ*NPT];
__device__ int   g_idx[BSZ*NPT*KNNK];
__device__ float g_uv[BSZ*2*CCH*NPT];
__device__ float g_h [(size_t)BSZ*CCH*NPT*KNNK];
__device__ float g_h2[(size_t)BSZ*CCH*NPT*KNNK];
__device__ float g_agg[BSZ*CCH*NPT];
__device__ float g_q  [BSZ*CCH*NPT];
__device__ float g_kv [BSZ*2*CCH*NPT];
__device__ float g_add[BSZ*CCH*NPT];
__device__ float g_cat[BSZ*2*CCH*NPT];
__device__ float g_hc [BSZ*2*CCH*NPT];

// ---------------- tf32 helpers -------------------------------------------
__device__ __forceinline__ uint32_t f2tf32(float x){
    uint32_t r;
    asm("cvt.rna.tf32.f32 %0, %1;" : "=r"(r) : "f"(x));
    return r;
}
__device__ __forceinline__ void mma_tf32(float* d, const uint32_t* a, uint32_t b0, uint32_t b1){
    asm volatile(
        "mma.sync.aligned.m16n8k8.row.col.f32.tf32.tf32.f32 "
        "{%0,%1,%2,%3},{%4,%5,%6,%7},{%8,%9},{%0,%1,%2,%3};"
        : "+f"(d[0]), "+f"(d[1]), "+f"(d[2]), "+f"(d[3])
        : "r"(a[0]), "r"(a[1]), "r"(a[2]), "r"(a[3]), "r"(b0), "r"(b1));
}
__device__ __forceinline__ void cp_async16(uint32_t saddr, const float* g, bool pred){
    asm volatile("cp.async.cg.shared.global [%0], [%1], 16, %2;"
        :: "r"(saddr), "l"(g), "r"(pred ? 16 : 0));
}
__device__ __forceinline__ void split_tf32(float x, uint32_t& hi, uint32_t& lo){
    hi = f2tf32(x);
    lo = f2tf32(x - __uint_as_float(hi));
}

// ---------------- split-tf32 MMA GEMM, cp.async double-buffered --------------
// Template NW = warps (TM = NW*16, threads = NW*32). Per-warp tile: 16 x 64.
#define GM_TN 64
#define GA_LD 20
#define GB_LD 72

template<int NW>
__global__ void __launch_bounds__(NW*32) gemm_mma(
    const float* __restrict__ A, const float* __restrict__ B, float* __restrict__ Cm,
    int M, int Nc, int Kc, int lda, int ldb, int ldc,
    long long sA, long long sB, long long sC,
    const float* __restrict__ bias,
    const float* __restrict__ gamma, const float* __restrict__ beta,
    int relu,
    const float* __restrict__ resid, long long sR, int ldr)
{
    constexpr int TMT = NW*16;
    constexpr int NTH = NW*32;
    constexpr int AIT = (TMT*4)/NTH;       // vec4 iters for A chunk (=2)
    constexpr int BIT = 256/NTH;           // vec4 iters for B chunk (1 or 2)

    int bz = blockIdx.z;
    A  += (long long)bz * sA;
    B  += (long long)bz * sB;
    Cm += (long long)bz * sC;
    if (resid) resid += (long long)bz * sR;

    __shared__ float As[2][TMT*GA_LD];
    __shared__ float Bs[2][16*GB_LD];

    int m0 = blockIdx.y * TMT;
    int n0 = blockIdx.x * GM_TN;
    int tid = threadIdx.x;
    int w = tid >> 5, lane = tid & 31;
    int g = lane >> 2, t = lane & 3;
    int row = w*16;

    int a_k4 = tid & 3,  a_r  = tid >> 2;    // A rows stride NTH/4
    int b_n4 = tid & 15, b_k  = tid >> 4;    // B k stride NTH/16

    float acc[8][4];
    #pragma unroll
    for (int i=0;i<8;i++)
        #pragma unroll
        for (int j=0;j<4;j++) acc[i][j] = 0.f;

#define GMM_PREFETCH(KC, BUF) {                                              \
    _Pragma("unroll")                                                        \
    for (int it=0; it<AIT; it++){                                            \
        int r = a_r + it*(NTH/4);                                            \
        int gm = m0 + r;                                                     \
        uint32_t sa = (uint32_t)__cvta_generic_to_shared(                    \
            &As[BUF][r*GA_LD + a_k4*4]);                                     \
        cp_async16(sa, A + (long long)gm*lda + (KC) + a_k4*4, gm < M);       \
    }                                                                        \
    _Pragma("unroll")                                                        \
    for (int it=0; it<BIT; it++){                                            \
        int k_ = b_k + it*(NTH/16);                                          \
        int gn = n0 + b_n4*4;                                                \
        uint32_t sb = (uint32_t)__cvta_generic_to_shared(                    \
            &Bs[BUF][k_*GB_LD + b_n4*4]);                                    \
        cp_async16(sb, B + (long long)((KC) + k_)*ldb + gn, gn < Nc);        \
    }                                                                        \
    asm volatile("cp.async.commit_group;" ::: "memory"); }

#define GMM_COMPUTE(BUF) {                                                   \
    _Pragma("unroll")                                                        \
    for (int ks=0; ks<2; ks++){                                              \
        int c0 = ks*8;                                                       \
        uint32_t ah[4], al[4];                                               \
        {                                                                    \
            float a0 = As[BUF][(row+g  )*GA_LD + c0 + t];                    \
            float a1 = As[BUF][(row+8+g)*GA_LD + c0 + t];                    \
            float a2 = As[BUF][(row+g  )*GA_LD + c0 + t + 4];                \
            float a3 = As[BUF][(row+8+g)*GA_LD + c0 + t + 4];                \
            split_tf32(a0, ah[0], al[0]);                                    \
            split_tf32(a1, ah[1], al[1]);                                    \
            split_tf32(a2, ah[2], al[2]);                                    \
            split_tf32(a3, ah[3], al[3]);                                    \
        }                                                                    \
        int kr = ks*8 + t;                                                   \
        _Pragma("unroll")                                                    \
        for (int nt=0; nt<8; nt++){                                          \
            int cidx = nt*8 + g;                                             \
            float b0 = Bs[BUF][(kr  )*GB_LD + cidx];                         \
            float b1 = Bs[BUF][(kr+4)*GB_LD + cidx];                         \
            uint32_t bh0, bl0, bh1, bl1;                                     \
            split_tf32(b0, bh0, bl0);                                        \
            split_tf32(b1, bh1, bl1);                                        \
            mma_tf32(acc[nt], ah, bh0, bh1);                                 \
            mma_tf32(acc[nt], ah, bl0, bl1);                                 \
            mma_tf32(acc[nt], al, bh0, bh1);                                 \
        }                                                                    \
    } }

    const int NC = Kc >> 4;
    GMM_PREFETCH(0, 0);
    int buf = 0;
    for (int c = 0; c < NC; c++){
        if (c + 1 < NC){
            GMM_PREFETCH((c+1)*16, buf^1);
            asm volatile("cp.async.wait_group 1;" ::: "memory");
        } else {
            asm volatile("cp.async.wait_group 0;" ::: "memory");
        }
        __syncthreads();
        GMM_COMPUTE(buf);
        __syncthreads();
        buf ^= 1;
    }

    const float invs = rsqrtf(1.0f + BN_EPS);
    #pragma unroll
    for (int half=0; half<2; half++){
        int gm = m0 + row + half*8 + g;
        if (gm >= M) continue;
        float bi = bias  ? bias[gm]       : 0.f;
        float ga = gamma ? gamma[gm]*invs : 1.f;
        float be = beta  ? beta[gm]       : 0.f;
        #pragma unroll
        for (int nt=0; nt<8; nt++){
            int c0 = n0 + nt*8 + 2*t;
            #pragma unroll
            for (int jj=0; jj<2; jj++){
                int gn = c0 + jj;
                if (gn >= Nc) continue;
                float r = acc[nt][half*2 + jj] + bi;
                if (gamma) r = r*ga + be;
                if (relu)  r = fmaxf(r, 0.f);
                if (resid) r += resid[(long long)gm*ldr + gn];
                Cm[(long long)gm*ldc + gn] = r;
            }
        }
    }
#undef GMM_PREFETCH
#undef GMM_COMPUTE
}

// ---------------- Gram via split-tf32 MMA (R9 proven) ------------------------
#define GM_TM 128
#define GRA_LD 17

__global__ void __launch_bounds__(256) gram_mma(
    const float* __restrict__ x,     // [B][C][N]
    float* __restrict__ gram,        // [B][N][N]
    float* __restrict__ xx)          // [B][N]
{
    __shared__ float AH[GM_TM*GRA_LD], AL[GM_TM*GRA_LD];
    __shared__ float BH[16*GB_LD],    BL[16*GB_LD];

    int b = blockIdx.z;
    const float* xb = x + (long long)b*CCH*NPT;
    float* gb = gram + (long long)b*NPT*NPT;

    int tt = blockIdx.x;
    int bi = 0;
    while ((32*(bi+1) - (bi+1)*bi) <= tt) bi++;
    int bj2 = 2*bi + (tt - (32*bi - bi*(bi-1)));

    int m0 = bi * GM_TM;
    int n0 = bj2 * GM_TN;
    int tid = threadIdx.x;
    int w = tid >> 5, lane = tid & 31;
    int g = lane >> 2, t = lane & 3;
    int row = w*16;

    float acc[8][4];
    #pragma unroll
    for (int i=0;i<8;i++)
        #pragma unroll
        for (int j=0;j<4;j++) acc[i][j] = 0.f;

    for (int kc = 0; kc < CCH; kc += 16) {
        #pragma unroll
        for (int it=0; it<8; it++){
            int e = tid + it*256;
            int r = e & 127, kk = e >> 7;
            int gm = m0 + r;
            float av = (gm < NPT) ? xb[(long long)(kc+kk)*NPT + gm] : 0.f;
            float ah = __uint_as_float(f2tf32(av));
            AH[r*GRA_LD + kk] = ah;
            AL[r*GRA_LD + kk] = __uint_as_float(f2tf32(av - ah));
        }
        #pragma unroll
        for (int it=0; it<4; it++){
            int e = tid + it*256;
            int n_ = e & 63, k_ = e >> 6;
            int gn = n0 + n_;
            float bv = (gn < NPT) ? xb[(long long)(kc + k_)*NPT + gn] : 0.f;
            float bh = __uint_as_float(f2tf32(bv));
            BH[k_*GB_LD + n_] = bh;
            BL[k_*GB_LD + n_] = __uint_as_float(f2tf32(bv - bh));
        }
        __syncthreads();

        #pragma unroll
        for (int ks=0; ks<2; ks++){
            int c0 = ks*8;
            uint32_t ah[4], al[4];
            ah[0] = __float_as_uint(AH[(row+g  )*GRA_LD + c0 + t]);
            ah[1] = __float_as_uint(AH[(row+8+g)*GRA_LD + c0 + t]);
            ah[2] = __float_as_uint(AH[(row+g  )*GRA_LD + c0 + t + 4]);
            ah[3] = __float_as_uint(AH[(row+8+g)*GRA_LD + c0 + t + 4]);
            al[0] = __float_as_uint(AL[(row+g  )*GRA_LD + c0 + t]);
            al[1] = __float_as_uint(AL[(row+8+g)*GRA_LD + c0 + t]);
            al[2] = __float_as_uint(AL[(row+g  )*GRA_LD + c0 + t + 4]);
            al[3] = __float_as_uint(AL[(row+8+g)*GRA_LD + c0 + t + 4]);
            int kr = ks*8 + t;
            #pragma unroll
            for (int nt=0; nt<8; nt++){
                int cidx = nt*8 + g;
                uint32_t bh0 = __float_as_uint(BH[(kr  )*GB_LD + cidx]);
                uint32_t bh1 = __float_as_uint(BH[(kr+4)*GB_LD + cidx]);
                uint32_t bl0 = __float_as_uint(BL[(kr  )*GB_LD + cidx]);
                uint32_t bl1 = __float_as_uint(BL[(kr+4)*GB_LD + cidx]);
                mma_tf32(acc[nt], ah, bh0, bh1);
                mma_tf32(acc[nt], ah, bl0, bl1);
                mma_tf32(acc[nt], al, bh0, bh1);
            }
        }
        __syncthreads();
    }

    bool diagtile = (bj2 >> 1) == bi;
    #pragma unroll
    for (int half=0; half<2; half++){
        int gm = m0 + row + half*8 + g;
        if (gm >= NPT) continue;
        #pragma unroll
        for (int nt=0; nt<8; nt++){
            #pragma unroll
            for (int jj=0; jj<2; jj++){
                int gn = n0 + nt*8 + 2*t + jj;
                if (gn >= NPT) continue;
                float val = acc[nt][half*2 + jj];
                gb[(long long)gm*NPT + gn] = val;
                gb[(long long)gn*NPT + gm] = val;
                if (diagtile && gm == gn) xx[b*NPT + gm] = val;
            }
        }
    }
}

// ---------------- prep ------------------------------------------------------
__global__ void prep_kernel(const float* __restrict__ w1,
                            const float* __restrict__ wk, const float* __restrict__ wv,
                            const float* __restrict__ bk, const float* __restrict__ bv,
                            float* __restrict__ w1sb, float* __restrict__ wkv,
                            float* __restrict__ bkv)
{
    int i = blockIdx.x*blockDim.x + threadIdx.x;
    if (i < CCH*CCH) {
        int o = i / CCH, c = i % CCH;
        float a  = w1[o*2*CCH + c];
        float bb = w1[o*2*CCH + CCH + c];
        w1sb[i] = a + bb;
        w1sb[CCH*CCH + i] = bb;
        wkv[i] = wk[i];
        wkv[CCH*CCH + i] = wv[i];
    }
    if (i < 2*CCH) bkv[i] = (i < CCH) ? bk[i] : bv[i - CCH];
}

// ---------------- topk: lane sort-8 + warp k-way merge -----------------------
__global__ void __launch_bounds__(256) topk_kernel(const float* __restrict__ gram,
                                                   const float* __restrict__ xx,
                                                   int* __restrict__ idx)
{
    int n = blockIdx.x, b = blockIdx.y;
    const float* row = gram + ((long long)(b*NPT+n))*NPT;
    const float* xb  = xx + b*NPT;
    int tid = threadIdx.x, w = tid >> 5, l = tid & 31;

    float v[8]; int id[8];
    #pragma unroll
    for (int j=0;j<8;j++){
        int m = w*256 + j*32 + l;
        bool ok = m < NPT;
        v[j]  = ok ? (2.f*row[m] - xb[m]) : -INFINITY;
        id[j] = ok ? m : 0x7fffffff;
    }
#define CSWP(a,bb) { bool sw = (v[a]<v[bb]) || (v[a]==v[bb] && id[a]>id[bb]); \
    float tv = sw?v[bb]:v[a]; float uv2 = sw?v[a]:v[bb]; v[a]=tv; v[bb]=uv2;   \
    int ti = sw?id[bb]:id[a]; int ui = sw?id[a]:id[bb]; id[a]=ti; id[bb]=ui; }
    CSWP(0,1) CSWP(2,3) CSWP(4,5) CSWP(6,7)
    CSWP(0,2) CSWP(1,3) CSWP(4,6) CSWP(5,7)
    CSWP(1,2) CSWP(5,6)
    CSWP(0,4) CSWP(1,5) CSWP(2,6) CSWP(3,7)
    CSWP(2,4) CSWP(3,5)
    CSWP(1,2) CSWP(3,4) CSWP(5,6)
#undef CSWP

    __shared__ float wv[8][12];
    __shared__ int   wi[8][12];

    float hv = v[0]; int hi = id[0];
    #pragma unroll
    for (int t=0;t<KNNK;t++){
        float bvv = hv; int bii = hi;
        #pragma unroll
        for (int s=16; s>0; s>>=1){
            float ov = __shfl_xor_sync(0xffffffffu, bvv, s);
            int   oi = __shfl_xor_sync(0xffffffffu, bii, s);
            if (ov > bvv || (ov == bvv && oi < bii)) { bvv = ov; bii = oi; }
        }
        if (l == 0) { wv[w][t] = bvv; wi[w][t] = bii; }
        if (hi == bii) {
            #pragma unroll
            for (int j=0;j<7;j++){ v[j]=v[j+1]; id[j]=id[j+1]; }
            v[7] = -INFINITY; id[7] = 0x7fffffff;
            hv = v[0]; hi = id[0];
        }
    }
    __syncthreads();

    if (w == 0){
        int ptr = 0;
        float hv2 = (l < 8) ? wv[l][0] : -INFINITY;
        int   hi2 = (l < 8) ? wi[l][0] : 0x7fffffff;
        int* outp = idx + (b*NPT+n)*KNNK;
        #pragma unroll
        for (int t=0;t<KNNK;t++){
            float bvv = hv2; int bii = hi2;
            #pragma unroll
            for (int s=16; s>0; s>>=1){
                float ov = __shfl_xor_sync(0xffffffffu, bvv, s);
                int   oi = __shfl_xor_sync(0xffffffffu, bii, s);
                if (ov > bvv || (ov == bvv && oi < bii)) { bvv = ov; bii = oi; }
            }
            if (l == 0) outp[t] = bii;
            if (hi2 == bii){
                ptr++;
                hv2 = (ptr < KNNK && l < 8) ? wv[l][ptr] : -INFINITY;
                hi2 = (ptr < KNNK && l < 8) ? wi[l][ptr] : 0x7fffffff;
            }
        }
    }
}

// h[b,c,n*9+k] = relu( bn( u[b,c,n] - v[b,c,idx] + b1[c] ) )
__global__ void gather_h_kernel(const float* __restrict__ uv,
                                const int* __restrict__ idx,
                                const float* __restrict__ b1, const float* __restrict__ g1,
                                const float* __restrict__ be1, float* __restrict__ h)
{
    long long i = (long long)blockIdx.x*blockDim.x + threadIdx.x;
    const long long total = (long long)BSZ*CCH*NPT*KNNK;
    if (i >= total) return;
    int k = (int)(i % KNNK);
    long long r = i / KNNK;
    int n = (int)(r % NPT); r /= NPT;
    int c = (int)(r % CCH);
    int b = (int)(r / CCH);
    int j = idx[(b*NPT+n)*KNNK + k];
    const float* ub = uv + (long long)b*2*CCH*NPT + (long long)c*NPT;
    float uvv = ub[n];
    float vg  = ub[(long long)CCH*NPT + j];
    const float invs = rsqrtf(1.f + BN_EPS);
    float val = (uvv - vg + b1[c]) * (g1[c]*invs) + be1[c];
    h[((long long)(b*CCH+c))*NPT*KNNK + (long long)n*KNNK + k] = fmaxf(val, 0.f);
}

// agg[b,c,n] = max_k h2[...]; also writes top half of cat
__global__ void maxk_kernel(const float* __restrict__ h2,
                            float* __restrict__ agg, float* __restrict__ cat)
{
    int i = blockIdx.x*blockDim.x + threadIdx.x;
    if (i >= BSZ*CCH*NPT) return;
    int n = i % NPT;
    int c = (i / NPT) % CCH;
    int b = i / (NPT*CCH);
    const float* p = h2 + ((long long)(b*CCH+c))*NPT*KNNK + (long long)n*KNNK;
    float m = p[0];
    #pragma unroll
    for (int k = 1; k < KNNK; k++) m = fmaxf(m, p[k]);
    agg[i] = m;
    cat[(long long)b*2*CCH*NPT + (long long)c*NPT + n] = m;
}

// ---------------- flash attention with tf32 mma.sync (R7 proven) -------------
#define FQT 128
#define FKT 64
#define QS_LD 36
#define KD_LD 72
#define VT_LD2 40
#define OF_QH 0
#define OF_QL (FQT*QS_LD)
#define OF_KH (OF_QL + FQT*QS_LD)
#define OF_KL (OF_KH + HD*KD_LD)
#define OF_VT (OF_KL + HD*KD_LD)
#define FLASH_SM_FLOATS (OF_VT + FKT*VT_LD2)

__global__ void __launch_bounds__(256,2) flash_mma(
    const float* __restrict__ q,
    const float* __restrict__ kv,
    float* __restrict__ add)
{
    extern __shared__ float sm[];
    float* Qsh = sm + OF_QH;
    float* Qsl = sm + OF_QL;
    float* Kdh = sm + OF_KH;
    float* Kdl = sm + OF_KL;
    float* Vt  = sm + OF_VT;

    int n0 = blockIdx.x * FQT;
    int h  = blockIdx.y;
    int b  = blockIdx.z;
    const float* qp = q  + ((long long)b*CCH   + h*HD)*NPT;
    const float* kp = kv + ((long long)b*2*CCH + h*HD)*NPT;
    const float* vp = kv + ((long long)b*2*CCH + CCH + h*HD)*NPT;
    float* oh = add + ((long long)b*CCH + h*HD)*NPT;

    int tid = threadIdx.x;
    const float scale = 0.17677669529663689f;

    #pragma unroll
    for (int e = tid; e < FQT*HD; e += 256) {
        int d = e >> 7, r = e & 127;
        int n = n0 + r;
        float qv = (n < NPT) ? qp[d*NPT + n]*scale : 0.f;
        float hf = __uint_as_float(f2tf32(qv));
        Qsh[r*QS_LD + d] = hf;
        Qsl[r*QS_LD + d] = __uint_as_float(f2tf32(qv - hf));
    }

    int w = tid >> 5, lane = tid & 31;
    int g = lane >> 2, t = lane & 3;
    int row = w*16 + g;

    float O[4][4];
    #pragma unroll
    for (int i=0;i<4;i++)
        #pragma unroll
        for (int j=0;j<4;j++) O[i][j] = 0.f;
    float m0r = -INFINITY, m1r = -INFINITY, l0r = 0.f, l1r = 0.f;

    const int NT = (NPT + FKT - 1)/FKT;

    for (int ti = 0; ti < NT; ti++) {
        int m0 = ti*FKT;
        __syncthreads();
        #pragma unroll
        for (int e = tid; e < HD*FKT; e += 256) {
            int d = e >> 6, c = e & 63;
            int m = m0 + c;
            float kvv = (m < NPT) ? kp[d*NPT + m] : 0.f;
            float hf = __uint_as_float(f2tf32(kvv));
            Kdh[d*KD_LD + c] = hf;
            Kdl[d*KD_LD + c] = __uint_as_float(f2tf32(kvv - hf));
            float vv = (m < NPT) ? vp[d*NPT + m] : 0.f;
            Vt[c*VT_LD2 + d] = __uint_as_float(f2tf32(vv));
        }
        __syncthreads();

        uint32_t qa[4][4], ql[4][4];
        #pragma unroll
        for (int ks=0; ks<4; ks++){
            int c0 = ks*8;
            qa[ks][0] = __float_as_uint(Qsh[(row  )*QS_LD + c0 + t]);
            qa[ks][1] = __float_as_uint(Qsh[(row+8)*QS_LD + c0 + t]);
            qa[ks][2] = __float_as_uint(Qsh[(row  )*QS_LD + c0 + t + 4]);
            qa[ks][3] = __float_as_uint(Qsh[(row+8)*QS_LD + c0 + t + 4]);
            ql[ks][0] = __float_as_uint(Qsl[(row  )*QS_LD + c0 + t]);
            ql[ks][1] = __float_as_uint(Qsl[(row+8)*QS_LD + c0 + t]);
            ql[ks][2] = __float_as_uint(Qsl[(row  )*QS_LD + c0 + t + 4]);
            ql[ks][3] = __float_as_uint(Qsl[(row+8)*QS_LD + c0 + t + 4]);
        }

        float S[8][4];
        #pragma unroll
        for (int nt=0; nt<8; nt++){
            S[nt][0]=0.f; S[nt][1]=0.f; S[nt][2]=0.f; S[nt][3]=0.f;
            #pragma unroll
            for (int ks=0; ks<4; ks++){
                int kr = ks*8 + t;
                int cidx = nt*8 + g;
                uint32_t bh0 = __float_as_uint(Kdh[(kr  )*KD_LD + cidx]);
                uint32_t bh1 = __float_as_uint(Kdh[(kr+4)*KD_LD + cidx]);
                uint32_t bl0 = __float_as_uint(Kdl[(kr  )*KD_LD + cidx]);
                uint32_t bl1 = __float_as_uint(Kdl[(kr+4)*KD_LD + cidx]);
                mma_tf32(S[nt], qa[ks], bh0, bh1);
                mma_tf32(S[nt], qa[ks], bl0, bl1);
                mma_tf32(S[nt], ql[ks], bh0, bh1);
            }
        }

        int mval = NPT - m0;
        float lm0 = -INFINITY, lm1 = -INFINITY;
        #pragma unroll
        for (int nt=0; nt<8; nt++){
            int c0 = nt*8 + 2*t, c1 = c0 + 1;
            if (c0 < mval){ lm0 = fmaxf(lm0, S[nt][0]); lm1 = fmaxf(lm1, S[nt][2]); }
            if (c1 < mval){ lm0 = fmaxf(lm0, S[nt][1]); lm1 = fmaxf(lm1, S[nt][3]); }
        }
        lm0 = fmaxf(lm0, __shfl_xor_sync(0xffffffffu, lm0, 1));
        lm0 = fmaxf(lm0, __shfl_xor_sync(0xffffffffu, lm0, 2));
        lm1 = fmaxf(lm1, __shfl_xor_sync(0xffffffffu, lm1, 1));
        lm1 = fmaxf(lm1, __shfl_xor_sync(0xffffffffu, lm1, 2));

        float mn0 = fmaxf(m0r, lm0), mn1 = fmaxf(m1r, lm1);
        float al0 = __expf(m0r - mn0), al1 = __expf(m1r - mn1);
        m0r = mn0; m1r = mn1;

        float ls0 = 0.f, ls1 = 0.f;
        #pragma unroll
        for (int nt=0; nt<8; nt++){
            int c0 = nt*8 + 2*t, c1 = c0 + 1;
            float e0 = (c0 < mval) ? __expf(S[nt][0] - mn0) : 0.f;
            float e1 = (c1 < mval) ? __expf(S[nt][1] - mn0) : 0.f;
            float e2 = (c0 < mval) ? __expf(S[nt][2] - mn1) : 0.f;
            float e3 = (c1 < mval) ? __expf(S[nt][3] - mn1) : 0.f;
            S[nt][0]=e0; S[nt][1]=e1; S[nt][2]=e2; S[nt][3]=e3;
            ls0 += e0 + e1; ls1 += e2 + e3;
        }
        ls0 += __shfl_xor_sync(0xffffffffu, ls0, 1);
        ls0 += __shfl_xor_sync(0xffffffffu, ls0, 2);
        ls1 += __shfl_xor_sync(0xffffffffu, ls1, 1);
        ls1 += __shfl_xor_sync(0xffffffffu, ls1, 2);
        l0r = l0r*al0 + ls0;
        l1r = l1r*al1 + ls1;
        #pragma unroll
        for (int nd=0; nd<4; nd++){
            O[nd][0] *= al0; O[nd][1] *= al0;
            O[nd][2] *= al1; O[nd][3] *= al1;
        }

        int s1 = g*4 + (t>>1), s2 = s1 + 2;
        bool odd = (t & 1);
        #pragma unroll
        for (int kt2=0; kt2<8; kt2++){
            float x0 = __shfl_sync(0xffffffffu, S[kt2][0], s1);
            float x1 = __shfl_sync(0xffffffffu, S[kt2][1], s1);
            float x2 = __shfl_sync(0xffffffffu, S[kt2][2], s1);
            float x3 = __shfl_sync(0xffffffffu, S[kt2][3], s1);
            float y0 = __shfl_sync(0xffffffffu, S[kt2][0], s2);
            float y1 = __shfl_sync(0xffffffffu, S[kt2][1], s2);
            float y2 = __shfl_sync(0xffffffffu, S[kt2][2], s2);
            float y3 = __shfl_sync(0xffffffffu, S[kt2][3], s2);
            uint32_t pa[4];
            pa[0] = f2tf32(odd ? x1 : x0);
            pa[1] = f2tf32(odd ? x3 : x2);
            pa[2] = f2tf32(odd ? y1 : y0);
            pa[3] = f2tf32(odd ? y3 : y2);
            #pragma unroll
            for (int nd=0; nd<4; nd++){
                uint32_t b0 = __float_as_uint(Vt[(kt2*8 + t    )*VT_LD2 + nd*8 + g]);
                uint32_t b1 = __float_as_uint(Vt[(kt2*8 + t + 4)*VT_LD2 + nd*8 + g]);
                mma_tf32(O[nd], pa, b0, b1);
            }
        }
    }

    float inv0 = 1.f / l0r, inv1 = 1.f / l1r;
    int q0 = n0 + row, q1 = q0 + 8;
    #pragma unroll
    for (int nd=0; nd<4; nd++){
        int d0 = nd*8 + 2*t, d1 = d0 + 1;
        if (q0 < NPT){
            oh[(long long)d0*NPT + q0] = O[nd][0]*inv0;
            oh[(long long)d1*NPT + q0] = O[nd][1]*inv0;
        }
        if (q1 < NPT){
            oh[(long long)d0*NPT + q1] = O[nd][2]*inv1;
            oh[(long long)d1*NPT + q1] = O[nd][3]*inv1;
        }
    }
}

// ---------------- launch ------------------------------------------------------
static inline dim3 gmma128(int M, int Nc, int batches) {
    return dim3((Nc + GM_TN - 1)/GM_TN, (M + 127)/128, batches);
}
static inline dim3 gmma64(int M, int Nc, int batches) {
    return dim3((Nc + GM_TN - 1)/GM_TN, (M + 63)/64, batches);
}

extern "C" void kernel_launch(void* const* d_in, const int* in_sizes, int n_in,
                              void* d_out, int out_size)
{
    const float* x    = (const float*)d_in[0];
    const float* y    = (const float*)d_in[1];
    const float* dgw1 = (const float*)d_in[2];
    const float* dgb1 = (const float*)d_in[3];
    const float* dgg1 = (const float*)d_in[4];
    const float* dgbe1= (const float*)d_in[5];
    const float* dgw2 = (const float*)d_in[6];
    const float* dgb2 = (const float*)d_in[7];
    const float* dgg2 = (const float*)d_in[8];
    const float* dgbe2= (const float*)d_in[9];
    const float* wq   = (const float*)d_in[10];
    const float* bq   = (const float*)d_in[11];
    const float* wk   = (const float*)d_in[12];
    const float* bk   = (const float*)d_in[13];
    const float* wv   = (const float*)d_in[14];
    const float* bv   = (const float*)d_in[15];
    const float* wmh  = (const float*)d_in[16];
    const float* bmh  = (const float*)d_in[17];
    const float* wc1  = (const float*)d_in[18];
    const float* bc1  = (const float*)d_in[19];
    const float* cg   = (const float*)d_in[20];
    const float* cbe  = (const float*)d_in[21];
    const float* wc2  = (const float*)d_in[22];
    const float* bc2  = (const float*)d_in[23];
    float* out = (float*)d_out;

    float *w1sb,*wkv,*bkv,*gram,*xx,*uv,*h,*h2,*agg,*q,*kvb,*add,*cat,*hc;
    int* idx;
    cudaGetSymbolAddress((void**)&w1sb, g_w1sb);
    cudaGetSymbolAddress((void**)&wkv,  g_wkv);
    cudaGetSymbolAddress((void**)&bkv,  g_bkv);
    cudaGetSymbolAddress((void**)&gram, g_gram);
    cudaGetSymbolAddress((void**)&xx,   g_xx);
    cudaGetSymbolAddress((void**)&idx,  g_idx);
    cudaGetSymbolAddress((void**)&uv,   g_uv);
    cudaGetSymbolAddress((void**)&h,    g_h);
    cudaGetSymbolAddress((void**)&h2,   g_h2);
    cudaGetSymbolAddress((void**)&agg,  g_agg);
    cudaGetSymbolAddress((void**)&q,    g_q);
    cudaGetSymbolAddress((void**)&kvb,  g_kv);
    cudaGetSymbolAddress((void**)&add,  g_add);
    cudaGetSymbolAddress((void**)&cat,  g_cat);
    cudaGetSymbolAddress((void**)&hc,   g_hc);

    const long long CN  = (long long)CCH*NPT;
    const long long CNK = (long long)CCH*NPT*KNNK;
    const int FLASH_SMEM = FLASH_SM_FLOATS * 4;
    const int NTRI2 = 272;

    cudaFuncSetAttribute(flash_mma, cudaFuncAttributeMaxDynamicSharedMemorySize, FLASH_SMEM);

    // 1) prep
    prep_kernel<<<(CCH*CCH+255)/256, 256>>>(dgw1, wk, wv, bk, bv, w1sb, wkv, bkv);

    // 2) gram[b] = x^T x (tf32 mma, triangular + mirror); diag -> xx
    gram_mma<<<dim3(NTRI2, 1, BSZ), 256>>>(x, gram, xx);

    // 3) top-9
    topk_kernel<<<dim3(NPT, BSZ), 256>>>(gram, xx, idx);

    // 4) uv = [w1s; w1b] @ x   (TM=64, 512 CTAs)
    gemm_mma<4><<<gmma64(2*CCH,NPT,BSZ), 128>>>(
        w1sb, x, uv, 2*CCH, NPT, CCH, CCH, NPT, NPT,
        0, CN, 2*CN, nullptr, nullptr, nullptr, 0, nullptr, 0, 0);

    // 5) edge features -> h
    {
        long long total = (long long)BSZ*CNK;
        gather_h_kernel<<<(unsigned)((total+255)/256), 256>>>(uv, idx, dgb1, dgg1, dgbe1, h);
    }

    // 6) conv2, fused bn+relu (TM=128, 1128 CTAs)
    gemm_mma<8><<<gmma128(CCH, NPT*KNNK, BSZ), 256>>>(
        dgw2, h, h2, CCH, NPT*KNNK, CCH, CCH, NPT*KNNK, NPT*KNNK,
        0, CNK, CNK, dgb2, dgg2, dgbe2, 1, nullptr, 0, 0);

    // 7) max over k
    maxk_kernel<<<(BSZ*CCH*NPT+255)/256, 256>>>(h2, agg, cat);

    // 8) q, kv projections (TM=64)
    gemm_mma<4><<<gmma64(CCH,NPT,BSZ), 128>>>(
        wq, agg, q, CCH, NPT, CCH, CCH, NPT, NPT,
        0, CN, CN, bq, nullptr, nullptr, 0, nullptr, 0, 0);
    gemm_mma<4><<<gmma64(2*CCH,NPT,BSZ), 128>>>(
        wkv, y, kvb, 2*CCH, NPT, CCH, CCH, NPT, NPT,
        0, CN, 2*CN, bkv, nullptr, nullptr, 0, nullptr, 0, 0);

    // 9) fused attention (tf32 mma) -> add
    {
        dim3 grid((NPT + FQT - 1)/FQT, NHEAD, BSZ);
        flash_mma<<<grid, 256, FLASH_SMEM>>>(q, kvb, add);
    }

    // 10) mh conv -> bottom half of cat (TM=64)
    gemm_mma<4><<<gmma64(CCH,NPT,BSZ), 128>>>(
        wmh, add, cat + CN, CCH, NPT, CCH, CCH, NPT, NPT,
        0, CN, 2*CN, bmh, nullptr, nullptr, 0, nullptr, 0, 0);

    // 11) hc = relu(bn(wc1 @ cat + bc1)) (TM=64)
    gemm_mma<4><<<gmma64(2*CCH,NPT,BSZ), 128>>>(
        wc1, cat, hc, 2*CCH, NPT, 2*CCH, 2*CCH, NPT, NPT,
        0, 2*CN, 2*CN, bc1, cg, cbe, 1, nullptr, 0, 0);

    // 12) out = agg + wc2 @ hc + bc2 (TM=64)
    gemm_mma<4><<<gmma64(CCH,NPT,BSZ), 128>>>(
        wc2, hc, out, CCH, NPT, 2*CCH, 2*CCH, NPT, NPT,
        0, 2*CN, CN, bc2, nullptr, nullptr, 0, agg, CN, NPT);
}